// round 2
// baseline (speedup 1.0000x reference)
#include <cuda_runtime.h>
#include <math.h>

// ---------------- problem constants ----------------
#define NN      50000      // nodes
#define EMAX    800000     // edges (before self loops)
#define ETOT    (EMAX + NN)
#define FEAT    256        // NFEAT = NHEADS*NHID = NOUT = 256
#define NHEADS  4
#define NHID    64
#define NEG_SLOPE 0.2f
#define BN_EPS  1e-5f
#define LN_EPS  1e-5f

// ---------------- scratch (device globals; no runtime alloc) ----------------
__device__ float g_xp[NN * FEAT];     // xp of current layer (reused for layer 2)
__device__ float g_h1[NN * FEAT];     // layer-1 output (ELU'd)
__device__ float g_asrc[NN * NHEADS];
__device__ float g_adst[NN * NHEADS];
__device__ int   g_count[NN];
__device__ int   g_rowptr[NN + 1];
__device__ int   g_cursor[NN];
__device__ int   g_csrsrc[ETOT];

// ---------------- CSR build ----------------
__global__ void init_count_kernel(int n) {
    int i = blockIdx.x * blockDim.x + threadIdx.x;
    if (i < n) g_count[i] = 1;  // self loop
}

__global__ void count_kernel(const int* __restrict__ ei, int E, int n) {
    int i = blockIdx.x * blockDim.x + threadIdx.x;
    if (i < E) {
        int d = ei[E + i];      // dst row of edge_index
        atomicAdd(&g_count[d], 1);
    }
}

// single-block scan, 1024 threads, warp-shuffle based
__global__ void scan_kernel(int n) {
    __shared__ int warpsum[32];
    __shared__ int s_carry;
    int tid = threadIdx.x, lane = tid & 31, wid = tid >> 5;
    if (tid == 0) { s_carry = 0; g_rowptr[0] = 0; }
    __syncthreads();
    for (int base = 0; base < n; base += 1024) {
        int i = base + tid;
        int v = (i < n) ? g_count[i] : 0;
        int x = v;
        #pragma unroll
        for (int off = 1; off < 32; off <<= 1) {
            int y = __shfl_up_sync(0xffffffffu, x, off);
            if (lane >= off) x += y;
        }
        if (lane == 31) warpsum[wid] = x;
        __syncthreads();
        int woff = 0, tot = 0;
        #pragma unroll
        for (int w = 0; w < 32; w++) {
            int ws = warpsum[w];
            if (w < wid) woff += ws;
            tot += ws;
        }
        int carry = s_carry;
        int incl = carry + woff + x;
        if (i < n) {
            g_cursor[i]     = incl - v;   // exclusive
            g_rowptr[i + 1] = incl;
        }
        __syncthreads();
        if (tid == 0) s_carry = carry + tot;
        __syncthreads();
    }
}

__global__ void fill_kernel(const int* __restrict__ ei, int E, int n) {
    int i = blockIdx.x * blockDim.x + threadIdx.x;
    int tot = E + n;
    if (i >= tot) return;
    int s, d;
    if (i < E) { s = ei[i]; d = ei[E + i]; }
    else       { s = d = i - E; }
    int pos = atomicAdd(&g_cursor[d], 1);
    g_csrsrc[pos] = s;
}

// ---------------- SGEMM: C[M,256] = A[M,256] @ B[256,256], fp32 ----------------
#define BM 128
#define BN 128
#define BK 8
#define TM 8
#define TN 8

__global__ __launch_bounds__(256) void sgemm_kernel(
    const float* __restrict__ A, const float* __restrict__ B,
    float* __restrict__ C, int M)
{
    const int K = 256, NC = 256;
    __shared__ float As[BK][BM];
    __shared__ float Bs[BK][BN];
    int tid = threadIdx.x;
    int block_row = blockIdx.x * BM;
    int block_col = blockIdx.y * BN;

    int tcol = (tid % 16) * TN;
    int trow = (tid / 16) * TM;
    int a_row = tid >> 1;
    int a_col = (tid & 1) * 4;
    int b_row = tid >> 5;
    int b_col = (tid & 31) * 4;

    float acc[TM][TN];
    #pragma unroll
    for (int i = 0; i < TM; i++)
        #pragma unroll
        for (int j = 0; j < TN; j++) acc[i][j] = 0.f;

    for (int k0 = 0; k0 < K; k0 += BK) {
        int gr = block_row + a_row;
        float4 av;
        if (gr < M) av = *reinterpret_cast<const float4*>(A + (size_t)gr * K + k0 + a_col);
        else av = make_float4(0.f, 0.f, 0.f, 0.f);
        As[a_col + 0][a_row] = av.x;
        As[a_col + 1][a_row] = av.y;
        As[a_col + 2][a_row] = av.z;
        As[a_col + 3][a_row] = av.w;
        float4 bv = *reinterpret_cast<const float4*>(B + (size_t)(k0 + b_row) * NC + block_col + b_col);
        *reinterpret_cast<float4*>(&Bs[b_row][b_col]) = bv;
        __syncthreads();
        #pragma unroll
        for (int k = 0; k < BK; k++) {
            float ra[TM], rb[TN];
            #pragma unroll
            for (int i = 0; i < TM; i++) ra[i] = As[k][trow + i];
            #pragma unroll
            for (int j = 0; j < TN; j++) rb[j] = Bs[k][tcol + j];
            #pragma unroll
            for (int i = 0; i < TM; i++)
                #pragma unroll
                for (int j = 0; j < TN; j++) acc[i][j] += ra[i] * rb[j];
        }
        __syncthreads();
    }
    #pragma unroll
    for (int i = 0; i < TM; i++) {
        int gr = block_row + trow + i;
        if (gr < M) {
            #pragma unroll
            for (int j = 0; j < TN; j += 4) {
                float4 v = make_float4(acc[i][j], acc[i][j+1], acc[i][j+2], acc[i][j+3]);
                *reinterpret_cast<float4*>(C + (size_t)gr * NC + block_col + tcol + j) = v;
            }
        }
    }
}

// ---------------- attention logits ----------------
// layer 1: warp per (node, head); 64 channels, 2/lane
__global__ void att1_kernel(const float* __restrict__ xp,
                            const float* __restrict__ att_src,
                            const float* __restrict__ att_dst, int n)
{
    int warp = (blockIdx.x * blockDim.x + threadIdx.x) >> 5;
    int lane = threadIdx.x & 31;
    if (warp >= n * NHEADS) return;
    int node = warp >> 2, h = warp & 3;
    const float* row = xp + (size_t)node * FEAT + h * NHID;
    const float* ws  = att_src + h * NHID;
    const float* wd  = att_dst + h * NHID;
    float v1 = row[lane], v2 = row[lane + 32];
    float s = v1 * ws[lane] + v2 * ws[lane + 32];
    float d = v1 * wd[lane] + v2 * wd[lane + 32];
    #pragma unroll
    for (int off = 16; off; off >>= 1) {
        s += __shfl_xor_sync(0xffffffffu, s, off);
        d += __shfl_xor_sync(0xffffffffu, d, off);
    }
    if (lane == 0) { g_asrc[warp] = s; g_adst[warp] = d; }
}

// layer 2: warp per node; 256 channels, 8/lane
__global__ void att2_kernel(const float* __restrict__ xp,
                            const float* __restrict__ att_src,
                            const float* __restrict__ att_dst, int n)
{
    int warp = (blockIdx.x * blockDim.x + threadIdx.x) >> 5;
    int lane = threadIdx.x & 31;
    if (warp >= n) return;
    const float4* row = reinterpret_cast<const float4*>(xp + (size_t)warp * FEAT + lane * 8);
    const float4* s4  = reinterpret_cast<const float4*>(att_src + lane * 8);
    const float4* d4  = reinterpret_cast<const float4*>(att_dst + lane * 8);
    float4 a0 = row[0], a1 = row[1];
    float4 w0 = s4[0], w1 = s4[1];
    float4 u0 = d4[0], u1 = d4[1];
    float s = a0.x*w0.x + a0.y*w0.y + a0.z*w0.z + a0.w*w0.w
            + a1.x*w1.x + a1.y*w1.y + a1.z*w1.z + a1.w*w1.w;
    float d = a0.x*u0.x + a0.y*u0.y + a0.z*u0.z + a0.w*u0.w
            + a1.x*u1.x + a1.y*u1.y + a1.z*u1.z + a1.w*u1.w;
    #pragma unroll
    for (int off = 16; off; off >>= 1) {
        s += __shfl_xor_sync(0xffffffffu, s, off);
        d += __shfl_xor_sync(0xffffffffu, d, off);
    }
    if (lane == 0) { g_asrc[warp] = s; g_adst[warp] = d; }
}

__device__ __forceinline__ float leaky(float x) {
    return (x > 0.f) ? x : NEG_SLOPE * x;
}

// ---------------- aggregation, layer 1 (4 heads) + bias + ELU ----------------
__global__ void agg1_kernel(const float* __restrict__ xp,
                            const float* __restrict__ bias,
                            float* __restrict__ out, int n)
{
    int node = (blockIdx.x * blockDim.x + threadIdx.x) >> 5;
    if (node >= n) return;
    int lane = threadIdx.x & 31;
    int h  = lane >> 3;         // 8 lanes per head (64 ch / 8 per lane)
    int c0 = lane * 8;
    float ad = g_adst[node * NHEADS + h];
    int beg = g_rowptr[node], end = g_rowptr[node + 1];
    float m = -1e30f, s = 0.f;
    float acc[8] = {0,0,0,0,0,0,0,0};
    for (int p = beg; p < end; p++) {
        int j = g_csrsrc[p];
        float e = leaky(g_asrc[j * NHEADS + h] + ad);
        float mn = fmaxf(m, e);
        float corr = __expf(m - mn);
        float pw   = __expf(e - mn);
        s = s * corr + pw;
        const float4* xr = reinterpret_cast<const float4*>(xp + (size_t)j * FEAT + c0);
        float4 v0 = xr[0], v1 = xr[1];
        acc[0] = acc[0] * corr + pw * v0.x;
        acc[1] = acc[1] * corr + pw * v0.y;
        acc[2] = acc[2] * corr + pw * v0.z;
        acc[3] = acc[3] * corr + pw * v0.w;
        acc[4] = acc[4] * corr + pw * v1.x;
        acc[5] = acc[5] * corr + pw * v1.y;
        acc[6] = acc[6] * corr + pw * v1.z;
        acc[7] = acc[7] * corr + pw * v1.w;
        m = mn;
    }
    float inv = 1.f / s;   // denom >= 1 (self-loop/max edge contributes exp(0))
    const float4* b4 = reinterpret_cast<const float4*>(bias + c0);
    float4 b0 = b4[0], b1 = b4[1];
    float vb[8] = {b0.x, b0.y, b0.z, b0.w, b1.x, b1.y, b1.z, b1.w};
    float v[8];
    #pragma unroll
    for (int k = 0; k < 8; k++) {
        float t = acc[k] * inv + vb[k];
        v[k] = (t > 0.f) ? t : expm1f(t);   // ELU
    }
    float4 o0 = make_float4(v[0], v[1], v[2], v[3]);
    float4 o1 = make_float4(v[4], v[5], v[6], v[7]);
    float4* orow = reinterpret_cast<float4*>(out + (size_t)node * FEAT + c0);
    orow[0] = o0; orow[1] = o1;
}

// ---------------- aggregation, layer 2 (1 head) + bias + ELU + BN + LN ----------------
__global__ void agg2_kernel(const float* __restrict__ xp,
                            const float* __restrict__ bias,
                            const float* __restrict__ bn_gamma,
                            const float* __restrict__ bn_beta,
                            const float* __restrict__ bn_mean,
                            const float* __restrict__ bn_var,
                            const float* __restrict__ ln_gamma,
                            const float* __restrict__ ln_beta,
                            float* __restrict__ out, int n)
{
    int node = (blockIdx.x * blockDim.x + threadIdx.x) >> 5;
    if (node >= n) return;
    int lane = threadIdx.x & 31;
    int c0 = lane * 8;
    float ad = g_adst[node];
    int beg = g_rowptr[node], end = g_rowptr[node + 1];
    float m = -1e30f, s = 0.f;
    float acc[8] = {0,0,0,0,0,0,0,0};
    for (int p = beg; p < end; p++) {
        int j = g_csrsrc[p];
        float e = leaky(g_asrc[j] + ad);
        float mn = fmaxf(m, e);
        float corr = __expf(m - mn);
        float pw   = __expf(e - mn);
        s = s * corr + pw;
        const float4* xr = reinterpret_cast<const float4*>(xp + (size_t)j * FEAT + c0);
        float4 v0 = xr[0], v1 = xr[1];
        acc[0] = acc[0] * corr + pw * v0.x;
        acc[1] = acc[1] * corr + pw * v0.y;
        acc[2] = acc[2] * corr + pw * v0.z;
        acc[3] = acc[3] * corr + pw * v0.w;
        acc[4] = acc[4] * corr + pw * v1.x;
        acc[5] = acc[5] * corr + pw * v1.y;
        acc[6] = acc[6] * corr + pw * v1.z;
        acc[7] = acc[7] * corr + pw * v1.w;
        m = mn;
    }
    float inv = 1.f / s;
    float v[8];
    #pragma unroll
    for (int k = 0; k < 8; k++) {
        int c = c0 + k;
        float x = acc[k] * inv + bias[c];
        x = (x > 0.f) ? x : expm1f(x);                           // ELU
        x = (x - bn_mean[c]) * rsqrtf(bn_var[c] + BN_EPS) * bn_gamma[c] + bn_beta[c];  // BN eval
        v[k] = x;
    }
    // LayerNorm over 256 channels (warp = row, 8 ch/lane)
    float lsum = 0.f;
    #pragma unroll
    for (int k = 0; k < 8; k++) lsum += v[k];
    #pragma unroll
    for (int off = 16; off; off >>= 1) lsum += __shfl_xor_sync(0xffffffffu, lsum, off);
    float mu = lsum * (1.f / 256.f);
    float lvar = 0.f;
    #pragma unroll
    for (int k = 0; k < 8; k++) { float d = v[k] - mu; lvar += d * d; }
    #pragma unroll
    for (int off = 16; off; off >>= 1) lvar += __shfl_xor_sync(0xffffffffu, lvar, off);
    float r = rsqrtf(lvar * (1.f / 256.f) + LN_EPS);
    float w[8];
    #pragma unroll
    for (int k = 0; k < 8; k++) {
        int c = c0 + k;
        w[k] = (v[k] - mu) * r * ln_gamma[c] + ln_beta[c];
    }
    float4 o0 = make_float4(w[0], w[1], w[2], w[3]);
    float4 o1 = make_float4(w[4], w[5], w[6], w[7]);
    float4* orow = reinterpret_cast<float4*>(out + (size_t)node * FEAT + c0);
    orow[0] = o0; orow[1] = o1;
}

// ---------------- launch ----------------
extern "C" void kernel_launch(void* const* d_in, const int* in_sizes, int n_in,
                              void* d_out, int out_size)
{
    const float* x        = (const float*)d_in[0];
    const int*   ei       = (const int*)  d_in[1];
    const float* W1       = (const float*)d_in[2];
    const float* att_src1 = (const float*)d_in[3];
    const float* att_dst1 = (const float*)d_in[4];
    const float* bias1    = (const float*)d_in[5];
    const float* W2       = (const float*)d_in[6];
    const float* att_src2 = (const float*)d_in[7];
    const float* att_dst2 = (const float*)d_in[8];
    const float* bias2    = (const float*)d_in[9];
    const float* bn_gamma = (const float*)d_in[10];
    const float* bn_beta  = (const float*)d_in[11];
    const float* bn_mean  = (const float*)d_in[12];
    const float* bn_var   = (const float*)d_in[13];
    const float* ln_gamma = (const float*)d_in[14];
    const float* ln_beta  = (const float*)d_in[15];
    float* out = (float*)d_out;

    int n = in_sizes[0] / FEAT;      // 50000
    int E = in_sizes[1] / 2;         // 800000
    if (n > NN) n = NN;
    if (E > EMAX) E = EMAX;

    float* xp = nullptr; float* h1 = nullptr;
    cudaGetSymbolAddress((void**)&xp, g_xp);
    cudaGetSymbolAddress((void**)&h1, g_h1);

    // --- CSR build ---
    init_count_kernel<<<(n + 255) / 256, 256>>>(n);
    count_kernel<<<(E + 255) / 256, 256>>>(ei, E, n);
    scan_kernel<<<1, 1024>>>(n);
    fill_kernel<<<(E + n + 255) / 256, 256>>>(ei, E, n);

    dim3 ggrid((n + BM - 1) / BM, FEAT / BN);

    // --- layer 1 ---
    sgemm_kernel<<<ggrid, 256>>>(x, W1, xp, n);
    att1_kernel<<<(n * NHEADS * 32 + 255) / 256, 256>>>(xp, att_src1, att_dst1, n);
    agg1_kernel<<<(n * 32 + 255) / 256, 256>>>(xp, bias1, h1, n);

    // --- layer 2 (reuse xp buffer) ---
    sgemm_kernel<<<ggrid, 256>>>(h1, W2, xp, n);
    att2_kernel<<<(n * 32 + 255) / 256, 256>>>(xp, att_src2, att_dst2, n);
    agg2_kernel<<<(n * 32 + 255) / 256, 256>>>(xp, bias2, bn_gamma, bn_beta, bn_mean,
                                               bn_var, ln_gamma, ln_beta, out, n);
    (void)n_in; (void)out_size;
}

// round 3
// speedup vs baseline: 1.4958x; 1.4958x over previous
#include <cuda_runtime.h>
#include <math.h>
#include <stdint.h>

// ---------------- problem constants ----------------
#define NN      50000      // nodes
#define EMAX    800000     // edges (before self loops)
#define ETOT    (EMAX + NN)
#define FEAT    256        // NFEAT = NHEADS*NHID = NOUT = 256
#define NHEADS  4
#define NHID    64
#define NEG_SLOPE 0.2f
#define BN_EPS  1e-5f
#define LN_EPS  1e-5f

// ---------------- scratch (device globals; no runtime alloc) ----------------
__device__ float g_xp[NN * FEAT];     // xp of current layer (reused for layer 2)
__device__ float g_h1[NN * FEAT];     // layer-1 output (ELU'd)
__device__ float g_wt1[FEAT * FEAT];  // W1^T, tf32-rounded, [n][k]
__device__ float g_wt2[FEAT * FEAT];  // W2^T, tf32-rounded, [n][k]
__device__ float g_asrc[NN * NHEADS];
__device__ float g_adst[NN * NHEADS];
__device__ int   g_count[NN];
__device__ int   g_rowptr[NN + 1];
__device__ int   g_cursor[NN];
__device__ int   g_csrsrc[ETOT];

// ---------------- CSR build ----------------
__global__ void init_count_kernel(int n) {
    int i = blockIdx.x * blockDim.x + threadIdx.x;
    if (i < n) g_count[i] = 1;  // self loop
}

__global__ void count_kernel(const int* __restrict__ ei, int E, int n) {
    int i = blockIdx.x * blockDim.x + threadIdx.x;
    if (i < E) {
        int d = ei[E + i];      // dst row of edge_index
        atomicAdd(&g_count[d], 1);
    }
}

// single-block scan, 1024 threads, warp-shuffle based
__global__ void scan_kernel(int n) {
    __shared__ int warpsum[32];
    __shared__ int s_carry;
    int tid = threadIdx.x, lane = tid & 31, wid = tid >> 5;
    if (tid == 0) { s_carry = 0; g_rowptr[0] = 0; }
    __syncthreads();
    for (int base = 0; base < n; base += 1024) {
        int i = base + tid;
        int v = (i < n) ? g_count[i] : 0;
        int x = v;
        #pragma unroll
        for (int off = 1; off < 32; off <<= 1) {
            int y = __shfl_up_sync(0xffffffffu, x, off);
            if (lane >= off) x += y;
        }
        if (lane == 31) warpsum[wid] = x;
        __syncthreads();
        int woff = 0, tot = 0;
        #pragma unroll
        for (int w = 0; w < 32; w++) {
            int ws = warpsum[w];
            if (w < wid) woff += ws;
            tot += ws;
        }
        int carry = s_carry;
        int incl = carry + woff + x;
        if (i < n) {
            g_cursor[i]     = incl - v;   // exclusive
            g_rowptr[i + 1] = incl;
        }
        __syncthreads();
        if (tid == 0) s_carry = carry + tot;
        __syncthreads();
    }
}

__global__ void fill_kernel(const int* __restrict__ ei, int E, int n) {
    int i = blockIdx.x * blockDim.x + threadIdx.x;
    int tot = E + n;
    if (i >= tot) return;
    int s, d;
    if (i < E) { s = ei[i]; d = ei[E + i]; }
    else       { s = d = i - E; }
    int pos = atomicAdd(&g_cursor[d], 1);
    g_csrsrc[pos] = s;
}

// ---------------- transpose + tf32-round weights: Wt[n][k] = rna_tf32(W[k][n]) ----------------
__global__ void transpose_round_kernel(const float* __restrict__ W, float* __restrict__ Wt) {
    __shared__ float tile[32][33];
    int bx = blockIdx.x * 32, by = blockIdx.y * 32;
    int tx = threadIdx.x, ty = threadIdx.y;   // 32 x 8
    #pragma unroll
    for (int i = 0; i < 32; i += 8)
        tile[ty + i][tx] = W[(by + ty + i) * FEAT + bx + tx];
    __syncthreads();
    #pragma unroll
    for (int i = 0; i < 32; i += 8) {
        float v = tile[tx][ty + i];
        uint32_t o;
        asm("cvt.rna.tf32.f32 %0, %1;" : "=r"(o) : "f"(v));
        Wt[(bx + ty + i) * FEAT + by + tx] = __uint_as_float(o);
    }
}

// ---------------- TF32 tensor-core GEMM ----------------
// C[M,256] = A[M,256] @ Wt^T  (Wt is [n][k], i.e. B col-major for mma row.col)
// Block tile 128x128, BK=16, 8 warps of 32x64, cp.async double buffer.
#define GP 20                // smem pitch in floats (ldmatrix conflict-free)
#define STAGE_FLOATS (2 * 128 * GP)   // As + Bs per stage

__device__ __forceinline__ void ldsm_x4(uint32_t addr, uint32_t& r0, uint32_t& r1,
                                        uint32_t& r2, uint32_t& r3) {
    asm volatile("ldmatrix.sync.aligned.m8n8.x4.shared.b16 {%0,%1,%2,%3}, [%4];"
                 : "=r"(r0), "=r"(r1), "=r"(r2), "=r"(r3) : "r"(addr));
}

__device__ __forceinline__ uint32_t f2tf32(uint32_t x) {
    uint32_t o;
    asm("cvt.rna.tf32.f32 %0, %1;" : "=r"(o) : "f"(__uint_as_float(x)));
    return o;
}

__device__ __forceinline__ void mma_tf32(float* c, const uint32_t* a, const uint32_t* b) {
    asm volatile(
        "mma.sync.aligned.m16n8k8.row.col.f32.tf32.tf32.f32 "
        "{%0,%1,%2,%3}, {%4,%5,%6,%7}, {%8,%9}, {%0,%1,%2,%3};"
        : "+f"(c[0]), "+f"(c[1]), "+f"(c[2]), "+f"(c[3])
        : "r"(a[0]), "r"(a[1]), "r"(a[2]), "r"(a[3]), "r"(b[0]), "r"(b[1]));
}

__device__ __forceinline__ void cp16(uint32_t saddr, const void* gptr, uint32_t srcsize) {
    asm volatile("cp.async.ca.shared.global [%0], [%1], 16, %2;\n"
                 :: "r"(saddr), "l"(gptr), "r"(srcsize));
}

__global__ __launch_bounds__(256) void gemm_tf32_kernel(
    const float* __restrict__ A, const float* __restrict__ Wt,
    float* __restrict__ C, int M)
{
    __shared__ float smem[2 * STAGE_FLOATS];
    const int K = 256;
    int tid = threadIdx.x;
    int lane = tid & 31;
    int warp = tid >> 5;
    int wm = warp >> 1;          // 0..3
    int wn = warp & 1;           // 0..1
    int block_row = blockIdx.x * 128;
    int block_col = blockIdx.y * 128;

    uint32_t s_base = (uint32_t)__cvta_generic_to_shared(smem);
    uint32_t sA = s_base;
    uint32_t sB = s_base + 128 * GP * 4;
    const uint32_t stage_bytes = STAGE_FLOATS * 4;

    // ---- cp.async source/dest mapping: 2 A-chunks + 2 B-chunks of 16B per thread ----
    // chunk c in [0,512): row = c/4, col4 = (c%4)*4
    int c0i = tid * 2, c1i = tid * 2 + 1;
    int ar0 = c0i >> 2, ac0 = (c0i & 3) * 4;
    int ar1 = c1i >> 2, ac1 = (c1i & 3) * 4;
    uint32_t dstA0 = sA + (uint32_t)(ar0 * GP + ac0) * 4;
    uint32_t dstA1 = sA + (uint32_t)(ar1 * GP + ac1) * 4;
    uint32_t dstB0 = sB + (uint32_t)(ar0 * GP + ac0) * 4;
    uint32_t dstB1 = sB + (uint32_t)(ar1 * GP + ac1) * 4;
    int grA0 = block_row + ar0, grA1 = block_row + ar1;
    uint32_t szA0 = (grA0 < M) ? 16u : 0u;
    uint32_t szA1 = (grA1 < M) ? 16u : 0u;
    if (grA0 >= M) grA0 = 0;
    if (grA1 >= M) grA1 = 0;
    const float* srcA0 = A + (size_t)grA0 * K + ac0;
    const float* srcA1 = A + (size_t)grA1 * K + ac1;
    const float* srcB0 = Wt + (size_t)(block_col + ar0) * K + ac0;
    const float* srcB1 = Wt + (size_t)(block_col + ar1) * K + ac1;

    // ---- ldmatrix per-lane base addresses ----
    int g = lane >> 3, r = lane & 7;
    // A groups: row = (g&1)*8 + r, koff = (g>>1)*4
    int a_row_l = (g & 1) * 8 + r;
    int a_koff  = (g >> 1) * 4;
    uint32_t a_base[2];
    #pragma unroll
    for (int mt = 0; mt < 2; mt++)
        a_base[mt] = sA + (uint32_t)((wm * 32 + mt * 16 + a_row_l) * GP + a_koff) * 4;
    // B groups: n = (g>>1)*8 + r, koff = (g&1)*4
    int b_row_l = (g >> 1) * 8 + r;
    int b_koff  = (g & 1) * 4;
    uint32_t b_base[4];
    #pragma unroll
    for (int np = 0; np < 4; np++)
        b_base[np] = sB + (uint32_t)((wn * 64 + np * 16 + b_row_l) * GP + b_koff) * 4;

    float acc[2][8][4];
    #pragma unroll
    for (int mt = 0; mt < 2; mt++)
        #pragma unroll
        for (int nt = 0; nt < 8; nt++)
            #pragma unroll
            for (int q = 0; q < 4; q++) acc[mt][nt][q] = 0.f;

    // ---- prologue: load stage 0 ----
    cp16(dstA0, srcA0, szA0);
    cp16(dstA1, srcA1, szA1);
    cp16(dstB0, srcB0, 16u);
    cp16(dstB1, srcB1, 16u);
    asm volatile("cp.async.commit_group;\n" ::);

    const int NITER = K / 16;   // 16
    for (int it = 0; it < NITER; it++) {
        int buf = it & 1;
        if (it + 1 < NITER) {
            uint32_t off = ((it + 1) & 1) * stage_bytes;
            int k0 = (it + 1) * 16;
            cp16(dstA0 + off, srcA0 + k0, szA0);
            cp16(dstA1 + off, srcA1 + k0, szA1);
            cp16(dstB0 + off, srcB0 + k0, 16u);
            cp16(dstB1 + off, srcB1 + k0, 16u);
            asm volatile("cp.async.commit_group;\n" ::);
            asm volatile("cp.async.wait_group 1;\n" ::);
        } else {
            asm volatile("cp.async.wait_group 0;\n" ::);
        }
        __syncthreads();

        uint32_t soff = buf * stage_bytes;
        #pragma unroll
        for (int ks = 0; ks < 16; ks += 8) {
            uint32_t a[2][4], b[4][4];
            #pragma unroll
            for (int mt = 0; mt < 2; mt++) {
                ldsm_x4(a_base[mt] + soff + ks * 4, a[mt][0], a[mt][1], a[mt][2], a[mt][3]);
                #pragma unroll
                for (int q = 0; q < 4; q++) a[mt][q] = f2tf32(a[mt][q]);
            }
            #pragma unroll
            for (int np = 0; np < 4; np++)
                ldsm_x4(b_base[np] + soff + ks * 4, b[np][0], b[np][1], b[np][2], b[np][3]);
            #pragma unroll
            for (int mt = 0; mt < 2; mt++)
                #pragma unroll
                for (int nt = 0; nt < 8; nt++)
                    mma_tf32(acc[mt][nt], a[mt], &b[nt >> 1][(nt & 1) * 2]);
        }
        __syncthreads();
    }

    // ---- epilogue ----
    int cr = lane >> 2;          // l/4
    int cc = (lane & 3) * 2;     // 2*(l%4)
    #pragma unroll
    for (int mt = 0; mt < 2; mt++) {
        int row0 = block_row + wm * 32 + mt * 16 + cr;
        #pragma unroll
        for (int nt = 0; nt < 8; nt++) {
            int col = block_col + wn * 64 + nt * 8 + cc;
            if (row0 < M)
                *reinterpret_cast<float2*>(C + (size_t)row0 * 256 + col) =
                    make_float2(acc[mt][nt][0], acc[mt][nt][1]);
            if (row0 + 8 < M)
                *reinterpret_cast<float2*>(C + (size_t)(row0 + 8) * 256 + col) =
                    make_float2(acc[mt][nt][2], acc[mt][nt][3]);
        }
    }
}

// ---------------- attention logits ----------------
// layer 1: warp per (node, head); 64 channels, 2/lane
__global__ void att1_kernel(const float* __restrict__ xp,
                            const float* __restrict__ att_src,
                            const float* __restrict__ att_dst, int n)
{
    int warp = (blockIdx.x * blockDim.x + threadIdx.x) >> 5;
    int lane = threadIdx.x & 31;
    if (warp >= n * NHEADS) return;
    int node = warp >> 2, h = warp & 3;
    const float* row = xp + (size_t)node * FEAT + h * NHID;
    const float* ws  = att_src + h * NHID;
    const float* wd  = att_dst + h * NHID;
    float v1 = row[lane], v2 = row[lane + 32];
    float s = v1 * ws[lane] + v2 * ws[lane + 32];
    float d = v1 * wd[lane] + v2 * wd[lane + 32];
    #pragma unroll
    for (int off = 16; off; off >>= 1) {
        s += __shfl_xor_sync(0xffffffffu, s, off);
        d += __shfl_xor_sync(0xffffffffu, d, off);
    }
    if (lane == 0) { g_asrc[warp] = s; g_adst[warp] = d; }
}

// layer 2: warp per node; 256 channels, 8/lane
__global__ void att2_kernel(const float* __restrict__ xp,
                            const float* __restrict__ att_src,
                            const float* __restrict__ att_dst, int n)
{
    int warp = (blockIdx.x * blockDim.x + threadIdx.x) >> 5;
    int lane = threadIdx.x & 31;
    if (warp >= n) return;
    const float4* row = reinterpret_cast<const float4*>(xp + (size_t)warp * FEAT + lane * 8);
    const float4* s4  = reinterpret_cast<const float4*>(att_src + lane * 8);
    const float4* d4  = reinterpret_cast<const float4*>(att_dst + lane * 8);
    float4 a0 = row[0], a1 = row[1];
    float4 w0 = s4[0], w1 = s4[1];
    float4 u0 = d4[0], u1 = d4[1];
    float s = a0.x*w0.x + a0.y*w0.y + a0.z*w0.z + a0.w*w0.w
            + a1.x*w1.x + a1.y*w1.y + a1.z*w1.z + a1.w*w1.w;
    float d = a0.x*u0.x + a0.y*u0.y + a0.z*u0.z + a0.w*u0.w
            + a1.x*u1.x + a1.y*u1.y + a1.z*u1.z + a1.w*u1.w;
    #pragma unroll
    for (int off = 16; off; off >>= 1) {
        s += __shfl_xor_sync(0xffffffffu, s, off);
        d += __shfl_xor_sync(0xffffffffu, d, off);
    }
    if (lane == 0) { g_asrc[warp] = s; g_adst[warp] = d; }
}

__device__ __forceinline__ float leaky(float x) {
    return (x > 0.f) ? x : NEG_SLOPE * x;
}

// ---------------- aggregation, layer 1 (4 heads) + bias + ELU ----------------
__global__ void agg1_kernel(const float* __restrict__ xp,
                            const float* __restrict__ bias,
                            float* __restrict__ out, int n)
{
    int node = (blockIdx.x * blockDim.x + threadIdx.x) >> 5;
    if (node >= n) return;
    int lane = threadIdx.x & 31;
    int h  = lane >> 3;         // 8 lanes per head (64 ch / 8 per lane)
    int c0 = lane * 8;
    float ad = g_adst[node * NHEADS + h];
    int beg = g_rowptr[node], end = g_rowptr[node + 1];
    float m = -1e30f, s = 0.f;
    float acc[8] = {0,0,0,0,0,0,0,0};
    for (int p = beg; p < end; p++) {
        int j = g_csrsrc[p];
        float e = leaky(g_asrc[j * NHEADS + h] + ad);
        float mn = fmaxf(m, e);
        float corr = __expf(m - mn);
        float pw   = __expf(e - mn);
        s = s * corr + pw;
        const float4* xr = reinterpret_cast<const float4*>(xp + (size_t)j * FEAT + c0);
        float4 v0 = xr[0], v1 = xr[1];
        acc[0] = acc[0] * corr + pw * v0.x;
        acc[1] = acc[1] * corr + pw * v0.y;
        acc[2] = acc[2] * corr + pw * v0.z;
        acc[3] = acc[3] * corr + pw * v0.w;
        acc[4] = acc[4] * corr + pw * v1.x;
        acc[5] = acc[5] * corr + pw * v1.y;
        acc[6] = acc[6] * corr + pw * v1.z;
        acc[7] = acc[7] * corr + pw * v1.w;
        m = mn;
    }
    float inv = 1.f / s;   // denom >= 1 (self-loop/max edge contributes exp(0))
    const float4* b4 = reinterpret_cast<const float4*>(bias + c0);
    float4 b0 = b4[0], b1 = b4[1];
    float vb[8] = {b0.x, b0.y, b0.z, b0.w, b1.x, b1.y, b1.z, b1.w};
    float v[8];
    #pragma unroll
    for (int k = 0; k < 8; k++) {
        float t = acc[k] * inv + vb[k];
        v[k] = (t > 0.f) ? t : expm1f(t);   // ELU
    }
    float4 o0 = make_float4(v[0], v[1], v[2], v[3]);
    float4 o1 = make_float4(v[4], v[5], v[6], v[7]);
    float4* orow = reinterpret_cast<float4*>(out + (size_t)node * FEAT + c0);
    orow[0] = o0; orow[1] = o1;
}

// ---------------- aggregation, layer 2 (1 head) + bias + ELU + BN + LN ----------------
__global__ void agg2_kernel(const float* __restrict__ xp,
                            const float* __restrict__ bias,
                            const float* __restrict__ bn_gamma,
                            const float* __restrict__ bn_beta,
                            const float* __restrict__ bn_mean,
                            const float* __restrict__ bn_var,
                            const float* __restrict__ ln_gamma,
                            const float* __restrict__ ln_beta,
                            float* __restrict__ out, int n)
{
    int node = (blockIdx.x * blockDim.x + threadIdx.x) >> 5;
    if (node >= n) return;
    int lane = threadIdx.x & 31;
    int c0 = lane * 8;
    float ad = g_adst[node];
    int beg = g_rowptr[node], end = g_rowptr[node + 1];
    float m = -1e30f, s = 0.f;
    float acc[8] = {0,0,0,0,0,0,0,0};
    for (int p = beg; p < end; p++) {
        int j = g_csrsrc[p];
        float e = leaky(g_asrc[j] + ad);
        float mn = fmaxf(m, e);
        float corr = __expf(m - mn);
        float pw   = __expf(e - mn);
        s = s * corr + pw;
        const float4* xr = reinterpret_cast<const float4*>(xp + (size_t)j * FEAT + c0);
        float4 v0 = xr[0], v1 = xr[1];
        acc[0] = acc[0] * corr + pw * v0.x;
        acc[1] = acc[1] * corr + pw * v0.y;
        acc[2] = acc[2] * corr + pw * v0.z;
        acc[3] = acc[3] * corr + pw * v0.w;
        acc[4] = acc[4] * corr + pw * v1.x;
        acc[5] = acc[5] * corr + pw * v1.y;
        acc[6] = acc[6] * corr + pw * v1.z;
        acc[7] = acc[7] * corr + pw * v1.w;
        m = mn;
    }
    float inv = 1.f / s;
    float v[8];
    #pragma unroll
    for (int k = 0; k < 8; k++) {
        int c = c0 + k;
        float x = acc[k] * inv + bias[c];
        x = (x > 0.f) ? x : expm1f(x);                           // ELU
        x = (x - bn_mean[c]) * rsqrtf(bn_var[c] + BN_EPS) * bn_gamma[c] + bn_beta[c];  // BN eval
        v[k] = x;
    }
    // LayerNorm over 256 channels (warp = row, 8 ch/lane)
    float lsum = 0.f;
    #pragma unroll
    for (int k = 0; k < 8; k++) lsum += v[k];
    #pragma unroll
    for (int off = 16; off; off >>= 1) lsum += __shfl_xor_sync(0xffffffffu, lsum, off);
    float mu = lsum * (1.f / 256.f);
    float lvar = 0.f;
    #pragma unroll
    for (int k = 0; k < 8; k++) { float d = v[k] - mu; lvar += d * d; }
    #pragma unroll
    for (int off = 16; off; off >>= 1) lvar += __shfl_xor_sync(0xffffffffu, lvar, off);
    float r = rsqrtf(lvar * (1.f / 256.f) + LN_EPS);
    float w[8];
    #pragma unroll
    for (int k = 0; k < 8; k++) {
        int c = c0 + k;
        w[k] = (v[k] - mu) * r * ln_gamma[c] + ln_beta[c];
    }
    float4 o0 = make_float4(w[0], w[1], w[2], w[3]);
    float4 o1 = make_float4(w[4], w[5], w[6], w[7]);
    float4* orow = reinterpret_cast<float4*>(out + (size_t)node * FEAT + c0);
    orow[0] = o0; orow[1] = o1;
}

// ---------------- launch ----------------
extern "C" void kernel_launch(void* const* d_in, const int* in_sizes, int n_in,
                              void* d_out, int out_size)
{
    const float* x        = (const float*)d_in[0];
    const int*   ei       = (const int*)  d_in[1];
    const float* W1       = (const float*)d_in[2];
    const float* att_src1 = (const float*)d_in[3];
    const float* att_dst1 = (const float*)d_in[4];
    const float* bias1    = (const float*)d_in[5];
    const float* W2       = (const float*)d_in[6];
    const float* att_src2 = (const float*)d_in[7];
    const float* att_dst2 = (const float*)d_in[8];
    const float* bias2    = (const float*)d_in[9];
    const float* bn_gamma = (const float*)d_in[10];
    const float* bn_beta  = (const float*)d_in[11];
    const float* bn_mean  = (const float*)d_in[12];
    const float* bn_var   = (const float*)d_in[13];
    const float* ln_gamma = (const float*)d_in[14];
    const float* ln_beta  = (const float*)d_in[15];
    float* out = (float*)d_out;

    int n = in_sizes[0] / FEAT;      // 50000
    int E = in_sizes[1] / 2;         // 800000
    if (n > NN) n = NN;
    if (E > EMAX) E = EMAX;

    float *xp, *h1, *wt1, *wt2;
    cudaGetSymbolAddress((void**)&xp,  g_xp);
    cudaGetSymbolAddress((void**)&h1,  g_h1);
    cudaGetSymbolAddress((void**)&wt1, g_wt1);
    cudaGetSymbolAddress((void**)&wt2, g_wt2);

    // --- CSR build ---
    init_count_kernel<<<(n + 255) / 256, 256>>>(n);
    count_kernel<<<(E + 255) / 256, 256>>>(ei, E, n);
    scan_kernel<<<1, 1024>>>(n);
    fill_kernel<<<(E + n + 255) / 256, 256>>>(ei, E, n);

    // --- weight transpose + tf32 rounding ---
    dim3 tgrid(FEAT / 32, FEAT / 32), tblk(32, 8);
    transpose_round_kernel<<<tgrid, tblk>>>(W1, wt1);
    transpose_round_kernel<<<tgrid, tblk>>>(W2, wt2);

    dim3 ggrid((n + 127) / 128, FEAT / 128);

    // --- layer 1 ---
    gemm_tf32_kernel<<<ggrid, 256>>>(x, wt1, xp, n);
    att1_kernel<<<(n * NHEADS * 32 + 255) / 256, 256>>>(xp, att_src1, att_dst1, n);
    agg1_kernel<<<(n * 32 + 255) / 256, 256>>>(xp, bias1, h1, n);

    // --- layer 2 (reuse xp buffer) ---
    gemm_tf32_kernel<<<ggrid, 256>>>(h1, wt2, xp, n);
    att2_kernel<<<(n * 32 + 255) / 256, 256>>>(xp, att_src2, att_dst2, n);
    agg2_kernel<<<(n * 32 + 255) / 256, 256>>>(xp, bias2, bn_gamma, bn_beta, bn_mean,
                                               bn_var, ln_gamma, ln_beta, out, n);
    (void)n_in; (void)out_size;
}

// round 5
// speedup vs baseline: 1.8335x; 1.2257x over previous
#include <cuda_runtime.h>
#include <cuda_bf16.h>
#include <math.h>
#include <stdint.h>

// ---------------- problem constants ----------------
#define NN      50000      // nodes
#define EMAX    800000     // edges (before self loops)
#define ETOT    (EMAX + NN)
#define FEAT    256        // NFEAT = NHEADS*NHID = NOUT = 256
#define NHEADS  4
#define NHID    64
#define NEG_SLOPE 0.2f
#define BN_EPS  1e-5f
#define LN_EPS  1e-5f

// ---------------- scratch (device globals; no runtime alloc) ----------------
__device__ float g_xp[NN * FEAT];              // xp of current layer (fp32, reused)
__device__ float g_h1[NN * FEAT];              // layer-1 output (ELU'd)
__device__ float g_wt1[FEAT * FEAT];           // W1^T, tf32-rounded, [n][k]
__device__ float g_wt2[FEAT * FEAT];           // W2^T, tf32-rounded, [n][k]
__device__ float g_asrc[NN * NHEADS];          // layer-1 logits (per head)
__device__ float g_adst[NN * NHEADS];
__device__ float g_asrc2[NN];                  // layer-2 logits (atomic-accumulated)
__device__ float g_adst2[NN];
__device__ int   g_count[NN];
__device__ int   g_rowptr[NN + 1];
__device__ int   g_cursor[NN];
__device__ int   g_csrsrc[ETOT];

// ---------------- CSR build ----------------
__global__ void init_count_kernel(int n) {
    int i = blockIdx.x * blockDim.x + threadIdx.x;
    if (i < n) {
        g_count[i] = 1;  // self loop
        g_asrc2[i] = 0.f;
        g_adst2[i] = 0.f;
    }
}

__global__ void count_kernel(const int* __restrict__ ei, int E, int n) {
    int i = blockIdx.x * blockDim.x + threadIdx.x;
    if (i < E) {
        int d = ei[E + i];      // dst row of edge_index
        atomicAdd(&g_count[d], 1);
    }
}

// single-block scan, 1024 threads, warp-shuffle based
__global__ void scan_kernel(int n) {
    __shared__ int warpsum[32];
    __shared__ int s_carry;
    int tid = threadIdx.x, lane = tid & 31, wid = tid >> 5;
    if (tid == 0) { s_carry = 0; g_rowptr[0] = 0; }
    __syncthreads();
    for (int base = 0; base < n; base += 1024) {
        int i = base + tid;
        int v = (i < n) ? g_count[i] : 0;
        int x = v;
        #pragma unroll
        for (int off = 1; off < 32; off <<= 1) {
            int y = __shfl_up_sync(0xffffffffu, x, off);
            if (lane >= off) x += y;
        }
        if (lane == 31) warpsum[wid] = x;
        __syncthreads();
        int woff = 0, tot = 0;
        #pragma unroll
        for (int w = 0; w < 32; w++) {
            int ws = warpsum[w];
            if (w < wid) woff += ws;
            tot += ws;
        }
        int carry = s_carry;
        int incl = carry + woff + x;
        if (i < n) {
            g_cursor[i]     = incl - v;   // exclusive
            g_rowptr[i + 1] = incl;
        }
        __syncthreads();
        if (tid == 0) s_carry = carry + tot;
        __syncthreads();
    }
}

__global__ void fill_kernel(const int* __restrict__ ei, int E, int n) {
    int i = blockIdx.x * blockDim.x + threadIdx.x;
    int tot = E + n;
    if (i >= tot) return;
    int s, d;
    if (i < E) { s = ei[i]; d = ei[E + i]; }
    else       { s = d = i - E; }
    int pos = atomicAdd(&g_cursor[d], 1);
    g_csrsrc[pos] = s;
}

// ---------------- transpose + tf32-round weights: Wt[n][k] = rna_tf32(W[k][n]) ----------------
__global__ void transpose_round_kernel(const float* __restrict__ W, float* __restrict__ Wt) {
    __shared__ float tile[32][33];
    int bx = blockIdx.x * 32, by = blockIdx.y * 32;
    int tx = threadIdx.x, ty = threadIdx.y;   // 32 x 8
    #pragma unroll
    for (int i = 0; i < 32; i += 8)
        tile[ty + i][tx] = W[(by + ty + i) * FEAT + bx + tx];
    __syncthreads();
    #pragma unroll
    for (int i = 0; i < 32; i += 8) {
        float v = tile[tx][ty + i];
        uint32_t o;
        asm("cvt.rna.tf32.f32 %0, %1;" : "=r"(o) : "f"(v));
        Wt[(bx + ty + i) * FEAT + by + tx] = __uint_as_float(o);
    }
}

// ---------------- TF32 tensor-core GEMM with fused attention-logit epilogue ----------------
// C[M,256] = A[M,256] @ Wt^T  (Wt is [n][k], i.e. B col-major for mma row.col)
// Block tile 128x128, BK=16, 8 warps of 32x64, cp.async double buffer.
// Epilogue: per-warp 64-col partial dots with att_src/att_dst.
//   HEADS=4: warp's 64 cols == one head -> direct store of per-head logits.
//   HEADS=1: atomicAdd partials (cols split across 2 col-blocks).
#define GP 20                // smem pitch in floats (ldmatrix conflict-free)
#define STAGE_FLOATS (2 * 128 * GP)   // As + Bs per stage

__device__ __forceinline__ void ldsm_x4(uint32_t addr, uint32_t& r0, uint32_t& r1,
                                        uint32_t& r2, uint32_t& r3) {
    asm volatile("ldmatrix.sync.aligned.m8n8.x4.shared.b16 {%0,%1,%2,%3}, [%4];"
                 : "=r"(r0), "=r"(r1), "=r"(r2), "=r"(r3) : "r"(addr));
}

__device__ __forceinline__ uint32_t f2tf32(uint32_t x) {
    uint32_t o;
    asm("cvt.rna.tf32.f32 %0, %1;" : "=r"(o) : "f"(__uint_as_float(x)));
    return o;
}

__device__ __forceinline__ void mma_tf32(float* c, const uint32_t* a, const uint32_t* b) {
    asm volatile(
        "mma.sync.aligned.m16n8k8.row.col.f32.tf32.tf32.f32 "
        "{%0,%1,%2,%3}, {%4,%5,%6,%7}, {%8,%9}, {%0,%1,%2,%3};"
        : "+f"(c[0]), "+f"(c[1]), "+f"(c[2]), "+f"(c[3])
        : "r"(a[0]), "r"(a[1]), "r"(a[2]), "r"(a[3]), "r"(b[0]), "r"(b[1]));
}

__device__ __forceinline__ void cp16(uint32_t saddr, const void* gptr, uint32_t srcsize) {
    asm volatile("cp.async.ca.shared.global [%0], [%1], 16, %2;\n"
                 :: "r"(saddr), "l"(gptr), "r"(srcsize));
}

template<int HEADS>
__global__ __launch_bounds__(256) void gemm_att_kernel(
    const float* __restrict__ A, const float* __restrict__ Wt,
    float* __restrict__ C,
    const float* __restrict__ attS, const float* __restrict__ attD,
    float* __restrict__ oS, float* __restrict__ oD, int M)
{
    __shared__ float smem[2 * STAGE_FLOATS];
    const int K = 256;
    int tid = threadIdx.x;
    int lane = tid & 31;
    int warp = tid >> 5;
    int wm = warp >> 1;          // 0..3
    int wn = warp & 1;           // 0..1
    int block_row = blockIdx.x * 128;
    int block_col = blockIdx.y * 128;

    uint32_t s_base = (uint32_t)__cvta_generic_to_shared(smem);
    uint32_t sA = s_base;
    uint32_t sB = s_base + 128 * GP * 4;
    const uint32_t stage_bytes = STAGE_FLOATS * 4;

    // ---- cp.async source/dest mapping: 2 A-chunks + 2 B-chunks of 16B per thread ----
    int c0i = tid * 2, c1i = tid * 2 + 1;
    int ar0 = c0i >> 2, ac0 = (c0i & 3) * 4;
    int ar1 = c1i >> 2, ac1 = (c1i & 3) * 4;
    uint32_t dstA0 = sA + (uint32_t)(ar0 * GP + ac0) * 4;
    uint32_t dstA1 = sA + (uint32_t)(ar1 * GP + ac1) * 4;
    uint32_t dstB0 = sB + (uint32_t)(ar0 * GP + ac0) * 4;
    uint32_t dstB1 = sB + (uint32_t)(ar1 * GP + ac1) * 4;
    int grA0 = block_row + ar0, grA1 = block_row + ar1;
    uint32_t szA0 = (grA0 < M) ? 16u : 0u;
    uint32_t szA1 = (grA1 < M) ? 16u : 0u;
    if (grA0 >= M) grA0 = 0;
    if (grA1 >= M) grA1 = 0;
    const float* srcA0 = A + (size_t)grA0 * K + ac0;
    const float* srcA1 = A + (size_t)grA1 * K + ac1;
    const float* srcB0 = Wt + (size_t)(block_col + ar0) * K + ac0;
    const float* srcB1 = Wt + (size_t)(block_col + ar1) * K + ac1;

    // ---- ldmatrix per-lane base addresses ----
    int g = lane >> 3, r = lane & 7;
    int a_row_l = (g & 1) * 8 + r;
    int a_koff  = (g >> 1) * 4;
    uint32_t a_base[2];
    #pragma unroll
    for (int mt = 0; mt < 2; mt++)
        a_base[mt] = sA + (uint32_t)((wm * 32 + mt * 16 + a_row_l) * GP + a_koff) * 4;
    int b_row_l = (g >> 1) * 8 + r;
    int b_koff  = (g & 1) * 4;
    uint32_t b_base[4];
    #pragma unroll
    for (int np = 0; np < 4; np++)
        b_base[np] = sB + (uint32_t)((wn * 64 + np * 16 + b_row_l) * GP + b_koff) * 4;

    float acc[2][8][4];
    #pragma unroll
    for (int mt = 0; mt < 2; mt++)
        #pragma unroll
        for (int nt = 0; nt < 8; nt++)
            #pragma unroll
            for (int q = 0; q < 4; q++) acc[mt][nt][q] = 0.f;

    // ---- prologue: load stage 0 ----
    cp16(dstA0, srcA0, szA0);
    cp16(dstA1, srcA1, szA1);
    cp16(dstB0, srcB0, 16u);
    cp16(dstB1, srcB1, 16u);
    asm volatile("cp.async.commit_group;\n" ::);

    const int NITER = K / 16;   // 16
    for (int it = 0; it < NITER; it++) {
        int buf = it & 1;
        if (it + 1 < NITER) {
            uint32_t off = ((it + 1) & 1) * stage_bytes;
            int k0 = (it + 1) * 16;
            cp16(dstA0 + off, srcA0 + k0, szA0);
            cp16(dstA1 + off, srcA1 + k0, szA1);
            cp16(dstB0 + off, srcB0 + k0, 16u);
            cp16(dstB1 + off, srcB1 + k0, 16u);
            asm volatile("cp.async.commit_group;\n" ::);
            asm volatile("cp.async.wait_group 1;\n" ::);
        } else {
            asm volatile("cp.async.wait_group 0;\n" ::);
        }
        __syncthreads();

        uint32_t soff = buf * stage_bytes;
        #pragma unroll
        for (int ks = 0; ks < 16; ks += 8) {
            uint32_t a[2][4], b[4][4];
            #pragma unroll
            for (int mt = 0; mt < 2; mt++) {
                ldsm_x4(a_base[mt] + soff + ks * 4, a[mt][0], a[mt][1], a[mt][2], a[mt][3]);
                #pragma unroll
                for (int q = 0; q < 4; q++) a[mt][q] = f2tf32(a[mt][q]);
            }
            #pragma unroll
            for (int np = 0; np < 4; np++)
                ldsm_x4(b_base[np] + soff + ks * 4, b[np][0], b[np][1], b[np][2], b[np][3]);
            #pragma unroll
            for (int mt = 0; mt < 2; mt++)
                #pragma unroll
                for (int nt = 0; nt < 8; nt++)
                    mma_tf32(acc[mt][nt], a[mt], &b[nt >> 1][(nt & 1) * 2]);
        }
        __syncthreads();
    }

    // ---- epilogue: fp32 stores ----
    int cr = lane >> 2;          // l/4
    int cc = (lane & 3) * 2;     // 2*(l%4)
    #pragma unroll
    for (int mt = 0; mt < 2; mt++) {
        int row0 = block_row + wm * 32 + mt * 16 + cr;
        #pragma unroll
        for (int nt = 0; nt < 8; nt++) {
            int col = block_col + wn * 64 + nt * 8 + cc;
            if (row0 < M)
                *reinterpret_cast<float2*>(C + (size_t)row0 * 256 + col) =
                    make_float2(acc[mt][nt][0], acc[mt][nt][1]);
            if (row0 + 8 < M)
                *reinterpret_cast<float2*>(C + (size_t)(row0 + 8) * 256 + col) =
                    make_float2(acc[mt][nt][2], acc[mt][nt][3]);
        }
    }

    // ---- epilogue: fused attention-logit partial dots over this warp's 64 cols ----
    float ps[2][2] = {{0.f,0.f},{0.f,0.f}};
    float pd[2][2] = {{0.f,0.f},{0.f,0.f}};
    #pragma unroll
    for (int mt = 0; mt < 2; mt++) {
        #pragma unroll
        for (int nt = 0; nt < 8; nt++) {
            int lc = nt * 8 + cc;
            int idx = (HEADS == 4) ? ((blockIdx.y * 2 + wn) * 64 + lc)
                                   : (block_col + wn * 64 + lc);
            float as0 = attS[idx], as1 = attS[idx + 1];
            float ad0 = attD[idx], ad1 = attD[idx + 1];
            ps[mt][0] += acc[mt][nt][0] * as0 + acc[mt][nt][1] * as1;
            ps[mt][1] += acc[mt][nt][2] * as0 + acc[mt][nt][3] * as1;
            pd[mt][0] += acc[mt][nt][0] * ad0 + acc[mt][nt][1] * ad1;
            pd[mt][1] += acc[mt][nt][2] * ad0 + acc[mt][nt][3] * ad1;
        }
    }
    #pragma unroll
    for (int mt = 0; mt < 2; mt++)
        #pragma unroll
        for (int hf = 0; hf < 2; hf++) {
            ps[mt][hf] += __shfl_xor_sync(0xffffffffu, ps[mt][hf], 1);
            ps[mt][hf] += __shfl_xor_sync(0xffffffffu, ps[mt][hf], 2);
            pd[mt][hf] += __shfl_xor_sync(0xffffffffu, pd[mt][hf], 1);
            pd[mt][hf] += __shfl_xor_sync(0xffffffffu, pd[mt][hf], 2);
        }
    if ((lane & 3) == 0) {
        #pragma unroll
        for (int mt = 0; mt < 2; mt++)
            #pragma unroll
            for (int hf = 0; hf < 2; hf++) {
                int node = block_row + wm * 32 + mt * 16 + cr + hf * 8;
                if (node < M) {
                    if (HEADS == 4) {
                        int head = blockIdx.y * 2 + wn;
                        oS[node * 4 + head] = ps[mt][hf];
                        oD[node * 4 + head] = pd[mt][hf];
                    } else {
                        atomicAdd(&oS[node], ps[mt][hf]);
                        atomicAdd(&oD[node], pd[mt][hf]);
                    }
                }
            }
    }
}

__device__ __forceinline__ float leaky(float x) {
    return (x > 0.f) ? x : NEG_SLOPE * x;
}

// ---------------- aggregation, layer 1 (4 heads) + bias + ELU ----------------
__global__ void agg1_kernel(const float* __restrict__ xp,
                            const float* __restrict__ bias,
                            float* __restrict__ out, int n)
{
    int node = (blockIdx.x * blockDim.x + threadIdx.x) >> 5;
    if (node >= n) return;
    int lane = threadIdx.x & 31;
    int h  = lane >> 3;         // 8 lanes per head (64 ch / 8 per lane)
    int c0 = lane * 8;
    float ad = g_adst[node * NHEADS + h];
    int beg = g_rowptr[node], end = g_rowptr[node + 1];
    float m = -1e30f, s = 0.f;
    float acc[8] = {0,0,0,0,0,0,0,0};
    for (int p = beg; p < end; p++) {
        int j = g_csrsrc[p];
        float e = leaky(g_asrc[j * NHEADS + h] + ad);
        float mn = fmaxf(m, e);
        float corr = __expf(m - mn);
        float pw   = __expf(e - mn);
        s = s * corr + pw;
        const float4* xr = reinterpret_cast<const float4*>(xp + (size_t)j * FEAT + c0);
        float4 v0 = xr[0], v1 = xr[1];
        acc[0] = acc[0] * corr + pw * v0.x;
        acc[1] = acc[1] * corr + pw * v0.y;
        acc[2] = acc[2] * corr + pw * v0.z;
        acc[3] = acc[3] * corr + pw * v0.w;
        acc[4] = acc[4] * corr + pw * v1.x;
        acc[5] = acc[5] * corr + pw * v1.y;
        acc[6] = acc[6] * corr + pw * v1.z;
        acc[7] = acc[7] * corr + pw * v1.w;
        m = mn;
    }
    float inv = 1.f / s;   // denom >= 1 (self-loop/max edge contributes exp(0))
    const float4* b4 = reinterpret_cast<const float4*>(bias + c0);
    float4 b0 = b4[0], b1 = b4[1];
    float vb[8] = {b0.x, b0.y, b0.z, b0.w, b1.x, b1.y, b1.z, b1.w};
    float v[8];
    #pragma unroll
    for (int k = 0; k < 8; k++) {
        float t = acc[k] * inv + vb[k];
        v[k] = (t > 0.f) ? t : expm1f(t);   // ELU
    }
    float4 o0 = make_float4(v[0], v[1], v[2], v[3]);
    float4 o1 = make_float4(v[4], v[5], v[6], v[7]);
    float4* orow = reinterpret_cast<float4*>(out + (size_t)node * FEAT + c0);
    orow[0] = o0; orow[1] = o1;
}

// ---------------- aggregation, layer 2 (1 head) + bias + ELU + BN + LN ----------------
__global__ void agg2_kernel(const float* __restrict__ xp,
                            const float* __restrict__ bias,
                            const float* __restrict__ bn_gamma,
                            const float* __restrict__ bn_beta,
                            const float* __restrict__ bn_mean,
                            const float* __restrict__ bn_var,
                            const float* __restrict__ ln_gamma,
                            const float* __restrict__ ln_beta,
                            float* __restrict__ out, int n)
{
    int node = (blockIdx.x * blockDim.x + threadIdx.x) >> 5;
    if (node >= n) return;
    int lane = threadIdx.x & 31;
    int c0 = lane * 8;
    float ad = g_adst2[node];
    int beg = g_rowptr[node], end = g_rowptr[node + 1];
    float m = -1e30f, s = 0.f;
    float acc[8] = {0,0,0,0,0,0,0,0};
    for (int p = beg; p < end; p++) {
        int j = g_csrsrc[p];
        float e = leaky(g_asrc2[j] + ad);
        float mn = fmaxf(m, e);
        float corr = __expf(m - mn);
        float pw   = __expf(e - mn);
        s = s * corr + pw;
        const float4* xr = reinterpret_cast<const float4*>(xp + (size_t)j * FEAT + c0);
        float4 v0 = xr[0], v1 = xr[1];
        acc[0] = acc[0] * corr + pw * v0.x;
        acc[1] = acc[1] * corr + pw * v0.y;
        acc[2] = acc[2] * corr + pw * v0.z;
        acc[3] = acc[3] * corr + pw * v0.w;
        acc[4] = acc[4] * corr + pw * v1.x;
        acc[5] = acc[5] * corr + pw * v1.y;
        acc[6] = acc[6] * corr + pw * v1.z;
        acc[7] = acc[7] * corr + pw * v1.w;
        m = mn;
    }
    float inv = 1.f / s;
    float v[8];
    #pragma unroll
    for (int k = 0; k < 8; k++) {
        int c = c0 + k;
        float x = acc[k] * inv + bias[c];
        x = (x > 0.f) ? x : expm1f(x);                           // ELU
        x = (x - bn_mean[c]) * rsqrtf(bn_var[c] + BN_EPS) * bn_gamma[c] + bn_beta[c];  // BN eval
        v[k] = x;
    }
    // LayerNorm over 256 channels (warp = row, 8 ch/lane)
    float lsum = 0.f;
    #pragma unroll
    for (int k = 0; k < 8; k++) lsum += v[k];
    #pragma unroll
    for (int off = 16; off; off >>= 1) lsum += __shfl_xor_sync(0xffffffffu, lsum, off);
    float mu = lsum * (1.f / 256.f);
    float lvar = 0.f;
    #pragma unroll
    for (int k = 0; k < 8; k++) { float d = v[k] - mu; lvar += d * d; }
    #pragma unroll
    for (int off = 16; off; off >>= 1) lvar += __shfl_xor_sync(0xffffffffu, lvar, off);
    float r = rsqrtf(lvar * (1.f / 256.f) + LN_EPS);
    float w[8];
    #pragma unroll
    for (int k = 0; k < 8; k++) {
        int c = c0 + k;
        w[k] = (v[k] - mu) * r * ln_gamma[c] + ln_beta[c];
    }
    float4 o0 = make_float4(w[0], w[1], w[2], w[3]);
    float4 o1 = make_float4(w[4], w[5], w[6], w[7]);
    float4* orow = reinterpret_cast<float4*>(out + (size_t)node * FEAT + c0);
    orow[0] = o0; orow[1] = o1;
}

// ---------------- launch ----------------
extern "C" void kernel_launch(void* const* d_in, const int* in_sizes, int n_in,
                              void* d_out, int out_size)
{
    const float* x        = (const float*)d_in[0];
    const int*   ei       = (const int*)  d_in[1];
    const float* W1       = (const float*)d_in[2];
    const float* att_src1 = (const float*)d_in[3];
    const float* att_dst1 = (const float*)d_in[4];
    const float* bias1    = (const float*)d_in[5];
    const float* W2       = (const float*)d_in[6];
    const float* att_src2 = (const float*)d_in[7];
    const float* att_dst2 = (const float*)d_in[8];
    const float* bias2    = (const float*)d_in[9];
    const float* bn_gamma = (const float*)d_in[10];
    const float* bn_beta  = (const float*)d_in[11];
    const float* bn_mean  = (const float*)d_in[12];
    const float* bn_var   = (const float*)d_in[13];
    const float* ln_gamma = (const float*)d_in[14];
    const float* ln_beta  = (const float*)d_in[15];
    float* out = (float*)d_out;

    int n = in_sizes[0] / FEAT;      // 50000
    int E = in_sizes[1] / 2;         // 800000
    if (n > NN) n = NN;
    if (E > EMAX) E = EMAX;

    float *xp, *h1, *wt1, *wt2, *asrc, *adst, *asrc2, *adst2;
    cudaGetSymbolAddress((void**)&xp,    g_xp);
    cudaGetSymbolAddress((void**)&h1,    g_h1);
    cudaGetSymbolAddress((void**)&wt1,   g_wt1);
    cudaGetSymbolAddress((void**)&wt2,   g_wt2);
    cudaGetSymbolAddress((void**)&asrc,  g_asrc);
    cudaGetSymbolAddress((void**)&adst,  g_adst);
    cudaGetSymbolAddress((void**)&asrc2, g_asrc2);
    cudaGetSymbolAddress((void**)&adst2, g_adst2);

    // lazy side-stream / event creation (first call is outside graph capture)
    static cudaStream_t s_side = nullptr;
    static cudaEvent_t  s_evF  = nullptr, s_evJ = nullptr;
    if (s_side == nullptr) {
        cudaStreamCreateWithFlags(&s_side, cudaStreamNonBlocking);
        cudaEventCreateWithFlags(&s_evF, cudaEventDisableTiming);
        cudaEventCreateWithFlags(&s_evJ, cudaEventDisableTiming);
    }

    // --- fork: CSR build on side stream, GEMM path on main stream ---
    cudaEventRecord(s_evF, 0);
    cudaStreamWaitEvent(s_side, s_evF, 0);
    init_count_kernel<<<(n + 255) / 256, 256, 0, s_side>>>(n);
    count_kernel<<<(E + 255) / 256, 256, 0, s_side>>>(ei, E, n);
    scan_kernel<<<1, 1024, 0, s_side>>>(n);
    fill_kernel<<<(E + n + 255) / 256, 256, 0, s_side>>>(ei, E, n);
    cudaEventRecord(s_evJ, s_side);

    // --- main stream: weight prep + layer-1 GEMM (att logits fused) ---
    dim3 tgrid(FEAT / 32, FEAT / 32), tblk(32, 8);
    transpose_round_kernel<<<tgrid, tblk>>>(W1, wt1);
    transpose_round_kernel<<<tgrid, tblk>>>(W2, wt2);

    dim3 ggrid((n + 127) / 128, FEAT / 128);
    gemm_att_kernel<4><<<ggrid, 256>>>(x, wt1, xp,
                                       att_src1, att_dst1, asrc, adst, n);

    // --- join: CSR ready ---
    cudaStreamWaitEvent(0, s_evJ, 0);

    agg1_kernel<<<(n * 32 + 255) / 256, 256>>>(xp, bias1, h1, n);

    // --- layer 2 (h1 -> xp reuse is safe: agg1 wrote h1, gemm reads h1, writes xp) ---
    gemm_att_kernel<1><<<ggrid, 256>>>(h1, wt2, xp,
                                       att_src2, att_dst2, asrc2, adst2, n);
    agg2_kernel<<<(n * 32 + 255) / 256, 256>>>(xp, bias2, bn_gamma, bn_beta, bn_mean,
                                               bn_var, ln_gamma, ln_beta, out, n);
    (void)n_in; (void)out_size;
}

// round 6
// speedup vs baseline: 1.8370x; 1.0019x over previous
#include <cuda_runtime.h>
#include <cuda_bf16.h>
#include <math.h>
#include <stdint.h>

// ---------------- problem constants ----------------
#define NN      50000      // nodes
#define EMAX    800000     // edges (before self loops)
#define ETOT    (EMAX + NN)
#define FEAT    256        // NFEAT = NHEADS*NHID = NOUT = 256
#define NHEADS  4
#define NHID    64
#define NEG_SLOPE 0.2f
#define BN_EPS  1e-5f
#define LN_EPS  1e-5f

// ---------------- scratch (device globals; no runtime alloc) ----------------
__device__ float g_xp[NN * FEAT];              // xp of current layer (fp32, reused)
__device__ float g_h1[NN * FEAT];              // layer-1 output (ELU'd)
__device__ float g_wt1[FEAT * FEAT];           // W1^T, tf32-rounded, [n][k]
__device__ float g_wt2[FEAT * FEAT];           // W2^T, tf32-rounded, [n][k]
__device__ float g_asrc[NN * NHEADS];          // layer-1 logits (per head)
__device__ float g_adst[NN * NHEADS];
__device__ float g_asrc2[NN];                  // layer-2 logits (atomic-accumulated)
__device__ float g_adst2[NN];
__device__ int   g_count[NN];
__device__ int   g_rowptr[NN + 1];
__device__ int   g_cursor[NN];
__device__ int   g_csrsrc[ETOT];

// ---------------- CSR build ----------------
__global__ void init_count_kernel(int n) {
    int i = blockIdx.x * blockDim.x + threadIdx.x;
    if (i < n) {
        g_count[i] = 1;  // self loop
        g_asrc2[i] = 0.f;
        g_adst2[i] = 0.f;
    }
}

__global__ void count_kernel(const int* __restrict__ ei, int E, int n) {
    int i = blockIdx.x * blockDim.x + threadIdx.x;
    if (i < E) {
        int d = ei[E + i];      // dst row of edge_index
        atomicAdd(&g_count[d], 1);
    }
}

// single-block scan, 1024 threads, warp-shuffle based
__global__ void scan_kernel(int n) {
    __shared__ int warpsum[32];
    __shared__ int s_carry;
    int tid = threadIdx.x, lane = tid & 31, wid = tid >> 5;
    if (tid == 0) { s_carry = 0; g_rowptr[0] = 0; }
    __syncthreads();
    for (int base = 0; base < n; base += 1024) {
        int i = base + tid;
        int v = (i < n) ? g_count[i] : 0;
        int x = v;
        #pragma unroll
        for (int off = 1; off < 32; off <<= 1) {
            int y = __shfl_up_sync(0xffffffffu, x, off);
            if (lane >= off) x += y;
        }
        if (lane == 31) warpsum[wid] = x;
        __syncthreads();
        int woff = 0, tot = 0;
        #pragma unroll
        for (int w = 0; w < 32; w++) {
            int ws = warpsum[w];
            if (w < wid) woff += ws;
            tot += ws;
        }
        int carry = s_carry;
        int incl = carry + woff + x;
        if (i < n) {
            g_cursor[i]     = incl - v;   // exclusive
            g_rowptr[i + 1] = incl;
        }
        __syncthreads();
        if (tid == 0) s_carry = carry + tot;
        __syncthreads();
    }
}

__global__ void fill_kernel(const int* __restrict__ ei, int E, int n) {
    int i = blockIdx.x * blockDim.x + threadIdx.x;
    int tot = E + n;
    if (i >= tot) return;
    int s, d;
    if (i < E) { s = ei[i]; d = ei[E + i]; }
    else       { s = d = i - E; }
    int pos = atomicAdd(&g_cursor[d], 1);
    g_csrsrc[pos] = s;
}

// ---------------- transpose + tf32-round weights: Wt[n][k] = rna_tf32(W[k][n]) ----------------
__global__ void transpose_round_kernel(const float* __restrict__ W, float* __restrict__ Wt) {
    __shared__ float tile[32][33];
    int bx = blockIdx.x * 32, by = blockIdx.y * 32;
    int tx = threadIdx.x, ty = threadIdx.y;   // 32 x 8
    #pragma unroll
    for (int i = 0; i < 32; i += 8)
        tile[ty + i][tx] = W[(by + ty + i) * FEAT + bx + tx];
    __syncthreads();
    #pragma unroll
    for (int i = 0; i < 32; i += 8) {
        float v = tile[tx][ty + i];
        uint32_t o;
        asm("cvt.rna.tf32.f32 %0, %1;" : "=r"(o) : "f"(v));
        Wt[(bx + ty + i) * FEAT + by + tx] = __uint_as_float(o);
    }
}

// ---------------- TF32 tensor-core GEMM with fused attention-logit epilogue ----------------
#define GP 20                // smem pitch in floats (ldmatrix conflict-free)
#define STAGE_FLOATS (2 * 128 * GP)   // As + Bs per stage

__device__ __forceinline__ void ldsm_x4(uint32_t addr, uint32_t& r0, uint32_t& r1,
                                        uint32_t& r2, uint32_t& r3) {
    asm volatile("ldmatrix.sync.aligned.m8n8.x4.shared.b16 {%0,%1,%2,%3}, [%4];"
                 : "=r"(r0), "=r"(r1), "=r"(r2), "=r"(r3) : "r"(addr));
}

__device__ __forceinline__ uint32_t f2tf32(uint32_t x) {
    uint32_t o;
    asm("cvt.rna.tf32.f32 %0, %1;" : "=r"(o) : "f"(__uint_as_float(x)));
    return o;
}

__device__ __forceinline__ void mma_tf32(float* c, const uint32_t* a, const uint32_t* b) {
    asm volatile(
        "mma.sync.aligned.m16n8k8.row.col.f32.tf32.tf32.f32 "
        "{%0,%1,%2,%3}, {%4,%5,%6,%7}, {%8,%9}, {%0,%1,%2,%3};"
        : "+f"(c[0]), "+f"(c[1]), "+f"(c[2]), "+f"(c[3])
        : "r"(a[0]), "r"(a[1]), "r"(a[2]), "r"(a[3]), "r"(b[0]), "r"(b[1]));
}

__device__ __forceinline__ void cp16(uint32_t saddr, const void* gptr, uint32_t srcsize) {
    asm volatile("cp.async.ca.shared.global [%0], [%1], 16, %2;\n"
                 :: "r"(saddr), "l"(gptr), "r"(srcsize));
}

template<int HEADS>
__global__ __launch_bounds__(256) void gemm_att_kernel(
    const float* __restrict__ A, const float* __restrict__ Wt,
    float* __restrict__ C,
    const float* __restrict__ attS, const float* __restrict__ attD,
    float* __restrict__ oS, float* __restrict__ oD, int M)
{
    __shared__ float smem[2 * STAGE_FLOATS];
    const int K = 256;
    int tid = threadIdx.x;
    int lane = tid & 31;
    int warp = tid >> 5;
    int wm = warp >> 1;          // 0..3
    int wn = warp & 1;           // 0..1
    int block_row = blockIdx.x * 128;
    int block_col = blockIdx.y * 128;

    uint32_t s_base = (uint32_t)__cvta_generic_to_shared(smem);
    uint32_t sA = s_base;
    uint32_t sB = s_base + 128 * GP * 4;
    const uint32_t stage_bytes = STAGE_FLOATS * 4;

    int c0i = tid * 2, c1i = tid * 2 + 1;
    int ar0 = c0i >> 2, ac0 = (c0i & 3) * 4;
    int ar1 = c1i >> 2, ac1 = (c1i & 3) * 4;
    uint32_t dstA0 = sA + (uint32_t)(ar0 * GP + ac0) * 4;
    uint32_t dstA1 = sA + (uint32_t)(ar1 * GP + ac1) * 4;
    uint32_t dstB0 = sB + (uint32_t)(ar0 * GP + ac0) * 4;
    uint32_t dstB1 = sB + (uint32_t)(ar1 * GP + ac1) * 4;
    int grA0 = block_row + ar0, grA1 = block_row + ar1;
    uint32_t szA0 = (grA0 < M) ? 16u : 0u;
    uint32_t szA1 = (grA1 < M) ? 16u : 0u;
    if (grA0 >= M) grA0 = 0;
    if (grA1 >= M) grA1 = 0;
    const float* srcA0 = A + (size_t)grA0 * K + ac0;
    const float* srcA1 = A + (size_t)grA1 * K + ac1;
    const float* srcB0 = Wt + (size_t)(block_col + ar0) * K + ac0;
    const float* srcB1 = Wt + (size_t)(block_col + ar1) * K + ac1;

    int g = lane >> 3, r = lane & 7;
    int a_row_l = (g & 1) * 8 + r;
    int a_koff  = (g >> 1) * 4;
    uint32_t a_base[2];
    #pragma unroll
    for (int mt = 0; mt < 2; mt++)
        a_base[mt] = sA + (uint32_t)((wm * 32 + mt * 16 + a_row_l) * GP + a_koff) * 4;
    int b_row_l = (g >> 1) * 8 + r;
    int b_koff  = (g & 1) * 4;
    uint32_t b_base[4];
    #pragma unroll
    for (int np = 0; np < 4; np++)
        b_base[np] = sB + (uint32_t)((wn * 64 + np * 16 + b_row_l) * GP + b_koff) * 4;

    float acc[2][8][4];
    #pragma unroll
    for (int mt = 0; mt < 2; mt++)
        #pragma unroll
        for (int nt = 0; nt < 8; nt++)
            #pragma unroll
            for (int q = 0; q < 4; q++) acc[mt][nt][q] = 0.f;

    cp16(dstA0, srcA0, szA0);
    cp16(dstA1, srcA1, szA1);
    cp16(dstB0, srcB0, 16u);
    cp16(dstB1, srcB1, 16u);
    asm volatile("cp.async.commit_group;\n" ::);

    const int NITER = K / 16;   // 16
    for (int it = 0; it < NITER; it++) {
        int buf = it & 1;
        if (it + 1 < NITER) {
            uint32_t off = ((it + 1) & 1) * stage_bytes;
            int k0 = (it + 1) * 16;
            cp16(dstA0 + off, srcA0 + k0, szA0);
            cp16(dstA1 + off, srcA1 + k0, szA1);
            cp16(dstB0 + off, srcB0 + k0, 16u);
            cp16(dstB1 + off, srcB1 + k0, 16u);
            asm volatile("cp.async.commit_group;\n" ::);
            asm volatile("cp.async.wait_group 1;\n" ::);
        } else {
            asm volatile("cp.async.wait_group 0;\n" ::);
        }
        __syncthreads();

        uint32_t soff = buf * stage_bytes;
        #pragma unroll
        for (int ks = 0; ks < 16; ks += 8) {
            uint32_t a[2][4], b[4][4];
            #pragma unroll
            for (int mt = 0; mt < 2; mt++) {
                ldsm_x4(a_base[mt] + soff + ks * 4, a[mt][0], a[mt][1], a[mt][2], a[mt][3]);
                #pragma unroll
                for (int q = 0; q < 4; q++) a[mt][q] = f2tf32(a[mt][q]);
            }
            #pragma unroll
            for (int np = 0; np < 4; np++)
                ldsm_x4(b_base[np] + soff + ks * 4, b[np][0], b[np][1], b[np][2], b[np][3]);
            #pragma unroll
            for (int mt = 0; mt < 2; mt++)
                #pragma unroll
                for (int nt = 0; nt < 8; nt++)
                    mma_tf32(acc[mt][nt], a[mt], &b[nt >> 1][(nt & 1) * 2]);
        }
        __syncthreads();
    }

    // ---- epilogue: fp32 stores ----
    int cr = lane >> 2;
    int cc = (lane & 3) * 2;
    #pragma unroll
    for (int mt = 0; mt < 2; mt++) {
        int row0 = block_row + wm * 32 + mt * 16 + cr;
        #pragma unroll
        for (int nt = 0; nt < 8; nt++) {
            int col = block_col + wn * 64 + nt * 8 + cc;
            if (row0 < M)
                *reinterpret_cast<float2*>(C + (size_t)row0 * 256 + col) =
                    make_float2(acc[mt][nt][0], acc[mt][nt][1]);
            if (row0 + 8 < M)
                *reinterpret_cast<float2*>(C + (size_t)(row0 + 8) * 256 + col) =
                    make_float2(acc[mt][nt][2], acc[mt][nt][3]);
        }
    }

    // ---- epilogue: fused attention-logit partial dots over this warp's 64 cols ----
    float ps[2][2] = {{0.f,0.f},{0.f,0.f}};
    float pd[2][2] = {{0.f,0.f},{0.f,0.f}};
    #pragma unroll
    for (int mt = 0; mt < 2; mt++) {
        #pragma unroll
        for (int nt = 0; nt < 8; nt++) {
            int lc = nt * 8 + cc;
            int idx = (HEADS == 4) ? ((blockIdx.y * 2 + wn) * 64 + lc)
                                   : (block_col + wn * 64 + lc);
            float as0 = attS[idx], as1 = attS[idx + 1];
            float ad0 = attD[idx], ad1 = attD[idx + 1];
            ps[mt][0] += acc[mt][nt][0] * as0 + acc[mt][nt][1] * as1;
            ps[mt][1] += acc[mt][nt][2] * as0 + acc[mt][nt][3] * as1;
            pd[mt][0] += acc[mt][nt][0] * ad0 + acc[mt][nt][1] * ad1;
            pd[mt][1] += acc[mt][nt][2] * ad0 + acc[mt][nt][3] * ad1;
        }
    }
    #pragma unroll
    for (int mt = 0; mt < 2; mt++)
        #pragma unroll
        for (int hf = 0; hf < 2; hf++) {
            ps[mt][hf] += __shfl_xor_sync(0xffffffffu, ps[mt][hf], 1);
            ps[mt][hf] += __shfl_xor_sync(0xffffffffu, ps[mt][hf], 2);
            pd[mt][hf] += __shfl_xor_sync(0xffffffffu, pd[mt][hf], 1);
            pd[mt][hf] += __shfl_xor_sync(0xffffffffu, pd[mt][hf], 2);
        }
    if ((lane & 3) == 0) {
        #pragma unroll
        for (int mt = 0; mt < 2; mt++)
            #pragma unroll
            for (int hf = 0; hf < 2; hf++) {
                int node = block_row + wm * 32 + mt * 16 + cr + hf * 8;
                if (node < M) {
                    if (HEADS == 4) {
                        int head = blockIdx.y * 2 + wn;
                        oS[node * 4 + head] = ps[mt][hf];
                        oD[node * 4 + head] = pd[mt][hf];
                    } else {
                        atomicAdd(&oS[node], ps[mt][hf]);
                        atomicAdd(&oD[node], pd[mt][hf]);
                    }
                }
            }
    }
}

__device__ __forceinline__ float leaky(float x) {
    return (x > 0.f) ? x : NEG_SLOPE * x;
}

// ---------------- aggregation, layer 1 (4 heads) + bias + ELU ----------------
// batch-2 edge processing: 2 independent row gathers in flight per warp.
__global__ void agg1_kernel(const float* __restrict__ xp,
                            const float* __restrict__ bias,
                            float* __restrict__ out, int n)
{
    int node = (blockIdx.x * blockDim.x + threadIdx.x) >> 5;
    if (node >= n) return;
    int lane = threadIdx.x & 31;
    int h  = lane >> 3;         // 8 lanes per head
    int c0 = lane * 8;
    float ad = g_adst[node * NHEADS + h];
    int beg = g_rowptr[node], end = g_rowptr[node + 1];
    float m = -1e30f, s = 0.f;
    float acc[8] = {0,0,0,0,0,0,0,0};
    int p = beg;
    for (; p + 1 < end; p += 2) {
        int j0 = g_csrsrc[p];
        int j1 = g_csrsrc[p + 1];
        float e0 = leaky(g_asrc[j0 * NHEADS + h] + ad);
        float e1 = leaky(g_asrc[j1 * NHEADS + h] + ad);
        const float4* x0 = reinterpret_cast<const float4*>(xp + (size_t)j0 * FEAT + c0);
        const float4* x1 = reinterpret_cast<const float4*>(xp + (size_t)j1 * FEAT + c0);
        float4 a0 = x0[0], a1 = x0[1];
        float4 b0 = x1[0], b1 = x1[1];
        float mn = fmaxf(m, fmaxf(e0, e1));
        float corr = __expf(m - mn);
        float p0   = __expf(e0 - mn);
        float p1   = __expf(e1 - mn);
        s = s * corr + p0 + p1;
        acc[0] = acc[0] * corr + p0 * a0.x + p1 * b0.x;
        acc[1] = acc[1] * corr + p0 * a0.y + p1 * b0.y;
        acc[2] = acc[2] * corr + p0 * a0.z + p1 * b0.z;
        acc[3] = acc[3] * corr + p0 * a0.w + p1 * b0.w;
        acc[4] = acc[4] * corr + p0 * a1.x + p1 * b1.x;
        acc[5] = acc[5] * corr + p0 * a1.y + p1 * b1.y;
        acc[6] = acc[6] * corr + p0 * a1.z + p1 * b1.z;
        acc[7] = acc[7] * corr + p0 * a1.w + p1 * b1.w;
        m = mn;
    }
    if (p < end) {
        int j = g_csrsrc[p];
        float e = leaky(g_asrc[j * NHEADS + h] + ad);
        const float4* xr = reinterpret_cast<const float4*>(xp + (size_t)j * FEAT + c0);
        float4 v0 = xr[0], v1 = xr[1];
        float mn = fmaxf(m, e);
        float corr = __expf(m - mn);
        float pw   = __expf(e - mn);
        s = s * corr + pw;
        acc[0] = acc[0] * corr + pw * v0.x;
        acc[1] = acc[1] * corr + pw * v0.y;
        acc[2] = acc[2] * corr + pw * v0.z;
        acc[3] = acc[3] * corr + pw * v0.w;
        acc[4] = acc[4] * corr + pw * v1.x;
        acc[5] = acc[5] * corr + pw * v1.y;
        acc[6] = acc[6] * corr + pw * v1.z;
        acc[7] = acc[7] * corr + pw * v1.w;
    }
    float inv = 1.f / s;   // denom >= 1 (self-loop contributes >= exp(min(0,..)))
    const float4* b4 = reinterpret_cast<const float4*>(bias + c0);
    float4 bb0 = b4[0], bb1 = b4[1];
    float vb[8] = {bb0.x, bb0.y, bb0.z, bb0.w, bb1.x, bb1.y, bb1.z, bb1.w};
    float v[8];
    #pragma unroll
    for (int k = 0; k < 8; k++) {
        float t = acc[k] * inv + vb[k];
        v[k] = (t > 0.f) ? t : expm1f(t);   // ELU
    }
    float4 o0 = make_float4(v[0], v[1], v[2], v[3]);
    float4 o1 = make_float4(v[4], v[5], v[6], v[7]);
    float4* orow = reinterpret_cast<float4*>(out + (size_t)node * FEAT + c0);
    orow[0] = o0; orow[1] = o1;
}

// ---------------- aggregation, layer 2 (1 head) + bias + ELU + BN + LN ----------------
__global__ void agg2_kernel(const float* __restrict__ xp,
                            const float* __restrict__ bias,
                            const float* __restrict__ bn_gamma,
                            const float* __restrict__ bn_beta,
                            const float* __restrict__ bn_mean,
                            const float* __restrict__ bn_var,
                            const float* __restrict__ ln_gamma,
                            const float* __restrict__ ln_beta,
                            float* __restrict__ out, int n)
{
    int node = (blockIdx.x * blockDim.x + threadIdx.x) >> 5;
    if (node >= n) return;
    int lane = threadIdx.x & 31;
    int c0 = lane * 8;
    float ad = g_adst2[node];
    int beg = g_rowptr[node], end = g_rowptr[node + 1];
    float m = -1e30f, s = 0.f;
    float acc[8] = {0,0,0,0,0,0,0,0};
    int p = beg;
    for (; p + 1 < end; p += 2) {
        int j0 = g_csrsrc[p];
        int j1 = g_csrsrc[p + 1];
        float e0 = leaky(g_asrc2[j0] + ad);
        float e1 = leaky(g_asrc2[j1] + ad);
        const float4* x0 = reinterpret_cast<const float4*>(xp + (size_t)j0 * FEAT + c0);
        const float4* x1 = reinterpret_cast<const float4*>(xp + (size_t)j1 * FEAT + c0);
        float4 a0 = x0[0], a1 = x0[1];
        float4 b0 = x1[0], b1 = x1[1];
        float mn = fmaxf(m, fmaxf(e0, e1));
        float corr = __expf(m - mn);
        float p0   = __expf(e0 - mn);
        float p1   = __expf(e1 - mn);
        s = s * corr + p0 + p1;
        acc[0] = acc[0] * corr + p0 * a0.x + p1 * b0.x;
        acc[1] = acc[1] * corr + p0 * a0.y + p1 * b0.y;
        acc[2] = acc[2] * corr + p0 * a0.z + p1 * b0.z;
        acc[3] = acc[3] * corr + p0 * a0.w + p1 * b0.w;
        acc[4] = acc[4] * corr + p0 * a1.x + p1 * b1.x;
        acc[5] = acc[5] * corr + p0 * a1.y + p1 * b1.y;
        acc[6] = acc[6] * corr + p0 * a1.z + p1 * b1.z;
        acc[7] = acc[7] * corr + p0 * a1.w + p1 * b1.w;
        m = mn;
    }
    if (p < end) {
        int j = g_csrsrc[p];
        float e = leaky(g_asrc2[j] + ad);
        const float4* xr = reinterpret_cast<const float4*>(xp + (size_t)j * FEAT + c0);
        float4 v0 = xr[0], v1 = xr[1];
        float mn = fmaxf(m, e);
        float corr = __expf(m - mn);
        float pw   = __expf(e - mn);
        s = s * corr + pw;
        acc[0] = acc[0] * corr + pw * v0.x;
        acc[1] = acc[1] * corr + pw * v0.y;
        acc[2] = acc[2] * corr + pw * v0.z;
        acc[3] = acc[3] * corr + pw * v0.w;
        acc[4] = acc[4] * corr + pw * v1.x;
        acc[5] = acc[5] * corr + pw * v1.y;
        acc[6] = acc[6] * corr + pw * v1.z;
        acc[7] = acc[7] * corr + pw * v1.w;
    }
    float inv = 1.f / s;
    float v[8];
    #pragma unroll
    for (int k = 0; k < 8; k++) {
        int c = c0 + k;
        float x = acc[k] * inv + bias[c];
        x = (x > 0.f) ? x : expm1f(x);                           // ELU
        x = (x - bn_mean[c]) * rsqrtf(bn_var[c] + BN_EPS) * bn_gamma[c] + bn_beta[c];  // BN eval
        v[k] = x;
    }
    // LayerNorm over 256 channels (warp = row, 8 ch/lane)
    float lsum = 0.f;
    #pragma unroll
    for (int k = 0; k < 8; k++) lsum += v[k];
    #pragma unroll
    for (int off = 16; off; off >>= 1) lsum += __shfl_xor_sync(0xffffffffu, lsum, off);
    float mu = lsum * (1.f / 256.f);
    float lvar = 0.f;
    #pragma unroll
    for (int k = 0; k < 8; k++) { float d = v[k] - mu; lvar += d * d; }
    #pragma unroll
    for (int off = 16; off; off >>= 1) lvar += __shfl_xor_sync(0xffffffffu, lvar, off);
    float r = rsqrtf(lvar * (1.f / 256.f) + LN_EPS);
    float w[8];
    #pragma unroll
    for (int k = 0; k < 8; k++) {
        int c = c0 + k;
        w[k] = (v[k] - mu) * r * ln_gamma[c] + ln_beta[c];
    }
    float4 o0 = make_float4(w[0], w[1], w[2], w[3]);
    float4 o1 = make_float4(w[4], w[5], w[6], w[7]);
    float4* orow = reinterpret_cast<float4*>(out + (size_t)node * FEAT + c0);
    orow[0] = o0; orow[1] = o1;
}

// ---------------- launch ----------------
extern "C" void kernel_launch(void* const* d_in, const int* in_sizes, int n_in,
                              void* d_out, int out_size)
{
    const float* x        = (const float*)d_in[0];
    const int*   ei       = (const int*)  d_in[1];
    const float* W1       = (const float*)d_in[2];
    const float* att_src1 = (const float*)d_in[3];
    const float* att_dst1 = (const float*)d_in[4];
    const float* bias1    = (const float*)d_in[5];
    const float* W2       = (const float*)d_in[6];
    const float* att_src2 = (const float*)d_in[7];
    const float* att_dst2 = (const float*)d_in[8];
    const float* bias2    = (const float*)d_in[9];
    const float* bn_gamma = (const float*)d_in[10];
    const float* bn_beta  = (const float*)d_in[11];
    const float* bn_mean  = (const float*)d_in[12];
    const float* bn_var   = (const float*)d_in[13];
    const float* ln_gamma = (const float*)d_in[14];
    const float* ln_beta  = (const float*)d_in[15];
    float* out = (float*)d_out;

    int n = in_sizes[0] / FEAT;      // 50000
    int E = in_sizes[1] / 2;         // 800000
    if (n > NN) n = NN;
    if (E > EMAX) E = EMAX;

    float *xp, *h1, *wt1, *wt2, *asrc, *adst, *asrc2, *adst2;
    cudaGetSymbolAddress((void**)&xp,    g_xp);
    cudaGetSymbolAddress((void**)&h1,    g_h1);
    cudaGetSymbolAddress((void**)&wt1,   g_wt1);
    cudaGetSymbolAddress((void**)&wt2,   g_wt2);
    cudaGetSymbolAddress((void**)&asrc,  g_asrc);
    cudaGetSymbolAddress((void**)&adst,  g_adst);
    cudaGetSymbolAddress((void**)&asrc2, g_asrc2);
    cudaGetSymbolAddress((void**)&adst2, g_adst2);

    // lazy side-stream / event creation (first call is outside graph capture)
    static cudaStream_t s_side = nullptr;
    static cudaEvent_t  s_evF  = nullptr, s_evJ = nullptr;
    if (s_side == nullptr) {
        cudaStreamCreateWithFlags(&s_side, cudaStreamNonBlocking);
        cudaEventCreateWithFlags(&s_evF, cudaEventDisableTiming);
        cudaEventCreateWithFlags(&s_evJ, cudaEventDisableTiming);
    }

    // --- fork: CSR build on side stream, GEMM path on main stream ---
    cudaEventRecord(s_evF, 0);
    cudaStreamWaitEvent(s_side, s_evF, 0);
    init_count_kernel<<<(n + 255) / 256, 256, 0, s_side>>>(n);
    count_kernel<<<(E + 255) / 256, 256, 0, s_side>>>(ei, E, n);
    scan_kernel<<<1, 1024, 0, s_side>>>(n);
    fill_kernel<<<(E + n + 255) / 256, 256, 0, s_side>>>(ei, E, n);
    cudaEventRecord(s_evJ, s_side);

    // --- main stream: weight prep + layer-1 GEMM (att logits fused) ---
    dim3 tgrid(FEAT / 32, FEAT / 32), tblk(32, 8);
    transpose_round_kernel<<<tgrid, tblk>>>(W1, wt1);
    transpose_round_kernel<<<tgrid, tblk>>>(W2, wt2);

    dim3 ggrid((n + 127) / 128, FEAT / 128);
    gemm_att_kernel<4><<<ggrid, 256>>>(x, wt1, xp,
                                       att_src1, att_dst1, asrc, adst, n);

    // --- join: CSR ready ---
    cudaStreamWaitEvent(0, s_evJ, 0);

    agg1_kernel<<<(n * 32 + 255) / 256, 256>>>(xp, bias1, h1, n);

    // --- layer 2 ---
    gemm_att_kernel<1><<<ggrid, 256>>>(h1, wt2, xp,
                                       att_src2, att_dst2, asrc2, adst2, n);
    agg2_kernel<<<(n * 32 + 255) / 256, 256>>>(xp, bias2, bn_gamma, bn_beta, bn_mean,
                                               bn_var, ln_gamma, ln_beta, out, n);
    (void)n_in; (void)out_size;
}

// round 7
// speedup vs baseline: 2.2101x; 1.2031x over previous
#include <cuda_runtime.h>
#include <cuda_fp16.h>
#include <math.h>
#include <stdint.h>

// ---------------- problem constants ----------------
#define NN      50000      // nodes
#define EMAX    800000     // edges (before self loops)
#define ETOT    (EMAX + NN)
#define FEAT    256        // NFEAT = NHEADS*NHID = NOUT = 256
#define NHEADS  4
#define NHID    64
#define NEG_SLOPE 0.2f
#define BN_EPS  1e-5f
#define LN_EPS  1e-5f

// ---------------- scratch (device globals; no runtime alloc) ----------------
__device__ __half g_xph[NN * FEAT];            // xp of current layer (fp16, reused both layers)
__device__ float g_h1[NN * FEAT];              // layer-1 output (ELU'd, fp32)
__device__ float g_wt1[FEAT * FEAT];           // W1^T, tf32-rounded, [n][k]
__device__ float g_wt2[FEAT * FEAT];           // W2^T, tf32-rounded, [n][k]
__device__ float g_asrc[NN * NHEADS];          // layer-1 logits (per head)
__device__ float g_adst[NN * NHEADS];
__device__ float g_asrc2[NN];                  // layer-2 logits (atomic-accumulated)
__device__ float g_adst2[NN];
__device__ int   g_count[NN];
__device__ int   g_rowptr[NN + 1];
__device__ int   g_cursor[NN];
__device__ int   g_csrsrc[ETOT];

// ---------------- CSR build ----------------
__global__ void init_count_kernel(int n) {
    int i = blockIdx.x * blockDim.x + threadIdx.x;
    if (i < n) {
        g_count[i] = 1;  // self loop
        g_asrc2[i] = 0.f;
        g_adst2[i] = 0.f;
    }
}

__global__ void count_kernel(const int* __restrict__ ei, int E, int n) {
    int i = blockIdx.x * blockDim.x + threadIdx.x;
    if (i < E) {
        int d = ei[E + i];      // dst row of edge_index
        atomicAdd(&g_count[d], 1);
    }
}

// single-block scan, 1024 threads, 4 elements/thread, warp-shuffle based
__global__ void scan_kernel(int n) {
    __shared__ int warpsum[32];
    __shared__ int s_carry;
    int tid = threadIdx.x, lane = tid & 31, wid = tid >> 5;
    if (tid == 0) { s_carry = 0; g_rowptr[0] = 0; }
    __syncthreads();
    for (int base = 0; base < n; base += 4096) {
        int i = base + tid * 4;
        int v0 = 0, v1 = 0, v2 = 0, v3 = 0;
        if (i + 3 < n) {
            int4 q = *reinterpret_cast<const int4*>(&g_count[i]);
            v0 = q.x; v1 = q.y; v2 = q.z; v3 = q.w;
        } else {
            if (i     < n) v0 = g_count[i];
            if (i + 1 < n) v1 = g_count[i + 1];
            if (i + 2 < n) v2 = g_count[i + 2];
        }
        int t = v0 + v1 + v2 + v3;
        int x = t;
        #pragma unroll
        for (int off = 1; off < 32; off <<= 1) {
            int y = __shfl_up_sync(0xffffffffu, x, off);
            if (lane >= off) x += y;
        }
        if (lane == 31) warpsum[wid] = x;
        __syncthreads();
        int woff = 0, tot = 0;
        #pragma unroll
        for (int w = 0; w < 32; w++) {
            int ws = warpsum[w];
            if (w < wid) woff += ws;
            tot += ws;
        }
        int carry = s_carry;
        int excl = carry + woff + x - t;   // exclusive prefix at element i
        int e1 = excl + v0, e2 = e1 + v1, e3 = e2 + v2;
        if (i     < n) { g_cursor[i]     = excl; g_rowptr[i + 1] = e1; }
        if (i + 1 < n) { g_cursor[i + 1] = e1;   g_rowptr[i + 2] = e2; }
        if (i + 2 < n) { g_cursor[i + 2] = e2;   g_rowptr[i + 3] = e3; }
        if (i + 3 < n) { g_cursor[i + 3] = e3;   g_rowptr[i + 4] = e3 + v3; }
        __syncthreads();
        if (tid == 0) s_carry = carry + tot;
        __syncthreads();
    }
}

__global__ void fill_kernel(const int* __restrict__ ei, int E, int n) {
    int i = blockIdx.x * blockDim.x + threadIdx.x;
    int tot = E + n;
    if (i >= tot) return;
    int s, d;
    if (i < E) { s = ei[i]; d = ei[E + i]; }
    else       { s = d = i - E; }
    int pos = atomicAdd(&g_cursor[d], 1);
    g_csrsrc[pos] = s;
}

// ---------------- transpose + tf32-round weights: Wt[n][k] = rna_tf32(W[k][n]) ----------------
__global__ void transpose_round_kernel(const float* __restrict__ W, float* __restrict__ Wt) {
    __shared__ float tile[32][33];
    int bx = blockIdx.x * 32, by = blockIdx.y * 32;
    int tx = threadIdx.x, ty = threadIdx.y;   // 32 x 8
    #pragma unroll
    for (int i = 0; i < 32; i += 8)
        tile[ty + i][tx] = W[(by + ty + i) * FEAT + bx + tx];
    __syncthreads();
    #pragma unroll
    for (int i = 0; i < 32; i += 8) {
        float v = tile[tx][ty + i];
        uint32_t o;
        asm("cvt.rna.tf32.f32 %0, %1;" : "=r"(o) : "f"(v));
        Wt[(bx + ty + i) * FEAT + by + tx] = __uint_as_float(o);
    }
}

// ---------------- TF32 tensor-core GEMM, fp16 output, fused attention-logit epilogue ----------------
#define GP 20                // smem pitch in floats (ldmatrix conflict-free)
#define STAGE_FLOATS (2 * 128 * GP)   // As + Bs per stage

__device__ __forceinline__ void ldsm_x4(uint32_t addr, uint32_t& r0, uint32_t& r1,
                                        uint32_t& r2, uint32_t& r3) {
    asm volatile("ldmatrix.sync.aligned.m8n8.x4.shared.b16 {%0,%1,%2,%3}, [%4];"
                 : "=r"(r0), "=r"(r1), "=r"(r2), "=r"(r3) : "r"(addr));
}

__device__ __forceinline__ uint32_t f2tf32(uint32_t x) {
    uint32_t o;
    asm("cvt.rna.tf32.f32 %0, %1;" : "=r"(o) : "f"(__uint_as_float(x)));
    return o;
}

__device__ __forceinline__ void mma_tf32(float* c, const uint32_t* a, const uint32_t* b) {
    asm volatile(
        "mma.sync.aligned.m16n8k8.row.col.f32.tf32.tf32.f32 "
        "{%0,%1,%2,%3}, {%4,%5,%6,%7}, {%8,%9}, {%0,%1,%2,%3};"
        : "+f"(c[0]), "+f"(c[1]), "+f"(c[2]), "+f"(c[3])
        : "r"(a[0]), "r"(a[1]), "r"(a[2]), "r"(a[3]), "r"(b[0]), "r"(b[1]));
}

__device__ __forceinline__ void cp16(uint32_t saddr, const void* gptr, uint32_t srcsize) {
    asm volatile("cp.async.ca.shared.global [%0], [%1], 16, %2;\n"
                 :: "r"(saddr), "l"(gptr), "r"(srcsize));
}

template<int HEADS>
__global__ __launch_bounds__(256) void gemm_att_kernel(
    const float* __restrict__ A, const float* __restrict__ Wt,
    __half* __restrict__ Ch,
    const float* __restrict__ attS, const float* __restrict__ attD,
    float* __restrict__ oS, float* __restrict__ oD, int M)
{
    __shared__ float smem[2 * STAGE_FLOATS];
    const int K = 256;
    int tid = threadIdx.x;
    int lane = tid & 31;
    int warp = tid >> 5;
    int wm = warp >> 1;          // 0..3
    int wn = warp & 1;           // 0..1
    int block_row = blockIdx.x * 128;
    int block_col = blockIdx.y * 128;

    uint32_t s_base = (uint32_t)__cvta_generic_to_shared(smem);
    uint32_t sA = s_base;
    uint32_t sB = s_base + 128 * GP * 4;
    const uint32_t stage_bytes = STAGE_FLOATS * 4;

    int c0i = tid * 2, c1i = tid * 2 + 1;
    int ar0 = c0i >> 2, ac0 = (c0i & 3) * 4;
    int ar1 = c1i >> 2, ac1 = (c1i & 3) * 4;
    uint32_t dstA0 = sA + (uint32_t)(ar0 * GP + ac0) * 4;
    uint32_t dstA1 = sA + (uint32_t)(ar1 * GP + ac1) * 4;
    uint32_t dstB0 = sB + (uint32_t)(ar0 * GP + ac0) * 4;
    uint32_t dstB1 = sB + (uint32_t)(ar1 * GP + ac1) * 4;
    int grA0 = block_row + ar0, grA1 = block_row + ar1;
    uint32_t szA0 = (grA0 < M) ? 16u : 0u;
    uint32_t szA1 = (grA1 < M) ? 16u : 0u;
    if (grA0 >= M) grA0 = 0;
    if (grA1 >= M) grA1 = 0;
    const float* srcA0 = A + (size_t)grA0 * K + ac0;
    const float* srcA1 = A + (size_t)grA1 * K + ac1;
    const float* srcB0 = Wt + (size_t)(block_col + ar0) * K + ac0;
    const float* srcB1 = Wt + (size_t)(block_col + ar1) * K + ac1;

    int g = lane >> 3, r = lane & 7;
    int a_row_l = (g & 1) * 8 + r;
    int a_koff  = (g >> 1) * 4;
    uint32_t a_base[2];
    #pragma unroll
    for (int mt = 0; mt < 2; mt++)
        a_base[mt] = sA + (uint32_t)((wm * 32 + mt * 16 + a_row_l) * GP + a_koff) * 4;
    int b_row_l = (g >> 1) * 8 + r;
    int b_koff  = (g & 1) * 4;
    uint32_t b_base[4];
    #pragma unroll
    for (int np = 0; np < 4; np++)
        b_base[np] = sB + (uint32_t)((wn * 64 + np * 16 + b_row_l) * GP + b_koff) * 4;

    float acc[2][8][4];
    #pragma unroll
    for (int mt = 0; mt < 2; mt++)
        #pragma unroll
        for (int nt = 0; nt < 8; nt++)
            #pragma unroll
            for (int q = 0; q < 4; q++) acc[mt][nt][q] = 0.f;

    cp16(dstA0, srcA0, szA0);
    cp16(dstA1, srcA1, szA1);
    cp16(dstB0, srcB0, 16u);
    cp16(dstB1, srcB1, 16u);
    asm volatile("cp.async.commit_group;\n" ::);

    const int NITER = K / 16;   // 16
    for (int it = 0; it < NITER; it++) {
        int buf = it & 1;
        if (it + 1 < NITER) {
            uint32_t off = ((it + 1) & 1) * stage_bytes;
            int k0 = (it + 1) * 16;
            cp16(dstA0 + off, srcA0 + k0, szA0);
            cp16(dstA1 + off, srcA1 + k0, szA1);
            cp16(dstB0 + off, srcB0 + k0, 16u);
            cp16(dstB1 + off, srcB1 + k0, 16u);
            asm volatile("cp.async.commit_group;\n" ::);
            asm volatile("cp.async.wait_group 1;\n" ::);
        } else {
            asm volatile("cp.async.wait_group 0;\n" ::);
        }
        __syncthreads();

        uint32_t soff = buf * stage_bytes;
        #pragma unroll
        for (int ks = 0; ks < 16; ks += 8) {
            uint32_t a[2][4], b[4][4];
            #pragma unroll
            for (int mt = 0; mt < 2; mt++) {
                ldsm_x4(a_base[mt] + soff + ks * 4, a[mt][0], a[mt][1], a[mt][2], a[mt][3]);
                #pragma unroll
                for (int q = 0; q < 4; q++) a[mt][q] = f2tf32(a[mt][q]);
            }
            #pragma unroll
            for (int np = 0; np < 4; np++)
                ldsm_x4(b_base[np] + soff + ks * 4, b[np][0], b[np][1], b[np][2], b[np][3]);
            #pragma unroll
            for (int mt = 0; mt < 2; mt++)
                #pragma unroll
                for (int nt = 0; nt < 8; nt++)
                    mma_tf32(acc[mt][nt], a[mt], &b[nt >> 1][(nt & 1) * 2]);
        }
        __syncthreads();
    }

    // ---- epilogue: fp16 stores ----
    int cr = lane >> 2;
    int cc = (lane & 3) * 2;
    #pragma unroll
    for (int mt = 0; mt < 2; mt++) {
        int row0 = block_row + wm * 32 + mt * 16 + cr;
        #pragma unroll
        for (int nt = 0; nt < 8; nt++) {
            int col = block_col + wn * 64 + nt * 8 + cc;
            if (row0 < M)
                *reinterpret_cast<__half2*>(Ch + (size_t)row0 * 256 + col) =
                    __float22half2_rn(make_float2(acc[mt][nt][0], acc[mt][nt][1]));
            if (row0 + 8 < M)
                *reinterpret_cast<__half2*>(Ch + (size_t)(row0 + 8) * 256 + col) =
                    __float22half2_rn(make_float2(acc[mt][nt][2], acc[mt][nt][3]));
        }
    }

    // ---- epilogue: fused attention-logit partial dots over this warp's 64 cols ----
    float ps[2][2] = {{0.f,0.f},{0.f,0.f}};
    float pd[2][2] = {{0.f,0.f},{0.f,0.f}};
    #pragma unroll
    for (int mt = 0; mt < 2; mt++) {
        #pragma unroll
        for (int nt = 0; nt < 8; nt++) {
            int lc = nt * 8 + cc;
            int idx = (HEADS == 4) ? ((blockIdx.y * 2 + wn) * 64 + lc)
                                   : (block_col + wn * 64 + lc);
            float as0 = attS[idx], as1 = attS[idx + 1];
            float ad0 = attD[idx], ad1 = attD[idx + 1];
            ps[mt][0] += acc[mt][nt][0] * as0 + acc[mt][nt][1] * as1;
            ps[mt][1] += acc[mt][nt][2] * as0 + acc[mt][nt][3] * as1;
            pd[mt][0] += acc[mt][nt][0] * ad0 + acc[mt][nt][1] * ad1;
            pd[mt][1] += acc[mt][nt][2] * ad0 + acc[mt][nt][3] * ad1;
        }
    }
    #pragma unroll
    for (int mt = 0; mt < 2; mt++)
        #pragma unroll
        for (int hf = 0; hf < 2; hf++) {
            ps[mt][hf] += __shfl_xor_sync(0xffffffffu, ps[mt][hf], 1);
            ps[mt][hf] += __shfl_xor_sync(0xffffffffu, ps[mt][hf], 2);
            pd[mt][hf] += __shfl_xor_sync(0xffffffffu, pd[mt][hf], 1);
            pd[mt][hf] += __shfl_xor_sync(0xffffffffu, pd[mt][hf], 2);
        }
    if ((lane & 3) == 0) {
        #pragma unroll
        for (int mt = 0; mt < 2; mt++)
            #pragma unroll
            for (int hf = 0; hf < 2; hf++) {
                int node = block_row + wm * 32 + mt * 16 + cr + hf * 8;
                if (node < M) {
                    if (HEADS == 4) {
                        int head = blockIdx.y * 2 + wn;
                        oS[node * 4 + head] = ps[mt][hf];
                        oD[node * 4 + head] = pd[mt][hf];
                    } else {
                        atomicAdd(&oS[node], ps[mt][hf]);
                        atomicAdd(&oD[node], pd[mt][hf]);
                    }
                }
            }
    }
}

__device__ __forceinline__ float leaky(float x) {
    return (x > 0.f) ? x : NEG_SLOPE * x;
}

__device__ __forceinline__ void unpack8h(uint4 u, float* f) {
    float2 a = __half22float2(*reinterpret_cast<__half2*>(&u.x));
    float2 b = __half22float2(*reinterpret_cast<__half2*>(&u.y));
    float2 c = __half22float2(*reinterpret_cast<__half2*>(&u.z));
    float2 d = __half22float2(*reinterpret_cast<__half2*>(&u.w));
    f[0] = a.x; f[1] = a.y; f[2] = b.x; f[3] = b.y;
    f[4] = c.x; f[5] = c.y; f[6] = d.x; f[7] = d.y;
}

// ---------------- aggregation, layer 1 (4 heads, fp16 gather) + bias + ELU ----------------
__global__ void agg1_kernel(const __half* __restrict__ xph,
                            const float* __restrict__ bias,
                            float* __restrict__ out, int n)
{
    int node = (blockIdx.x * blockDim.x + threadIdx.x) >> 5;
    if (node >= n) return;
    int lane = threadIdx.x & 31;
    int h  = lane >> 3;         // 8 lanes per head
    int c0 = lane * 8;
    float ad = g_adst[node * NHEADS + h];
    int beg = g_rowptr[node], end = g_rowptr[node + 1];
    float m = -1e30f, s = 0.f;
    float acc[8] = {0,0,0,0,0,0,0,0};
    int p = beg;
    for (; p + 1 < end; p += 2) {
        int j0 = g_csrsrc[p];
        int j1 = g_csrsrc[p + 1];
        float e0 = leaky(g_asrc[j0 * NHEADS + h] + ad);
        float e1 = leaky(g_asrc[j1 * NHEADS + h] + ad);
        uint4 u0 = *reinterpret_cast<const uint4*>(xph + (size_t)j0 * FEAT + c0);
        uint4 u1 = *reinterpret_cast<const uint4*>(xph + (size_t)j1 * FEAT + c0);
        float fa[8], fb[8];
        unpack8h(u0, fa);
        unpack8h(u1, fb);
        float mn = fmaxf(m, fmaxf(e0, e1));
        float corr = __expf(m - mn);
        float p0   = __expf(e0 - mn);
        float p1   = __expf(e1 - mn);
        s = s * corr + p0 + p1;
        #pragma unroll
        for (int k = 0; k < 8; k++)
            acc[k] = acc[k] * corr + p0 * fa[k] + p1 * fb[k];
        m = mn;
    }
    if (p < end) {
        int j = g_csrsrc[p];
        float e = leaky(g_asrc[j * NHEADS + h] + ad);
        uint4 u = *reinterpret_cast<const uint4*>(xph + (size_t)j * FEAT + c0);
        float fa[8];
        unpack8h(u, fa);
        float mn = fmaxf(m, e);
        float corr = __expf(m - mn);
        float pw   = __expf(e - mn);
        s = s * corr + pw;
        #pragma unroll
        for (int k = 0; k < 8; k++)
            acc[k] = acc[k] * corr + pw * fa[k];
    }
    float inv = 1.f / s;
    const float4* b4 = reinterpret_cast<const float4*>(bias + c0);
    float4 bb0 = b4[0], bb1 = b4[1];
    float vb[8] = {bb0.x, bb0.y, bb0.z, bb0.w, bb1.x, bb1.y, bb1.z, bb1.w};
    float v[8];
    #pragma unroll
    for (int k = 0; k < 8; k++) {
        float t = acc[k] * inv + vb[k];
        v[k] = (t > 0.f) ? t : expm1f(t);   // ELU
    }
    float4 o0 = make_float4(v[0], v[1], v[2], v[3]);
    float4 o1 = make_float4(v[4], v[5], v[6], v[7]);
    float4* orow = reinterpret_cast<float4*>(out + (size_t)node * FEAT + c0);
    orow[0] = o0; orow[1] = o1;
}

// ---------------- aggregation, layer 2 (1 head, fp16 gather) + bias + ELU + BN + LN ----------------
__global__ void agg2_kernel(const __half* __restrict__ xph,
                            const float* __restrict__ bias,
                            const float* __restrict__ bn_gamma,
                            const float* __restrict__ bn_beta,
                            const float* __restrict__ bn_mean,
                            const float* __restrict__ bn_var,
                            const float* __restrict__ ln_gamma,
                            const float* __restrict__ ln_beta,
                            float* __restrict__ out, int n)
{
    int node = (blockIdx.x * blockDim.x + threadIdx.x) >> 5;
    if (node >= n) return;
    int lane = threadIdx.x & 31;
    int c0 = lane * 8;
    float ad = g_adst2[node];
    int beg = g_rowptr[node], end = g_rowptr[node + 1];
    float m = -1e30f, s = 0.f;
    float acc[8] = {0,0,0,0,0,0,0,0};
    int p = beg;
    for (; p + 1 < end; p += 2) {
        int j0 = g_csrsrc[p];
        int j1 = g_csrsrc[p + 1];
        float e0 = leaky(g_asrc2[j0] + ad);
        float e1 = leaky(g_asrc2[j1] + ad);
        uint4 u0 = *reinterpret_cast<const uint4*>(xph + (size_t)j0 * FEAT + c0);
        uint4 u1 = *reinterpret_cast<const uint4*>(xph + (size_t)j1 * FEAT + c0);
        float fa[8], fb[8];
        unpack8h(u0, fa);
        unpack8h(u1, fb);
        float mn = fmaxf(m, fmaxf(e0, e1));
        float corr = __expf(m - mn);
        float p0   = __expf(e0 - mn);
        float p1   = __expf(e1 - mn);
        s = s * corr + p0 + p1;
        #pragma unroll
        for (int k = 0; k < 8; k++)
            acc[k] = acc[k] * corr + p0 * fa[k] + p1 * fb[k];
        m = mn;
    }
    if (p < end) {
        int j = g_csrsrc[p];
        float e = leaky(g_asrc2[j] + ad);
        uint4 u = *reinterpret_cast<const uint4*>(xph + (size_t)j * FEAT + c0);
        float fa[8];
        unpack8h(u, fa);
        float mn = fmaxf(m, e);
        float corr = __expf(m - mn);
        float pw   = __expf(e - mn);
        s = s * corr + pw;
        #pragma unroll
        for (int k = 0; k < 8; k++)
            acc[k] = acc[k] * corr + pw * fa[k];
    }
    float inv = 1.f / s;
    float v[8];
    #pragma unroll
    for (int k = 0; k < 8; k++) {
        int c = c0 + k;
        float x = acc[k] * inv + bias[c];
        x = (x > 0.f) ? x : expm1f(x);                           // ELU
        x = (x - bn_mean[c]) * rsqrtf(bn_var[c] + BN_EPS) * bn_gamma[c] + bn_beta[c];  // BN eval
        v[k] = x;
    }
    // LayerNorm over 256 channels (warp = row, 8 ch/lane)
    float lsum = 0.f;
    #pragma unroll
    for (int k = 0; k < 8; k++) lsum += v[k];
    #pragma unroll
    for (int off = 16; off; off >>= 1) lsum += __shfl_xor_sync(0xffffffffu, lsum, off);
    float mu = lsum * (1.f / 256.f);
    float lvar = 0.f;
    #pragma unroll
    for (int k = 0; k < 8; k++) { float d = v[k] - mu; lvar += d * d; }
    #pragma unroll
    for (int off = 16; off; off >>= 1) lvar += __shfl_xor_sync(0xffffffffu, lvar, off);
    float r = rsqrtf(lvar * (1.f / 256.f) + LN_EPS);
    float w[8];
    #pragma unroll
    for (int k = 0; k < 8; k++) {
        int c = c0 + k;
        w[k] = (v[k] - mu) * r * ln_gamma[c] + ln_beta[c];
    }
    float4 o0 = make_float4(w[0], w[1], w[2], w[3]);
    float4 o1 = make_float4(w[4], w[5], w[6], w[7]);
    float4* orow = reinterpret_cast<float4*>(out + (size_t)node * FEAT + c0);
    orow[0] = o0; orow[1] = o1;
}

// ---------------- launch ----------------
extern "C" void kernel_launch(void* const* d_in, const int* in_sizes, int n_in,
                              void* d_out, int out_size)
{
    const float* x        = (const float*)d_in[0];
    const int*   ei       = (const int*)  d_in[1];
    const float* W1       = (const float*)d_in[2];
    const float* att_src1 = (const float*)d_in[3];
    const float* att_dst1 = (const float*)d_in[4];
    const float* bias1    = (const float*)d_in[5];
    const float* W2       = (const float*)d_in[6];
    const float* att_src2 = (const float*)d_in[7];
    const float* att_dst2 = (const float*)d_in[8];
    const float* bias2    = (const float*)d_in[9];
    const float* bn_gamma = (const float*)d_in[10];
    const float* bn_beta  = (const float*)d_in[11];
    const float* bn_mean  = (const float*)d_in[12];
    const float* bn_var   = (const float*)d_in[13];
    const float* ln_gamma = (const float*)d_in[14];
    const float* ln_beta  = (const float*)d_in[15];
    float* out = (float*)d_out;

    int n = in_sizes[0] / FEAT;      // 50000
    int E = in_sizes[1] / 2;         // 800000
    if (n > NN) n = NN;
    if (E > EMAX) E = EMAX;

    float *h1, *wt1, *wt2, *asrc, *adst, *asrc2, *adst2;
    __half* xph;
    cudaGetSymbolAddress((void**)&xph,   g_xph);
    cudaGetSymbolAddress((void**)&h1,    g_h1);
    cudaGetSymbolAddress((void**)&wt1,   g_wt1);
    cudaGetSymbolAddress((void**)&wt2,   g_wt2);
    cudaGetSymbolAddress((void**)&asrc,  g_asrc);
    cudaGetSymbolAddress((void**)&adst,  g_adst);
    cudaGetSymbolAddress((void**)&asrc2, g_asrc2);
    cudaGetSymbolAddress((void**)&adst2, g_adst2);

    // lazy side-stream / event creation (first call is outside graph capture)
    static cudaStream_t s_side = nullptr;
    static cudaEvent_t  s_evF  = nullptr, s_evJ = nullptr;
    if (s_side == nullptr) {
        cudaStreamCreateWithFlags(&s_side, cudaStreamNonBlocking);
        cudaEventCreateWithFlags(&s_evF, cudaEventDisableTiming);
        cudaEventCreateWithFlags(&s_evJ, cudaEventDisableTiming);
    }

    // --- fork: CSR build on side stream, GEMM path on main stream ---
    cudaEventRecord(s_evF, 0);
    cudaStreamWaitEvent(s_side, s_evF, 0);
    init_count_kernel<<<(n + 255) / 256, 256, 0, s_side>>>(n);
    count_kernel<<<(E + 255) / 256, 256, 0, s_side>>>(ei, E, n);
    scan_kernel<<<1, 1024, 0, s_side>>>(n);
    fill_kernel<<<(E + n + 255) / 256, 256, 0, s_side>>>(ei, E, n);
    cudaEventRecord(s_evJ, s_side);

    // --- main stream: weight prep + layer-1 GEMM (att logits fused) ---
    dim3 tgrid(FEAT / 32, FEAT / 32), tblk(32, 8);
    transpose_round_kernel<<<tgrid, tblk>>>(W1, wt1);
    transpose_round_kernel<<<tgrid, tblk>>>(W2, wt2);

    dim3 ggrid((n + 127) / 128, FEAT / 128);
    gemm_att_kernel<4><<<ggrid, 256>>>(x, wt1, xph,
                                       att_src1, att_dst1, asrc, adst, n);

    // --- join: CSR ready ---
    cudaStreamWaitEvent(0, s_evJ, 0);

    agg1_kernel<<<(n * 32 + 255) / 256, 256>>>(xph, bias1, h1, n);

    // --- layer 2 ---
    gemm_att_kernel<1><<<ggrid, 256>>>(h1, wt2, xph,
                                       att_src2, att_dst2, asrc2, adst2, n);
    agg2_kernel<<<(n * 32 + 255) / 256, 256>>>(xph, bias2, bn_gamma, bn_beta, bn_mean,
                                               bn_var, ln_gamma, ln_beta, out, n);
    (void)n_in; (void)out_size;
}

// round 8
// speedup vs baseline: 2.2372x; 1.0123x over previous
#include <cuda_runtime.h>
#include <cuda_fp16.h>
#include <math.h>
#include <stdint.h>

// ---------------- problem constants ----------------
#define NN      50000      // nodes
#define EMAX    800000     // edges (before self loops)
#define ETOT    (EMAX + NN)
#define FEAT    256        // NFEAT = NHEADS*NHID = NOUT = 256
#define NHEADS  4
#define NHID    64
#define NEG_SLOPE 0.2f
#define BN_EPS  1e-5f
#define LN_EPS  1e-5f

// ---------------- scratch (device globals; no runtime alloc) ----------------
__device__ __half g_xph[NN * FEAT];            // xp of current layer (fp16, reused both layers)
__device__ float g_h1[NN * FEAT];              // layer-1 output (ELU'd, fp32)
__device__ float g_wt1[FEAT * FEAT];           // W1^T, tf32-rounded, [n][k]
__device__ float g_wt2[FEAT * FEAT];           // W2^T, tf32-rounded, [n][k]
__device__ float g_asrc[NN * NHEADS];          // layer-1 logits (per head)
__device__ float g_adst[NN * NHEADS];
__device__ float g_asrc2[NN];                  // layer-2 logits (atomic-accumulated)
__device__ float g_adst2[NN];
__device__ int   g_count[NN];                  // zero at rest (restored by fill_kernel)
__device__ int   g_rowptr[NN + 1];
__device__ int   g_cursor[NN];
__device__ int   g_csrsrc[ETOT];

// ---------------- CSR build (no init kernel: count starts zero, fill re-zeros) ----------------
__global__ void count_kernel(const int* __restrict__ ei, int E, int n) {
    int i = blockIdx.x * blockDim.x + threadIdx.x;
    if (i < E) {
        int d = ei[E + i];      // dst row of edge_index
        atomicAdd(&g_count[d], 1);
    }
}

// single-block scan, 1024 threads, 4 elements/thread; adds +1 per node (self loop)
__global__ void scan_kernel(int n) {
    __shared__ int warpsum[32];
    __shared__ int s_carry;
    int tid = threadIdx.x, lane = tid & 31, wid = tid >> 5;
    if (tid == 0) { s_carry = 0; g_rowptr[0] = 0; }
    __syncthreads();
    for (int base = 0; base < n; base += 4096) {
        int i = base + tid * 4;
        int v0 = 0, v1 = 0, v2 = 0, v3 = 0;
        if (i + 3 < n) {
            int4 q = *reinterpret_cast<const int4*>(&g_count[i]);
            v0 = q.x + 1; v1 = q.y + 1; v2 = q.z + 1; v3 = q.w + 1;  // +1 self loop
        } else {
            if (i     < n) v0 = g_count[i]     + 1;
            if (i + 1 < n) v1 = g_count[i + 1] + 1;
            if (i + 2 < n) v2 = g_count[i + 2] + 1;
        }
        int t = v0 + v1 + v2 + v3;
        int x = t;
        #pragma unroll
        for (int off = 1; off < 32; off <<= 1) {
            int y = __shfl_up_sync(0xffffffffu, x, off);
            if (lane >= off) x += y;
        }
        if (lane == 31) warpsum[wid] = x;
        __syncthreads();
        int woff = 0, tot = 0;
        #pragma unroll
        for (int w = 0; w < 32; w++) {
            int ws = warpsum[w];
            if (w < wid) woff += ws;
            tot += ws;
        }
        int carry = s_carry;
        int excl = carry + woff + x - t;   // exclusive prefix at element i
        int e1 = excl + v0, e2 = e1 + v1, e3 = e2 + v2;
        if (i     < n) { g_cursor[i]     = excl; g_rowptr[i + 1] = e1; }
        if (i + 1 < n) { g_cursor[i + 1] = e1;   g_rowptr[i + 2] = e2; }
        if (i + 2 < n) { g_cursor[i + 2] = e2;   g_rowptr[i + 3] = e3; }
        if (i + 3 < n) { g_cursor[i + 3] = e3;   g_rowptr[i + 4] = e3 + v3; }
        __syncthreads();
        if (tid == 0) s_carry = carry + tot;
        __syncthreads();
    }
}

// fill also: re-zeros g_count (post-scan; restores rest state for next replay)
// and zeros asrc2/adst2 (before gemm2's atomic accumulation, which is after the join).
__global__ void fill_kernel(const int* __restrict__ ei, int E, int n) {
    int i = blockIdx.x * blockDim.x + threadIdx.x;
    int tot = E + n;
    if (i >= tot) return;
    int s, d;
    if (i < E) {
        s = ei[i]; d = ei[E + i];
        if (i < n) g_count[i] = 0;
    } else {
        s = d = i - E;
        g_asrc2[d] = 0.f;
        g_adst2[d] = 0.f;
        if (n > E && d + E < n) g_count[d + E] = 0;   // cover n > E case (not hit here)
    }
    int pos = atomicAdd(&g_cursor[d], 1);
    g_csrsrc[pos] = s;
}

// ---------------- transpose + tf32-round both weights in one launch ----------------
__global__ void transpose_round2_kernel(const float* __restrict__ W1,
                                        const float* __restrict__ W2) {
    __shared__ float tile[32][33];
    const float* W  = (blockIdx.z == 0) ? W1 : W2;
    float* Wt = (blockIdx.z == 0) ? g_wt1 : g_wt2;
    int bx = blockIdx.x * 32, by = blockIdx.y * 32;
    int tx = threadIdx.x, ty = threadIdx.y;   // 32 x 8
    #pragma unroll
    for (int i = 0; i < 32; i += 8)
        tile[ty + i][tx] = W[(by + ty + i) * FEAT + bx + tx];
    __syncthreads();
    #pragma unroll
    for (int i = 0; i < 32; i += 8) {
        float v = tile[tx][ty + i];
        uint32_t o;
        asm("cvt.rna.tf32.f32 %0, %1;" : "=r"(o) : "f"(v));
        Wt[(bx + ty + i) * FEAT + by + tx] = __uint_as_float(o);
    }
}

// ---------------- TF32 tensor-core GEMM, fp16 output, fused attention-logit epilogue ----------------
#define GP 20                // smem pitch in floats (ldmatrix conflict-free)
#define STAGE_FLOATS (2 * 128 * GP)   // As + Bs per stage

__device__ __forceinline__ void ldsm_x4(uint32_t addr, uint32_t& r0, uint32_t& r1,
                                        uint32_t& r2, uint32_t& r3) {
    asm volatile("ldmatrix.sync.aligned.m8n8.x4.shared.b16 {%0,%1,%2,%3}, [%4];"
                 : "=r"(r0), "=r"(r1), "=r"(r2), "=r"(r3) : "r"(addr));
}

__device__ __forceinline__ uint32_t f2tf32(uint32_t x) {
    uint32_t o;
    asm("cvt.rna.tf32.f32 %0, %1;" : "=r"(o) : "f"(__uint_as_float(x)));
    return o;
}

__device__ __forceinline__ void mma_tf32(float* c, const uint32_t* a, const uint32_t* b) {
    asm volatile(
        "mma.sync.aligned.m16n8k8.row.col.f32.tf32.tf32.f32 "
        "{%0,%1,%2,%3}, {%4,%5,%6,%7}, {%8,%9}, {%0,%1,%2,%3};"
        : "+f"(c[0]), "+f"(c[1]), "+f"(c[2]), "+f"(c[3])
        : "r"(a[0]), "r"(a[1]), "r"(a[2]), "r"(a[3]), "r"(b[0]), "r"(b[1]));
}

__device__ __forceinline__ void cp16(uint32_t saddr, const void* gptr, uint32_t srcsize) {
    asm volatile("cp.async.ca.shared.global [%0], [%1], 16, %2;\n"
                 :: "r"(saddr), "l"(gptr), "r"(srcsize));
}

template<int HEADS>
__global__ __launch_bounds__(256) void gemm_att_kernel(
    const float* __restrict__ A, const float* __restrict__ Wt,
    __half* __restrict__ Ch,
    const float* __restrict__ attS, const float* __restrict__ attD,
    float* __restrict__ oS, float* __restrict__ oD, int M)
{
    __shared__ float smem[2 * STAGE_FLOATS];
    const int K = 256;
    int tid = threadIdx.x;
    int lane = tid & 31;
    int warp = tid >> 5;
    int wm = warp >> 1;          // 0..3
    int wn = warp & 1;           // 0..1
    int block_row = blockIdx.x * 128;
    int block_col = blockIdx.y * 128;

    uint32_t s_base = (uint32_t)__cvta_generic_to_shared(smem);
    uint32_t sA = s_base;
    uint32_t sB = s_base + 128 * GP * 4;
    const uint32_t stage_bytes = STAGE_FLOATS * 4;

    int c0i = tid * 2, c1i = tid * 2 + 1;
    int ar0 = c0i >> 2, ac0 = (c0i & 3) * 4;
    int ar1 = c1i >> 2, ac1 = (c1i & 3) * 4;
    uint32_t dstA0 = sA + (uint32_t)(ar0 * GP + ac0) * 4;
    uint32_t dstA1 = sA + (uint32_t)(ar1 * GP + ac1) * 4;
    uint32_t dstB0 = sB + (uint32_t)(ar0 * GP + ac0) * 4;
    uint32_t dstB1 = sB + (uint32_t)(ar1 * GP + ac1) * 4;
    int grA0 = block_row + ar0, grA1 = block_row + ar1;
    uint32_t szA0 = (grA0 < M) ? 16u : 0u;
    uint32_t szA1 = (grA1 < M) ? 16u : 0u;
    if (grA0 >= M) grA0 = 0;
    if (grA1 >= M) grA1 = 0;
    const float* srcA0 = A + (size_t)grA0 * K + ac0;
    const float* srcA1 = A + (size_t)grA1 * K + ac1;
    const float* srcB0 = Wt + (size_t)(block_col + ar0) * K + ac0;
    const float* srcB1 = Wt + (size_t)(block_col + ar1) * K + ac1;

    int g = lane >> 3, r = lane & 7;
    int a_row_l = (g & 1) * 8 + r;
    int a_koff  = (g >> 1) * 4;
    uint32_t a_base[2];
    #pragma unroll
    for (int mt = 0; mt < 2; mt++)
        a_base[mt] = sA + (uint32_t)((wm * 32 + mt * 16 + a_row_l) * GP + a_koff) * 4;
    int b_row_l = (g >> 1) * 8 + r;
    int b_koff  = (g & 1) * 4;
    uint32_t b_base[4];
    #pragma unroll
    for (int np = 0; np < 4; np++)
        b_base[np] = sB + (uint32_t)((wn * 64 + np * 16 + b_row_l) * GP + b_koff) * 4;

    float acc[2][8][4];
    #pragma unroll
    for (int mt = 0; mt < 2; mt++)
        #pragma unroll
        for (int nt = 0; nt < 8; nt++)
            #pragma unroll
            for (int q = 0; q < 4; q++) acc[mt][nt][q] = 0.f;

    cp16(dstA0, srcA0, szA0);
    cp16(dstA1, srcA1, szA1);
    cp16(dstB0, srcB0, 16u);
    cp16(dstB1, srcB1, 16u);
    asm volatile("cp.async.commit_group;\n" ::);

    const int NITER = K / 16;   // 16
    for (int it = 0; it < NITER; it++) {
        int buf = it & 1;
        if (it + 1 < NITER) {
            uint32_t off = ((it + 1) & 1) * stage_bytes;
            int k0 = (it + 1) * 16;
            cp16(dstA0 + off, srcA0 + k0, szA0);
            cp16(dstA1 + off, srcA1 + k0, szA1);
            cp16(dstB0 + off, srcB0 + k0, 16u);
            cp16(dstB1 + off, srcB1 + k0, 16u);
            asm volatile("cp.async.commit_group;\n" ::);
            asm volatile("cp.async.wait_group 1;\n" ::);
        } else {
            asm volatile("cp.async.wait_group 0;\n" ::);
        }
        __syncthreads();

        uint32_t soff = buf * stage_bytes;
        #pragma unroll
        for (int ks = 0; ks < 16; ks += 8) {
            uint32_t a[2][4], b[4][4];
            #pragma unroll
            for (int mt = 0; mt < 2; mt++) {
                ldsm_x4(a_base[mt] + soff + ks * 4, a[mt][0], a[mt][1], a[mt][2], a[mt][3]);
                #pragma unroll
                for (int q = 0; q < 4; q++) a[mt][q] = f2tf32(a[mt][q]);
            }
            #pragma unroll
            for (int np = 0; np < 4; np++)
                ldsm_x4(b_base[np] + soff + ks * 4, b[np][0], b[np][1], b[np][2], b[np][3]);
            #pragma unroll
            for (int mt = 0; mt < 2; mt++)
                #pragma unroll
                for (int nt = 0; nt < 8; nt++)
                    mma_tf32(acc[mt][nt], a[mt], &b[nt >> 1][(nt & 1) * 2]);
        }
        __syncthreads();
    }

    // ---- epilogue: fp16 stores ----
    int cr = lane >> 2;
    int cc = (lane & 3) * 2;
    #pragma unroll
    for (int mt = 0; mt < 2; mt++) {
        int row0 = block_row + wm * 32 + mt * 16 + cr;
        #pragma unroll
        for (int nt = 0; nt < 8; nt++) {
            int col = block_col + wn * 64 + nt * 8 + cc;
            if (row0 < M)
                *reinterpret_cast<__half2*>(Ch + (size_t)row0 * 256 + col) =
                    __float22half2_rn(make_float2(acc[mt][nt][0], acc[mt][nt][1]));
            if (row0 + 8 < M)
                *reinterpret_cast<__half2*>(Ch + (size_t)(row0 + 8) * 256 + col) =
                    __float22half2_rn(make_float2(acc[mt][nt][2], acc[mt][nt][3]));
        }
    }

    // ---- epilogue: fused attention-logit partial dots over this warp's 64 cols ----
    float ps[2][2] = {{0.f,0.f},{0.f,0.f}};
    float pd[2][2] = {{0.f,0.f},{0.f,0.f}};
    #pragma unroll
    for (int mt = 0; mt < 2; mt++) {
        #pragma unroll
        for (int nt = 0; nt < 8; nt++) {
            int lc = nt * 8 + cc;
            int idx = (HEADS == 4) ? ((blockIdx.y * 2 + wn) * 64 + lc)
                                   : (block_col + wn * 64 + lc);
            float as0 = attS[idx], as1 = attS[idx + 1];
            float ad0 = attD[idx], ad1 = attD[idx + 1];
            ps[mt][0] += acc[mt][nt][0] * as0 + acc[mt][nt][1] * as1;
            ps[mt][1] += acc[mt][nt][2] * as0 + acc[mt][nt][3] * as1;
            pd[mt][0] += acc[mt][nt][0] * ad0 + acc[mt][nt][1] * ad1;
            pd[mt][1] += acc[mt][nt][2] * ad0 + acc[mt][nt][3] * ad1;
        }
    }
    #pragma unroll
    for (int mt = 0; mt < 2; mt++)
        #pragma unroll
        for (int hf = 0; hf < 2; hf++) {
            ps[mt][hf] += __shfl_xor_sync(0xffffffffu, ps[mt][hf], 1);
            ps[mt][hf] += __shfl_xor_sync(0xffffffffu, ps[mt][hf], 2);
            pd[mt][hf] += __shfl_xor_sync(0xffffffffu, pd[mt][hf], 1);
            pd[mt][hf] += __shfl_xor_sync(0xffffffffu, pd[mt][hf], 2);
        }
    if ((lane & 3) == 0) {
        #pragma unroll
        for (int mt = 0; mt < 2; mt++)
            #pragma unroll
            for (int hf = 0; hf < 2; hf++) {
                int node = block_row + wm * 32 + mt * 16 + cr + hf * 8;
                if (node < M) {
                    if (HEADS == 4) {
                        int head = blockIdx.y * 2 + wn;
                        oS[node * 4 + head] = ps[mt][hf];
                        oD[node * 4 + head] = pd[mt][hf];
                    } else {
                        atomicAdd(&oS[node], ps[mt][hf]);
                        atomicAdd(&oD[node], pd[mt][hf]);
                    }
                }
            }
    }
}

__device__ __forceinline__ float leaky(float x) {
    return (x > 0.f) ? x : NEG_SLOPE * x;
}

__device__ __forceinline__ void unpack8h(uint4 u, float* f) {
    float2 a = __half22float2(*reinterpret_cast<__half2*>(&u.x));
    float2 b = __half22float2(*reinterpret_cast<__half2*>(&u.y));
    float2 c = __half22float2(*reinterpret_cast<__half2*>(&u.z));
    float2 d = __half22float2(*reinterpret_cast<__half2*>(&u.w));
    f[0] = a.x; f[1] = a.y; f[2] = b.x; f[3] = b.y;
    f[4] = c.x; f[5] = c.y; f[6] = d.x; f[7] = d.y;
}

// ---------------- aggregation, layer 1 (4 heads, fp16 gather) + bias + ELU ----------------
__global__ void agg1_kernel(const __half* __restrict__ xph,
                            const float* __restrict__ bias,
                            float* __restrict__ out, int n)
{
    int node = (blockIdx.x * blockDim.x + threadIdx.x) >> 5;
    if (node >= n) return;
    int lane = threadIdx.x & 31;
    int h  = lane >> 3;         // 8 lanes per head
    int c0 = lane * 8;
    float ad = g_adst[node * NHEADS + h];
    int beg = g_rowptr[node], end = g_rowptr[node + 1];
    float m = -1e30f, s = 0.f;
    float acc[8] = {0,0,0,0,0,0,0,0};
    int p = beg;
    for (; p + 1 < end; p += 2) {
        int j0 = g_csrsrc[p];
        int j1 = g_csrsrc[p + 1];
        float e0 = leaky(g_asrc[j0 * NHEADS + h] + ad);
        float e1 = leaky(g_asrc[j1 * NHEADS + h] + ad);
        uint4 u0 = *reinterpret_cast<const uint4*>(xph + (size_t)j0 * FEAT + c0);
        uint4 u1 = *reinterpret_cast<const uint4*>(xph + (size_t)j1 * FEAT + c0);
        float fa[8], fb[8];
        unpack8h(u0, fa);
        unpack8h(u1, fb);
        float mn = fmaxf(m, fmaxf(e0, e1));
        float corr = __expf(m - mn);
        float p0   = __expf(e0 - mn);
        float p1   = __expf(e1 - mn);
        s = s * corr + p0 + p1;
        #pragma unroll
        for (int k = 0; k < 8; k++)
            acc[k] = acc[k] * corr + p0 * fa[k] + p1 * fb[k];
        m = mn;
    }
    if (p < end) {
        int j = g_csrsrc[p];
        float e = leaky(g_asrc[j * NHEADS + h] + ad);
        uint4 u = *reinterpret_cast<const uint4*>(xph + (size_t)j * FEAT + c0);
        float fa[8];
        unpack8h(u, fa);
        float mn = fmaxf(m, e);
        float corr = __expf(m - mn);
        float pw   = __expf(e - mn);
        s = s * corr + pw;
        #pragma unroll
        for (int k = 0; k < 8; k++)
            acc[k] = acc[k] * corr + pw * fa[k];
    }
    float inv = 1.f / s;
    const float4* b4 = reinterpret_cast<const float4*>(bias + c0);
    float4 bb0 = b4[0], bb1 = b4[1];
    float vb[8] = {bb0.x, bb0.y, bb0.z, bb0.w, bb1.x, bb1.y, bb1.z, bb1.w};
    float v[8];
    #pragma unroll
    for (int k = 0; k < 8; k++) {
        float t = acc[k] * inv + vb[k];
        v[k] = (t > 0.f) ? t : expm1f(t);   // ELU
    }
    float4 o0 = make_float4(v[0], v[1], v[2], v[3]);
    float4 o1 = make_float4(v[4], v[5], v[6], v[7]);
    float4* orow = reinterpret_cast<float4*>(out + (size_t)node * FEAT + c0);
    orow[0] = o0; orow[1] = o1;
}

// ---------------- aggregation, layer 2 (1 head, fp16 gather) + bias + ELU + BN + LN ----------------
__global__ void agg2_kernel(const __half* __restrict__ xph,
                            const float* __restrict__ bias,
                            const float* __restrict__ bn_gamma,
                            const float* __restrict__ bn_beta,
                            const float* __restrict__ bn_mean,
                            const float* __restrict__ bn_var,
                            const float* __restrict__ ln_gamma,
                            const float* __restrict__ ln_beta,
                            float* __restrict__ out, int n)
{
    int node = (blockIdx.x * blockDim.x + threadIdx.x) >> 5;
    if (node >= n) return;
    int lane = threadIdx.x & 31;
    int c0 = lane * 8;
    float ad = g_adst2[node];
    int beg = g_rowptr[node], end = g_rowptr[node + 1];
    float m = -1e30f, s = 0.f;
    float acc[8] = {0,0,0,0,0,0,0,0};
    int p = beg;
    for (; p + 1 < end; p += 2) {
        int j0 = g_csrsrc[p];
        int j1 = g_csrsrc[p + 1];
        float e0 = leaky(g_asrc2[j0] + ad);
        float e1 = leaky(g_asrc2[j1] + ad);
        uint4 u0 = *reinterpret_cast<const uint4*>(xph + (size_t)j0 * FEAT + c0);
        uint4 u1 = *reinterpret_cast<const uint4*>(xph + (size_t)j1 * FEAT + c0);
        float fa[8], fb[8];
        unpack8h(u0, fa);
        unpack8h(u1, fb);
        float mn = fmaxf(m, fmaxf(e0, e1));
        float corr = __expf(m - mn);
        float p0   = __expf(e0 - mn);
        float p1   = __expf(e1 - mn);
        s = s * corr + p0 + p1;
        #pragma unroll
        for (int k = 0; k < 8; k++)
            acc[k] = acc[k] * corr + p0 * fa[k] + p1 * fb[k];
        m = mn;
    }
    if (p < end) {
        int j = g_csrsrc[p];
        float e = leaky(g_asrc2[j] + ad);
        uint4 u = *reinterpret_cast<const uint4*>(xph + (size_t)j * FEAT + c0);
        float fa[8];
        unpack8h(u, fa);
        float mn = fmaxf(m, e);
        float corr = __expf(m - mn);
        float pw   = __expf(e - mn);
        s = s * corr + pw;
        #pragma unroll
        for (int k = 0; k < 8; k++)
            acc[k] = acc[k] * corr + pw * fa[k];
    }
    float inv = 1.f / s;
    float v[8];
    #pragma unroll
    for (int k = 0; k < 8; k++) {
        int c = c0 + k;
        float x = acc[k] * inv + bias[c];
        x = (x > 0.f) ? x : expm1f(x);                           // ELU
        x = (x - bn_mean[c]) * rsqrtf(bn_var[c] + BN_EPS) * bn_gamma[c] + bn_beta[c];  // BN eval
        v[k] = x;
    }
    // LayerNorm over 256 channels (warp = row, 8 ch/lane)
    float lsum = 0.f;
    #pragma unroll
    for (int k = 0; k < 8; k++) lsum += v[k];
    #pragma unroll
    for (int off = 16; off; off >>= 1) lsum += __shfl_xor_sync(0xffffffffu, lsum, off);
    float mu = lsum * (1.f / 256.f);
    float lvar = 0.f;
    #pragma unroll
    for (int k = 0; k < 8; k++) { float d = v[k] - mu; lvar += d * d; }
    #pragma unroll
    for (int off = 16; off; off >>= 1) lvar += __shfl_xor_sync(0xffffffffu, lvar, off);
    float r = rsqrtf(lvar * (1.f / 256.f) + LN_EPS);
    float w[8];
    #pragma unroll
    for (int k = 0; k < 8; k++) {
        int c = c0 + k;
        w[k] = (v[k] - mu) * r * ln_gamma[c] + ln_beta[c];
    }
    float4 o0 = make_float4(w[0], w[1], w[2], w[3]);
    float4 o1 = make_float4(w[4], w[5], w[6], w[7]);
    float4* orow = reinterpret_cast<float4*>(out + (size_t)node * FEAT + c0);
    orow[0] = o0; orow[1] = o1;
}

// ---------------- launch ----------------
extern "C" void kernel_launch(void* const* d_in, const int* in_sizes, int n_in,
                              void* d_out, int out_size)
{
    const float* x        = (const float*)d_in[0];
    const int*   ei       = (const int*)  d_in[1];
    const float* W1       = (const float*)d_in[2];
    const float* att_src1 = (const float*)d_in[3];
    const float* att_dst1 = (const float*)d_in[4];
    const float* bias1    = (const float*)d_in[5];
    const float* W2       = (const float*)d_in[6];
    const float* att_src2 = (const float*)d_in[7];
    const float* att_dst2 = (const float*)d_in[8];
    const float* bias2    = (const float*)d_in[9];
    const float* bn_gamma = (const float*)d_in[10];
    const float* bn_beta  = (const float*)d_in[11];
    const float* bn_mean  = (const float*)d_in[12];
    const float* bn_var   = (const float*)d_in[13];
    const float* ln_gamma = (const float*)d_in[14];
    const float* ln_beta  = (const float*)d_in[15];
    float* out = (float*)d_out;

    int n = in_sizes[0] / FEAT;      // 50000
    int E = in_sizes[1] / 2;         // 800000
    if (n > NN) n = NN;
    if (E > EMAX) E = EMAX;

    float *h1, *wt1, *wt2, *asrc, *adst, *asrc2, *adst2;
    __half* xph;
    cudaGetSymbolAddress((void**)&xph,   g_xph);
    cudaGetSymbolAddress((void**)&h1,    g_h1);
    cudaGetSymbolAddress((void**)&wt1,   g_wt1);
    cudaGetSymbolAddress((void**)&wt2,   g_wt2);
    cudaGetSymbolAddress((void**)&asrc,  g_asrc);
    cudaGetSymbolAddress((void**)&adst,  g_adst);
    cudaGetSymbolAddress((void**)&asrc2, g_asrc2);
    cudaGetSymbolAddress((void**)&adst2, g_adst2);

    // lazy side-stream / event creation (first call is outside graph capture)
    static cudaStream_t s_side = nullptr;
    static cudaEvent_t  s_evF  = nullptr, s_evJ = nullptr;
    if (s_side == nullptr) {
        cudaStreamCreateWithFlags(&s_side, cudaStreamNonBlocking);
        cudaEventCreateWithFlags(&s_evF, cudaEventDisableTiming);
        cudaEventCreateWithFlags(&s_evJ, cudaEventDisableTiming);
    }

    // --- fork: CSR build on side stream, GEMM path on main stream ---
    cudaEventRecord(s_evF, 0);
    cudaStreamWaitEvent(s_side, s_evF, 0);
    count_kernel<<<(E + 255) / 256, 256, 0, s_side>>>(ei, E, n);
    scan_kernel<<<1, 1024, 0, s_side>>>(n);
    fill_kernel<<<(E + n + 255) / 256, 256, 0, s_side>>>(ei, E, n);
    cudaEventRecord(s_evJ, s_side);

    // --- main stream: both weight transposes in ONE launch + layer-1 GEMM ---
    dim3 tgrid(FEAT / 32, FEAT / 32, 2), tblk(32, 8);
    transpose_round2_kernel<<<tgrid, tblk>>>(W1, W2);

    dim3 ggrid((n + 127) / 128, FEAT / 128);
    gemm_att_kernel<4><<<ggrid, 256>>>(x, wt1, xph,
                                       att_src1, att_dst1, asrc, adst, n);

    // --- join: CSR ready ---
    cudaStreamWaitEvent(0, s_evJ, 0);

    agg1_kernel<<<(n * 32 + 255) / 256, 256>>>(xph, bias1, h1, n);

    // --- layer 2 ---
    gemm_att_kernel<1><<<ggrid, 256>>>(h1, wt2, xph,
                                       att_src2, att_dst2, asrc2, adst2, n);
    agg2_kernel<<<(n * 32 + 255) / 256, 256>>>(xph, bias2, bn_gamma, bn_beta, bn_mean,
                                               bn_var, ln_gamma, ln_beta, out, n);
    (void)n_in; (void)out_size;
}

// round 10
// speedup vs baseline: 2.2621x; 1.0111x over previous
#include <cuda_runtime.h>
#include <cuda_fp16.h>
#include <math.h>
#include <stdint.h>

// ---------------- problem constants ----------------
#define NN      50000      // nodes
#define EMAX    800000     // edges (before self loops)
#define ETOT    (EMAX + NN)
#define FEAT    256        // NFEAT = NHEADS*NHID = NOUT = 256
#define NHEADS  4
#define NHID    64
#define NEG_SLOPE 0.2f
#define BN_EPS  1e-5f
#define LN_EPS  1e-5f

// ---------------- scratch (device globals; no runtime alloc) ----------------
__device__ __half g_xph[NN * FEAT];            // xp of current layer (fp16, reused both layers)
__device__ float g_h1[NN * FEAT];              // layer-1 output (ELU'd, fp32)
__device__ float g_wt1[FEAT * FEAT];           // W1^T, tf32-rounded, [n][k]
__device__ float g_wt2[FEAT * FEAT];           // W2^T, tf32-rounded, [n][k]
__device__ float g_asrc[NN * NHEADS];          // layer-1 logits (per head)
__device__ float g_adst[NN * NHEADS];
__device__ float g_asrc2[NN];                  // layer-2 logits (atomic-accumulated)
__device__ float g_adst2[NN];
__device__ int   g_count[NN];                  // zero at rest (restored by fill_kernel)
__device__ int   g_rowptr[NN + 1];
__device__ int   g_cursor[NN];
__device__ int   g_csrsrc[ETOT];

// ---------------- count + weight transposes fused (one launch) ----------------
// blocks [0, nblk_e): edge histogram. blocks [nblk_e, nblk_e+128): transpose W1/W2.
__global__ void count_transpose_kernel(const int* __restrict__ ei, int E, int nblk_e,
                                       const float* __restrict__ W1,
                                       const float* __restrict__ W2) {
    if ((int)blockIdx.x < nblk_e) {
        int i = blockIdx.x * blockDim.x + threadIdx.x;
        if (i < E) {
            int d = ei[E + i];      // dst row of edge_index
            atomicAdd(&g_count[d], 1);
        }
        return;
    }
    // transpose part: 64 blocks per weight (8x8 tiles of 32x32), 2 weights
    __shared__ float tile[32][33];
    int tb = blockIdx.x - nblk_e;          // 0..127
    int z = tb >> 6;                        // 0 = W1, 1 = W2
    int rem = tb & 63;
    int bx = (rem & 7) * 32, by = (rem >> 3) * 32;
    const float* W  = (z == 0) ? W1 : W2;
    float* Wt = (z == 0) ? g_wt1 : g_wt2;
    int tx = threadIdx.x & 31, ty = threadIdx.x >> 5;   // 32 x 8
    #pragma unroll
    for (int i = 0; i < 32; i += 8)
        tile[ty + i][tx] = W[(by + ty + i) * FEAT + bx + tx];
    __syncthreads();
    #pragma unroll
    for (int i = 0; i < 32; i += 8) {
        float v = tile[tx][ty + i];
        uint32_t o;
        asm("cvt.rna.tf32.f32 %0, %1;" : "=r"(o) : "f"(v));
        Wt[(bx + ty + i) * FEAT + by + tx] = __uint_as_float(o);
    }
}

// single-block scan, 1024 threads, 4 elements/thread; adds +1 per node (self loop)
__global__ void scan_kernel(int n) {
    __shared__ int warpsum[32];
    __shared__ int s_carry;
    int tid = threadIdx.x, lane = tid & 31, wid = tid >> 5;
    if (tid == 0) { s_carry = 0; g_rowptr[0] = 0; }
    __syncthreads();
    for (int base = 0; base < n; base += 4096) {
        int i = base + tid * 4;
        int v0 = 0, v1 = 0, v2 = 0, v3 = 0;
        if (i + 3 < n) {
            int4 q = *reinterpret_cast<const int4*>(&g_count[i]);
            v0 = q.x + 1; v1 = q.y + 1; v2 = q.z + 1; v3 = q.w + 1;  // +1 self loop
        } else {
            if (i     < n) v0 = g_count[i]     + 1;
            if (i + 1 < n) v1 = g_count[i + 1] + 1;
            if (i + 2 < n) v2 = g_count[i + 2] + 1;
        }
        int t = v0 + v1 + v2 + v3;
        int x = t;
        #pragma unroll
        for (int off = 1; off < 32; off <<= 1) {
            int y = __shfl_up_sync(0xffffffffu, x, off);
            if (lane >= off) x += y;
        }
        if (lane == 31) warpsum[wid] = x;
        __syncthreads();
        int woff = 0, tot = 0;
        #pragma unroll
        for (int w = 0; w < 32; w++) {
            int ws = warpsum[w];
            if (w < wid) woff += ws;
            tot += ws;
        }
        int carry = s_carry;
        int excl = carry + woff + x - t;   // exclusive prefix at element i
        int e1 = excl + v0, e2 = e1 + v1, e3 = e2 + v2;
        if (i     < n) { g_cursor[i]     = excl; g_rowptr[i + 1] = e1; }
        if (i + 1 < n) { g_cursor[i + 1] = e1;   g_rowptr[i + 2] = e2; }
        if (i + 2 < n) { g_cursor[i + 2] = e2;   g_rowptr[i + 3] = e3; }
        if (i + 3 < n) { g_cursor[i + 3] = e3;   g_rowptr[i + 4] = e3 + v3; }
        __syncthreads();
        if (tid == 0) s_carry = carry + tot;
        __syncthreads();
    }
}

// fill also: re-zeros g_count (post-scan; restores rest state for next replay)
// and zeros asrc2/adst2 (before gemm2's atomic accumulation, which is after the join).
__global__ void fill_kernel(const int* __restrict__ ei, int E, int n) {
    int i = blockIdx.x * blockDim.x + threadIdx.x;
    int tot = E + n;
    if (i >= tot) return;
    int s, d;
    if (i < E) {
        s = ei[i]; d = ei[E + i];
        if (i < n) g_count[i] = 0;
    } else {
        s = d = i - E;
        g_asrc2[d] = 0.f;
        g_adst2[d] = 0.f;
    }
    int pos = atomicAdd(&g_cursor[d], 1);
    g_csrsrc[pos] = s;
}

// ---------------- TF32 tensor-core GEMM, fp16 output, fused attention-logit epilogue ----------------
#define GP 20                // smem pitch in floats (ldmatrix conflict-free)
#define STAGE_FLOATS (2 * 128 * GP)   // As + Bs per stage

__device__ __forceinline__ void ldsm_x4(uint32_t addr, uint32_t& r0, uint32_t& r1,
                                        uint32_t& r2, uint32_t& r3) {
    asm volatile("ldmatrix.sync.aligned.m8n8.x4.shared.b16 {%0,%1,%2,%3}, [%4];"
                 : "=r"(r0), "=r"(r1), "=r"(r2), "=r"(r3) : "r"(addr));
}

__device__ __forceinline__ uint32_t f2tf32(uint32_t x) {
    uint32_t o;
    asm("cvt.rna.tf32.f32 %0, %1;" : "=r"(o) : "f"(__uint_as_float(x)));
    return o;
}

__device__ __forceinline__ void mma_tf32(float* c, const uint32_t* a, const uint32_t* b) {
    asm volatile(
        "mma.sync.aligned.m16n8k8.row.col.f32.tf32.tf32.f32 "
        "{%0,%1,%2,%3}, {%4,%5,%6,%7}, {%8,%9}, {%0,%1,%2,%3};"
        : "+f"(c[0]), "+f"(c[1]), "+f"(c[2]), "+f"(c[3])
        : "r"(a[0]), "r"(a[1]), "r"(a[2]), "r"(a[3]), "r"(b[0]), "r"(b[1]));
}

__device__ __forceinline__ void cp16(uint32_t saddr, const void* gptr, uint32_t srcsize) {
    asm volatile("cp.async.ca.shared.global [%0], [%1], 16, %2;\n"
                 :: "r"(saddr), "l"(gptr), "r"(srcsize));
}

template<int HEADS>
__global__ __launch_bounds__(256) void gemm_att_kernel(
    const float* __restrict__ A, const float* __restrict__ Wt,
    __half* __restrict__ Ch,
    const float* __restrict__ attS, const float* __restrict__ attD,
    float* __restrict__ oS, float* __restrict__ oD, int M)
{
    __shared__ float smem[2 * STAGE_FLOATS];
    const int K = 256;
    int tid = threadIdx.x;
    int lane = tid & 31;
    int warp = tid >> 5;
    int wm = warp >> 1;          // 0..3
    int wn = warp & 1;           // 0..1
    int block_row = blockIdx.x * 128;
    int block_col = blockIdx.y * 128;

    uint32_t s_base = (uint32_t)__cvta_generic_to_shared(smem);
    uint32_t sA = s_base;
    uint32_t sB = s_base + 128 * GP * 4;
    const uint32_t stage_bytes = STAGE_FLOATS * 4;

    int c0i = tid * 2, c1i = tid * 2 + 1;
    int ar0 = c0i >> 2, ac0 = (c0i & 3) * 4;
    int ar1 = c1i >> 2, ac1 = (c1i & 3) * 4;
    uint32_t dstA0 = sA + (uint32_t)(ar0 * GP + ac0) * 4;
    uint32_t dstA1 = sA + (uint32_t)(ar1 * GP + ac1) * 4;
    uint32_t dstB0 = sB + (uint32_t)(ar0 * GP + ac0) * 4;
    uint32_t dstB1 = sB + (uint32_t)(ar1 * GP + ac1) * 4;
    int grA0 = block_row + ar0, grA1 = block_row + ar1;
    uint32_t szA0 = (grA0 < M) ? 16u : 0u;
    uint32_t szA1 = (grA1 < M) ? 16u : 0u;
    if (grA0 >= M) grA0 = 0;
    if (grA1 >= M) grA1 = 0;
    const float* srcA0 = A + (size_t)grA0 * K + ac0;
    const float* srcA1 = A + (size_t)grA1 * K + ac1;
    const float* srcB0 = Wt + (size_t)(block_col + ar0) * K + ac0;
    const float* srcB1 = Wt + (size_t)(block_col + ar1) * K + ac1;

    int g = lane >> 3, r = lane & 7;
    int a_row_l = (g & 1) * 8 + r;
    int a_koff  = (g >> 1) * 4;
    uint32_t a_base[2];
    #pragma unroll
    for (int mt = 0; mt < 2; mt++)
        a_base[mt] = sA + (uint32_t)((wm * 32 + mt * 16 + a_row_l) * GP + a_koff) * 4;
    int b_row_l = (g >> 1) * 8 + r;
    int b_koff  = (g & 1) * 4;
    uint32_t b_base[4];
    #pragma unroll
    for (int np = 0; np < 4; np++)
        b_base[np] = sB + (uint32_t)((wn * 64 + np * 16 + b_row_l) * GP + b_koff) * 4;

    float acc[2][8][4];
    #pragma unroll
    for (int mt = 0; mt < 2; mt++)
        #pragma unroll
        for (int nt = 0; nt < 8; nt++)
            #pragma unroll
            for (int q = 0; q < 4; q++) acc[mt][nt][q] = 0.f;

    cp16(dstA0, srcA0, szA0);
    cp16(dstA1, srcA1, szA1);
    cp16(dstB0, srcB0, 16u);
    cp16(dstB1, srcB1, 16u);
    asm volatile("cp.async.commit_group;\n" ::);

    const int NITER = K / 16;   // 16
    for (int it = 0; it < NITER; it++) {
        int buf = it & 1;
        if (it + 1 < NITER) {
            uint32_t off = ((it + 1) & 1) * stage_bytes;
            int k0 = (it + 1) * 16;
            cp16(dstA0 + off, srcA0 + k0, szA0);
            cp16(dstA1 + off, srcA1 + k0, szA1);
            cp16(dstB0 + off, srcB0 + k0, 16u);
            cp16(dstB1 + off, srcB1 + k0, 16u);
            asm volatile("cp.async.commit_group;\n" ::);
            asm volatile("cp.async.wait_group 1;\n" ::);
        } else {
            asm volatile("cp.async.wait_group 0;\n" ::);
        }
        __syncthreads();

        uint32_t soff = buf * stage_bytes;
        #pragma unroll
        for (int ks = 0; ks < 16; ks += 8) {
            uint32_t a[2][4], b[4][4];
            #pragma unroll
            for (int mt = 0; mt < 2; mt++) {
                ldsm_x4(a_base[mt] + soff + ks * 4, a[mt][0], a[mt][1], a[mt][2], a[mt][3]);
                #pragma unroll
                for (int q = 0; q < 4; q++) a[mt][q] = f2tf32(a[mt][q]);
            }
            #pragma unroll
            for (int np = 0; np < 4; np++)
                ldsm_x4(b_base[np] + soff + ks * 4, b[np][0], b[np][1], b[np][2], b[np][3]);
            #pragma unroll
            for (int mt = 0; mt < 2; mt++)
                #pragma unroll
                for (int nt = 0; nt < 8; nt++)
                    mma_tf32(acc[mt][nt], a[mt], &b[nt >> 1][(nt & 1) * 2]);
        }
        __syncthreads();
    }

    // ---- epilogue: fp16 stores ----
    int cr = lane >> 2;
    int cc = (lane & 3) * 2;
    #pragma unroll
    for (int mt = 0; mt < 2; mt++) {
        int row0 = block_row + wm * 32 + mt * 16 + cr;
        #pragma unroll
        for (int nt = 0; nt < 8; nt++) {
            int col = block_col + wn * 64 + nt * 8 + cc;
            if (row0 < M)
                *reinterpret_cast<__half2*>(Ch + (size_t)row0 * 256 + col) =
                    __float22half2_rn(make_float2(acc[mt][nt][0], acc[mt][nt][1]));
            if (row0 + 8 < M)
                *reinterpret_cast<__half2*>(Ch + (size_t)(row0 + 8) * 256 + col) =
                    __float22half2_rn(make_float2(acc[mt][nt][2], acc[mt][nt][3]));
        }
    }

    // ---- epilogue: fused attention-logit partial dots over this warp's 64 cols ----
    float ps[2][2] = {{0.f,0.f},{0.f,0.f}};
    float pd[2][2] = {{0.f,0.f},{0.f,0.f}};
    #pragma unroll
    for (int mt = 0; mt < 2; mt++) {
        #pragma unroll
        for (int nt = 0; nt < 8; nt++) {
            int lc = nt * 8 + cc;
            int idx = (HEADS == 4) ? ((blockIdx.y * 2 + wn) * 64 + lc)
                                   : (block_col + wn * 64 + lc);
            float as0 = attS[idx], as1 = attS[idx + 1];
            float ad0 = attD[idx], ad1 = attD[idx + 1];
            ps[mt][0] += acc[mt][nt][0] * as0 + acc[mt][nt][1] * as1;
            ps[mt][1] += acc[mt][nt][2] * as0 + acc[mt][nt][3] * as1;
            pd[mt][0] += acc[mt][nt][0] * ad0 + acc[mt][nt][1] * ad1;
            pd[mt][1] += acc[mt][nt][2] * ad0 + acc[mt][nt][3] * ad1;
        }
    }
    #pragma unroll
    for (int mt = 0; mt < 2; mt++)
        #pragma unroll
        for (int hf = 0; hf < 2; hf++) {
            ps[mt][hf] += __shfl_xor_sync(0xffffffffu, ps[mt][hf], 1);
            ps[mt][hf] += __shfl_xor_sync(0xffffffffu, ps[mt][hf], 2);
            pd[mt][hf] += __shfl_xor_sync(0xffffffffu, pd[mt][hf], 1);
            pd[mt][hf] += __shfl_xor_sync(0xffffffffu, pd[mt][hf], 2);
        }
    if ((lane & 3) == 0) {
        #pragma unroll
        for (int mt = 0; mt < 2; mt++)
            #pragma unroll
            for (int hf = 0; hf < 2; hf++) {
                int node = block_row + wm * 32 + mt * 16 + cr + hf * 8;
                if (node < M) {
                    if (HEADS == 4) {
                        int head = blockIdx.y * 2 + wn;
                        oS[node * 4 + head] = ps[mt][hf];
                        oD[node * 4 + head] = pd[mt][hf];
                    } else {
                        atomicAdd(&oS[node], ps[mt][hf]);
                        atomicAdd(&oD[node], pd[mt][hf]);
                    }
                }
            }
    }
}

__device__ __forceinline__ float leaky(float x) {
    return (x > 0.f) ? x : NEG_SLOPE * x;
}

__device__ __forceinline__ void unpack8h(uint4 u, float* f) {
    float2 a = __half22float2(*reinterpret_cast<__half2*>(&u.x));
    float2 b = __half22float2(*reinterpret_cast<__half2*>(&u.y));
    float2 c = __half22float2(*reinterpret_cast<__half2*>(&u.z));
    float2 d = __half22float2(*reinterpret_cast<__half2*>(&u.w));
    f[0] = a.x; f[1] = a.y; f[2] = b.x; f[3] = b.y;
    f[4] = c.x; f[5] = c.y; f[6] = d.x; f[7] = d.y;
}

// ---------------- aggregation, layer 1 (4 heads, fp16 gather) + bias + ELU ----------------
// 64-thread blocks: 2 nodes/CTA -> minimal degree-tail waste.
__global__ __launch_bounds__(64) void agg1_kernel(const __half* __restrict__ xph,
                            const float* __restrict__ bias,
                            float* __restrict__ out, int n)
{
    int node = (blockIdx.x * blockDim.x + threadIdx.x) >> 5;
    if (node >= n) return;
    int lane = threadIdx.x & 31;
    int h  = lane >> 3;         // 8 lanes per head
    int c0 = lane * 8;
    float ad = g_adst[node * NHEADS + h];
    int beg = g_rowptr[node], end = g_rowptr[node + 1];
    float m = -1e30f, s = 0.f;
    float acc[8] = {0,0,0,0,0,0,0,0};
    int p = beg;
    for (; p + 1 < end; p += 2) {
        int j0 = g_csrsrc[p];
        int j1 = g_csrsrc[p + 1];
        float e0 = leaky(g_asrc[j0 * NHEADS + h] + ad);
        float e1 = leaky(g_asrc[j1 * NHEADS + h] + ad);
        uint4 u0 = *reinterpret_cast<const uint4*>(xph + (size_t)j0 * FEAT + c0);
        uint4 u1 = *reinterpret_cast<const uint4*>(xph + (size_t)j1 * FEAT + c0);
        float fa[8], fb[8];
        unpack8h(u0, fa);
        unpack8h(u1, fb);
        float mn = fmaxf(m, fmaxf(e0, e1));
        float corr = __expf(m - mn);
        float p0   = __expf(e0 - mn);
        float p1   = __expf(e1 - mn);
        s = s * corr + p0 + p1;
        #pragma unroll
        for (int k = 0; k < 8; k++)
            acc[k] = acc[k] * corr + p0 * fa[k] + p1 * fb[k];
        m = mn;
    }
    if (p < end) {
        int j = g_csrsrc[p];
        float e = leaky(g_asrc[j * NHEADS + h] + ad);
        uint4 u = *reinterpret_cast<const uint4*>(xph + (size_t)j * FEAT + c0);
        float fa[8];
        unpack8h(u, fa);
        float mn = fmaxf(m, e);
        float corr = __expf(m - mn);
        float pw   = __expf(e - mn);
        s = s * corr + pw;
        #pragma unroll
        for (int k = 0; k < 8; k++)
            acc[k] = acc[k] * corr + pw * fa[k];
    }
    float inv = 1.f / s;
    const float4* b4 = reinterpret_cast<const float4*>(bias + c0);
    float4 bb0 = b4[0], bb1 = b4[1];
    float vb[8] = {bb0.x, bb0.y, bb0.z, bb0.w, bb1.x, bb1.y, bb1.z, bb1.w};
    float v[8];
    #pragma unroll
    for (int k = 0; k < 8; k++) {
        float t = acc[k] * inv + vb[k];
        v[k] = (t > 0.f) ? t : expm1f(t);   // ELU
    }
    float4 o0 = make_float4(v[0], v[1], v[2], v[3]);
    float4 o1 = make_float4(v[4], v[5], v[6], v[7]);
    float4* orow = reinterpret_cast<float4*>(out + (size_t)node * FEAT + c0);
    orow[0] = o0; orow[1] = o1;
}

// ---------------- aggregation, layer 2 (1 head, fp16 gather) + bias + ELU + BN + LN ----------------
__global__ __launch_bounds__(64) void agg2_kernel(const __half* __restrict__ xph,
                            const float* __restrict__ bias,
                            const float* __restrict__ bn_gamma,
                            const float* __restrict__ bn_beta,
                            const float* __restrict__ bn_mean,
                            const float* __restrict__ bn_var,
                            const float* __restrict__ ln_gamma,
                            const float* __restrict__ ln_beta,
                            float* __restrict__ out, int n)
{
    int node = (blockIdx.x * blockDim.x + threadIdx.x) >> 5;
    if (node >= n) return;
    int lane = threadIdx.x & 31;
    int c0 = lane * 8;
    float ad = g_adst2[node];
    int beg = g_rowptr[node], end = g_rowptr[node + 1];
    float m = -1e30f, s = 0.f;
    float acc[8] = {0,0,0,0,0,0,0,0};
    int p = beg;
    for (; p + 1 < end; p += 2) {
        int j0 = g_csrsrc[p];
        int j1 = g_csrsrc[p + 1];
        float e0 = leaky(g_asrc2[j0] + ad);
        float e1 = leaky(g_asrc2[j1] + ad);
        uint4 u0 = *reinterpret_cast<const uint4*>(xph + (size_t)j0 * FEAT + c0);
        uint4 u1 = *reinterpret_cast<const uint4*>(xph + (size_t)j1 * FEAT + c0);
        float fa[8], fb[8];
        unpack8h(u0, fa);
        unpack8h(u1, fb);
        float mn = fmaxf(m, fmaxf(e0, e1));
        float corr = __expf(m - mn);
        float p0   = __expf(e0 - mn);
        float p1   = __expf(e1 - mn);
        s = s * corr + p0 + p1;
        #pragma unroll
        for (int k = 0; k < 8; k++)
            acc[k] = acc[k] * corr + p0 * fa[k] + p1 * fb[k];
        m = mn;
    }
    if (p < end) {
        int j = g_csrsrc[p];
        float e = leaky(g_asrc2[j] + ad);
        uint4 u = *reinterpret_cast<const uint4*>(xph + (size_t)j * FEAT + c0);
        float fa[8];
        unpack8h(u, fa);
        float mn = fmaxf(m, e);
        float corr = __expf(m - mn);
        float pw   = __expf(e - mn);
        s = s * corr + pw;
        #pragma unroll
        for (int k = 0; k < 8; k++)
            acc[k] = acc[k] * corr + pw * fa[k];
    }
    float inv = 1.f / s;
    float v[8];
    #pragma unroll
    for (int k = 0; k < 8; k++) {
        int c = c0 + k;
        float x = acc[k] * inv + bias[c];
        x = (x > 0.f) ? x : expm1f(x);                           // ELU
        x = (x - bn_mean[c]) * rsqrtf(bn_var[c] + BN_EPS) * bn_gamma[c] + bn_beta[c];  // BN eval
        v[k] = x;
    }
    // LayerNorm over 256 channels (warp = row, 8 ch/lane)
    float lsum = 0.f;
    #pragma unroll
    for (int k = 0; k < 8; k++) lsum += v[k];
    #pragma unroll
    for (int off = 16; off; off >>= 1) lsum += __shfl_xor_sync(0xffffffffu, lsum, off);
    float mu = lsum * (1.f / 256.f);
    float lvar = 0.f;
    #pragma unroll
    for (int k = 0; k < 8; k++) { float d = v[k] - mu; lvar += d * d; }
    #pragma unroll
    for (int off = 16; off; off >>= 1) lvar += __shfl_xor_sync(0xffffffffu, lvar, off);
    float r = rsqrtf(lvar * (1.f / 256.f) + LN_EPS);
    float w[8];
    #pragma unroll
    for (int k = 0; k < 8; k++) {
        int c = c0 + k;
        w[k] = (v[k] - mu) * r * ln_gamma[c] + ln_beta[c];
    }
    float4 o0 = make_float4(w[0], w[1], w[2], w[3]);
    float4 o1 = make_float4(w[4], w[5], w[6], w[7]);
    float4* orow = reinterpret_cast<float4*>(out + (size_t)node * FEAT + c0);
    orow[0] = o0; orow[1] = o1;
}

// ---------------- launch ----------------
extern "C" void kernel_launch(void* const* d_in, const int* in_sizes, int n_in,
                              void* d_out, int out_size)
{
    const float* x        = (const float*)d_in[0];
    const int*   ei       = (const int*)  d_in[1];
    const float* W1       = (const float*)d_in[2];
    const float* att_src1 = (const float*)d_in[3];
    const float* att_dst1 = (const float*)d_in[4];
    const float* bias1    = (const float*)d_in[5];
    const float* W2       = (const float*)d_in[6];
    const float* att_src2 = (const float*)d_in[7];
    const float* att_dst2 = (const float*)d_in[8];
    const float* bias2    = (const float*)d_in[9];
    const float* bn_gamma = (const float*)d_in[10];
    const float* bn_beta  = (const float*)d_in[11];
    const float* bn_mean  = (const float*)d_in[12];
    const float* bn_var   = (const float*)d_in[13];
    const float* ln_gamma = (const float*)d_in[14];
    const float* ln_beta  = (const float*)d_in[15];
    float* out = (float*)d_out;

    int n = in_sizes[0] / FEAT;      // 50000
    int E = in_sizes[1] / 2;         // 800000
    if (n > NN) n = NN;
    if (E > EMAX) E = EMAX;

    float *h1, *wt1, *wt2, *asrc, *adst, *asrc2, *adst2;
    __half* xph;
    cudaGetSymbolAddress((void**)&xph,   g_xph);
    cudaGetSymbolAddress((void**)&h1,    g_h1);
    cudaGetSymbolAddress((void**)&wt1,   g_wt1);
    cudaGetSymbolAddress((void**)&wt2,   g_wt2);
    cudaGetSymbolAddress((void**)&asrc,  g_asrc);
    cudaGetSymbolAddress((void**)&adst,  g_adst);
    cudaGetSymbolAddress((void**)&asrc2, g_asrc2);
    cudaGetSymbolAddress((void**)&adst2, g_adst2);

    // lazy side-stream / event creation (first call is outside graph capture)
    static cudaStream_t s_side = nullptr;
    static cudaEvent_t  s_evF  = nullptr, s_evW = nullptr, s_evJ = nullptr;
    if (s_side == nullptr) {
        cudaStreamCreateWithFlags(&s_side, cudaStreamNonBlocking);
        cudaEventCreateWithFlags(&s_evF, cudaEventDisableTiming);
        cudaEventCreateWithFlags(&s_evW, cudaEventDisableTiming);
        cudaEventCreateWithFlags(&s_evJ, cudaEventDisableTiming);
    }

    // --- fork: CSR build + weight transpose on side stream ---
    cudaEventRecord(s_evF, 0);
    cudaStreamWaitEvent(s_side, s_evF, 0);
    int nblk_e = (E + 255) / 256;
    count_transpose_kernel<<<nblk_e + 128, 256, 0, s_side>>>(ei, E, nblk_e, W1, W2);
    cudaEventRecord(s_evW, s_side);              // weights (wt1/wt2) ready
    scan_kernel<<<1, 1024, 0, s_side>>>(n);
    fill_kernel<<<(E + n + 255) / 256, 256, 0, s_side>>>(ei, E, n);
    cudaEventRecord(s_evJ, s_side);              // CSR ready

    // --- main stream: layer-1 GEMM (waits only on weights; overlaps scan+fill) ---
    cudaStreamWaitEvent(0, s_evW, 0);
    dim3 ggrid((n + 127) / 128, FEAT / 128);
    gemm_att_kernel<4><<<ggrid, 256>>>(x, wt1, xph,
                                       att_src1, att_dst1, asrc, adst, n);

    // --- join: CSR ready ---
    cudaStreamWaitEvent(0, s_evJ, 0);

    agg1_kernel<<<(n * 32 + 63) / 64, 64>>>(xph, bias1, h1, n);

    // --- layer 2 ---
    gemm_att_kernel<1><<<ggrid, 256>>>(h1, wt2, xph,
                                       att_src2, att_dst2, asrc2, adst2, n);
    agg2_kernel<<<(n * 32 + 63) / 64, 64>>>(xph, bias2, bn_gamma, bn_beta, bn_mean,
                                            bn_var, ln_gamma, ln_beta, out, n);
    (void)n_in; (void)out_size;
}

// round 11
// speedup vs baseline: 2.5009x; 1.1056x over previous
#include <cuda_runtime.h>
#include <cuda_fp16.h>
#include <math.h>
#include <stdint.h>

// ---------------- problem constants ----------------
#define NN      50000      // nodes
#define EMAX    800000     // edges (before self loops)
#define ETOT    (EMAX + NN)
#define FEAT    256        // NFEAT = NHEADS*NHID = NOUT = 256
#define NHEADS  4
#define NHID    64
#define NEG_SLOPE 0.2f
#define BN_EPS  1e-5f
#define LN_EPS  1e-5f

// ---------------- scratch (device globals; no runtime alloc) ----------------
__device__ __half g_xh[NN * FEAT];             // x converted to fp16 (layer-1 GEMM A)
__device__ __half g_xph[NN * FEAT];            // xp of current layer (fp16, gather + reuse)
__device__ __half g_h1h[NN * FEAT];            // layer-1 output (ELU'd, fp16; layer-2 GEMM A)
__device__ __half g_wth1[FEAT * FEAT];         // W1^T, fp16, [n][k]
__device__ __half g_wth2[FEAT * FEAT];         // W2^T, fp16, [n][k]
__device__ float g_asrc[NN * NHEADS];          // layer-1 logits (per head)
__device__ float g_adst[NN * NHEADS];
__device__ float g_asrc2[NN];                  // layer-2 logits (atomic-accumulated)
__device__ float g_adst2[NN];
__device__ int   g_count[NN];                  // zero at rest (restored by fill_kernel)
__device__ int   g_rowptr[NN + 1];
__device__ int   g_cursor[NN];
__device__ int   g_csrsrc[ETOT];

// ---------------- count + weight transpose + x->fp16 convert, fused (one launch) ----------------
// blocks [0, nblk_e): edge histogram.
// blocks [nblk_e, nblk_e+128): transpose+round W1/W2 to fp16.
// blocks [nblk_e+128, nblk_e+128+nblk_x): convert x (fp32) -> g_xh (fp16).
__global__ void prep_kernel(const int* __restrict__ ei, int E, int nblk_e,
                            const float* __restrict__ W1,
                            const float* __restrict__ W2,
                            const float* __restrict__ x, int nx8) {
    if ((int)blockIdx.x < nblk_e) {
        int i = blockIdx.x * blockDim.x + threadIdx.x;
        if (i < E) {
            int d = ei[E + i];      // dst row of edge_index
            atomicAdd(&g_count[d], 1);
        }
        return;
    }
    int tb = blockIdx.x - nblk_e;
    if (tb < 128) {
        // transpose part: 64 blocks per weight (8x8 tiles of 32x32), 2 weights
        __shared__ float tile[32][33];
        int z = tb >> 6;                        // 0 = W1, 1 = W2
        int rem = tb & 63;
        int bx = (rem & 7) * 32, by = (rem >> 3) * 32;
        const float* W  = (z == 0) ? W1 : W2;
        __half* Wt = (z == 0) ? g_wth1 : g_wth2;
        int tx = threadIdx.x & 31, ty = threadIdx.x >> 5;   // 32 x 8
        #pragma unroll
        for (int i = 0; i < 32; i += 8)
            tile[ty + i][tx] = W[(by + ty + i) * FEAT + bx + tx];
        __syncthreads();
        #pragma unroll
        for (int i = 0; i < 32; i += 8)
            Wt[(bx + ty + i) * FEAT + by + tx] = __float2half_rn(tile[tx][ty + i]);
        return;
    }
    // x -> fp16 convert: each thread handles 8 elements
    int i8 = (tb - 128) * blockDim.x + threadIdx.x;
    if (i8 < nx8) {
        const float4* src = reinterpret_cast<const float4*>(x + (size_t)i8 * 8);
        float4 a = src[0], b = src[1];
        __half2 h0 = __float22half2_rn(make_float2(a.x, a.y));
        __half2 h1 = __float22half2_rn(make_float2(a.z, a.w));
        __half2 h2 = __float22half2_rn(make_float2(b.x, b.y));
        __half2 h3 = __float22half2_rn(make_float2(b.z, b.w));
        uint4 o;
        o.x = *reinterpret_cast<uint32_t*>(&h0);
        o.y = *reinterpret_cast<uint32_t*>(&h1);
        o.z = *reinterpret_cast<uint32_t*>(&h2);
        o.w = *reinterpret_cast<uint32_t*>(&h3);
        *reinterpret_cast<uint4*>(g_xh + (size_t)i8 * 8) = o;
    }
}

// single-block scan, 1024 threads, 4 elements/thread; adds +1 per node (self loop)
__global__ void scan_kernel(int n) {
    __shared__ int warpsum[32];
    __shared__ int s_carry;
    int tid = threadIdx.x, lane = tid & 31, wid = tid >> 5;
    if (tid == 0) { s_carry = 0; g_rowptr[0] = 0; }
    __syncthreads();
    for (int base = 0; base < n; base += 4096) {
        int i = base + tid * 4;
        int v0 = 0, v1 = 0, v2 = 0, v3 = 0;
        if (i + 3 < n) {
            int4 q = *reinterpret_cast<const int4*>(&g_count[i]);
            v0 = q.x + 1; v1 = q.y + 1; v2 = q.z + 1; v3 = q.w + 1;  // +1 self loop
        } else {
            if (i     < n) v0 = g_count[i]     + 1;
            if (i + 1 < n) v1 = g_count[i + 1] + 1;
            if (i + 2 < n) v2 = g_count[i + 2] + 1;
        }
        int t = v0 + v1 + v2 + v3;
        int x = t;
        #pragma unroll
        for (int off = 1; off < 32; off <<= 1) {
            int y = __shfl_up_sync(0xffffffffu, x, off);
            if (lane >= off) x += y;
        }
        if (lane == 31) warpsum[wid] = x;
        __syncthreads();
        int woff = 0, tot = 0;
        #pragma unroll
        for (int w = 0; w < 32; w++) {
            int ws = warpsum[w];
            if (w < wid) woff += ws;
            tot += ws;
        }
        int carry = s_carry;
        int excl = carry + woff + x - t;   // exclusive prefix at element i
        int e1 = excl + v0, e2 = e1 + v1, e3 = e2 + v2;
        if (i     < n) { g_cursor[i]     = excl; g_rowptr[i + 1] = e1; }
        if (i + 1 < n) { g_cursor[i + 1] = e1;   g_rowptr[i + 2] = e2; }
        if (i + 2 < n) { g_cursor[i + 2] = e2;   g_rowptr[i + 3] = e3; }
        if (i + 3 < n) { g_cursor[i + 3] = e3;   g_rowptr[i + 4] = e3 + v3; }
        __syncthreads();
        if (tid == 0) s_carry = carry + tot;
        __syncthreads();
    }
}

// fill also: re-zeros g_count (restores rest state) and zeros asrc2/adst2.
__global__ void fill_kernel(const int* __restrict__ ei, int E, int n) {
    int i = blockIdx.x * blockDim.x + threadIdx.x;
    int tot = E + n;
    if (i >= tot) return;
    int s, d;
    if (i < E) {
        s = ei[i]; d = ei[E + i];
        if (i < n) g_count[i] = 0;
    } else {
        s = d = i - E;
        g_asrc2[d] = 0.f;
        g_adst2[d] = 0.f;
    }
    int pos = atomicAdd(&g_cursor[d], 1);
    g_csrsrc[pos] = s;
}

// ---------------- FP16 tensor-core GEMM (m16n8k16), fp16 A/B/out, fp32 accum ----------------
// A [M,256] fp16 row-major; Wt [n][k] fp16 (B col-major for row.col).
// Block 128x128, BK=32 halfs, 8 warps of 32x64, cp.async double buffer.
#define PH 40                 // smem pitch in halfs (80B = 5x16B, ldmatrix conflict-free)
#define STAGE_BYTES (2 * 128 * PH * 2)   // As + Bs per stage

__device__ __forceinline__ void ldsm_x4(uint32_t addr, uint32_t& r0, uint32_t& r1,
                                        uint32_t& r2, uint32_t& r3) {
    asm volatile("ldmatrix.sync.aligned.m8n8.x4.shared.b16 {%0,%1,%2,%3}, [%4];"
                 : "=r"(r0), "=r"(r1), "=r"(r2), "=r"(r3) : "r"(addr));
}

__device__ __forceinline__ void mma_fp16(float* c, const uint32_t* a, const uint32_t* b) {
    asm volatile(
        "mma.sync.aligned.m16n8k16.row.col.f32.f16.f16.f32 "
        "{%0,%1,%2,%3}, {%4,%5,%6,%7}, {%8,%9}, {%0,%1,%2,%3};"
        : "+f"(c[0]), "+f"(c[1]), "+f"(c[2]), "+f"(c[3])
        : "r"(a[0]), "r"(a[1]), "r"(a[2]), "r"(a[3]), "r"(b[0]), "r"(b[1]));
}

__device__ __forceinline__ void cp16(uint32_t saddr, const void* gptr, uint32_t srcsize) {
    asm volatile("cp.async.ca.shared.global [%0], [%1], 16, %2;\n"
                 :: "r"(saddr), "l"(gptr), "r"(srcsize));
}

template<int HEADS>
__global__ __launch_bounds__(256) void gemm_att_kernel(
    const __half* __restrict__ A, const __half* __restrict__ Wt,
    __half* __restrict__ Ch,
    const float* __restrict__ attS, const float* __restrict__ attD,
    float* __restrict__ oS, float* __restrict__ oD, int M)
{
    __shared__ __half smem[2 * 2 * 128 * PH];
    const int K = 256;
    int tid = threadIdx.x;
    int lane = tid & 31;
    int warp = tid >> 5;
    int wm = warp >> 1;          // 0..3
    int wn = warp & 1;           // 0..1
    int block_row = blockIdx.x * 128;
    int block_col = blockIdx.y * 128;

    uint32_t s_base = (uint32_t)__cvta_generic_to_shared(smem);
    uint32_t sA = s_base;
    uint32_t sB = s_base + 128 * PH * 2;

    // ---- cp.async mapping: BK=32 halfs/row = 4 chunks of 16B; 512 chunks per tile;
    //      2 A-chunks + 2 B-chunks per thread ----
    int c0i = tid * 2, c1i = tid * 2 + 1;
    int ar0 = c0i >> 2, ac0 = (c0i & 3) * 8;   // col offset in halfs
    int ar1 = c1i >> 2, ac1 = (c1i & 3) * 8;
    uint32_t dstA0 = sA + (uint32_t)(ar0 * PH + ac0) * 2;
    uint32_t dstA1 = sA + (uint32_t)(ar1 * PH + ac1) * 2;
    uint32_t dstB0 = sB + (uint32_t)(ar0 * PH + ac0) * 2;
    uint32_t dstB1 = sB + (uint32_t)(ar1 * PH + ac1) * 2;
    int grA0 = block_row + ar0, grA1 = block_row + ar1;
    uint32_t szA0 = (grA0 < M) ? 16u : 0u;
    uint32_t szA1 = (grA1 < M) ? 16u : 0u;
    if (grA0 >= M) grA0 = 0;
    if (grA1 >= M) grA1 = 0;
    const __half* srcA0 = A + (size_t)grA0 * K + ac0;
    const __half* srcA1 = A + (size_t)grA1 * K + ac1;
    const __half* srcB0 = Wt + (size_t)(block_col + ar0) * K + ac0;
    const __half* srcB1 = Wt + (size_t)(block_col + ar1) * K + ac1;

    // ---- ldmatrix per-lane base addresses (fp16 m16n8k16 fragments) ----
    int g = lane >> 3, r = lane & 7;
    int a_row_l = (g & 1) * 8 + r;
    int a_koff  = (g >> 1) * 8;                // halfs
    uint32_t a_base[2];
    #pragma unroll
    for (int mt = 0; mt < 2; mt++)
        a_base[mt] = sA + (uint32_t)((wm * 32 + mt * 16 + a_row_l) * PH + a_koff) * 2;
    int b_row_l = (g >> 1) * 8 + r;
    int b_koff  = (g & 1) * 8;                 // halfs
    uint32_t b_base[4];
    #pragma unroll
    for (int np = 0; np < 4; np++)
        b_base[np] = sB + (uint32_t)((wn * 64 + np * 16 + b_row_l) * PH + b_koff) * 2;

    float acc[2][8][4];
    #pragma unroll
    for (int mt = 0; mt < 2; mt++)
        #pragma unroll
        for (int nt = 0; nt < 8; nt++)
            #pragma unroll
            for (int q = 0; q < 4; q++) acc[mt][nt][q] = 0.f;

    cp16(dstA0, srcA0, szA0);
    cp16(dstA1, srcA1, szA1);
    cp16(dstB0, srcB0, 16u);
    cp16(dstB1, srcB1, 16u);
    asm volatile("cp.async.commit_group;\n" ::);

    const int NITER = K / 32;   // 8
    for (int it = 0; it < NITER; it++) {
        int buf = it & 1;
        if (it + 1 < NITER) {
            uint32_t off = ((it + 1) & 1) * STAGE_BYTES;
            int k0 = (it + 1) * 32;
            cp16(dstA0 + off, srcA0 + k0, szA0);
            cp16(dstA1 + off, srcA1 + k0, szA1);
            cp16(dstB0 + off, srcB0 + k0, 16u);
            cp16(dstB1 + off, srcB1 + k0, 16u);
            asm volatile("cp.async.commit_group;\n" ::);
            asm volatile("cp.async.wait_group 1;\n" ::);
        } else {
            asm volatile("cp.async.wait_group 0;\n" ::);
        }
        __syncthreads();

        uint32_t soff = buf * STAGE_BYTES;
        #pragma unroll
        for (int ks = 0; ks < 32; ks += 16) {   // two k16 steps per stage
            uint32_t a[2][4], b[4][4];
            #pragma unroll
            for (int mt = 0; mt < 2; mt++)
                ldsm_x4(a_base[mt] + soff + ks * 2, a[mt][0], a[mt][1], a[mt][2], a[mt][3]);
            #pragma unroll
            for (int np = 0; np < 4; np++)
                ldsm_x4(b_base[np] + soff + ks * 2, b[np][0], b[np][1], b[np][2], b[np][3]);
            #pragma unroll
            for (int mt = 0; mt < 2; mt++)
                #pragma unroll
                for (int nt = 0; nt < 8; nt++)
                    mma_fp16(acc[mt][nt], a[mt], &b[nt >> 1][(nt & 1) * 2]);
        }
        __syncthreads();
    }

    // ---- epilogue: fp16 stores ----
    int cr = lane >> 2;
    int cc = (lane & 3) * 2;
    #pragma unroll
    for (int mt = 0; mt < 2; mt++) {
        int row0 = block_row + wm * 32 + mt * 16 + cr;
        #pragma unroll
        for (int nt = 0; nt < 8; nt++) {
            int col = block_col + wn * 64 + nt * 8 + cc;
            if (row0 < M)
                *reinterpret_cast<__half2*>(Ch + (size_t)row0 * 256 + col) =
                    __float22half2_rn(make_float2(acc[mt][nt][0], acc[mt][nt][1]));
            if (row0 + 8 < M)
                *reinterpret_cast<__half2*>(Ch + (size_t)(row0 + 8) * 256 + col) =
                    __float22half2_rn(make_float2(acc[mt][nt][2], acc[mt][nt][3]));
        }
    }

    // ---- epilogue: fused attention-logit partial dots over this warp's 64 cols ----
    float ps[2][2] = {{0.f,0.f},{0.f,0.f}};
    float pd[2][2] = {{0.f,0.f},{0.f,0.f}};
    #pragma unroll
    for (int mt = 0; mt < 2; mt++) {
        #pragma unroll
        for (int nt = 0; nt < 8; nt++) {
            int lc = nt * 8 + cc;
            int idx = (HEADS == 4) ? ((blockIdx.y * 2 + wn) * 64 + lc)
                                   : (block_col + wn * 64 + lc);
            float as0 = attS[idx], as1 = attS[idx + 1];
            float ad0 = attD[idx], ad1 = attD[idx + 1];
            ps[mt][0] += acc[mt][nt][0] * as0 + acc[mt][nt][1] * as1;
            ps[mt][1] += acc[mt][nt][2] * as0 + acc[mt][nt][3] * as1;
            pd[mt][0] += acc[mt][nt][0] * ad0 + acc[mt][nt][1] * ad1;
            pd[mt][1] += acc[mt][nt][2] * ad0 + acc[mt][nt][3] * ad1;
        }
    }
    #pragma unroll
    for (int mt = 0; mt < 2; mt++)
        #pragma unroll
        for (int hf = 0; hf < 2; hf++) {
            ps[mt][hf] += __shfl_xor_sync(0xffffffffu, ps[mt][hf], 1);
            ps[mt][hf] += __shfl_xor_sync(0xffffffffu, ps[mt][hf], 2);
            pd[mt][hf] += __shfl_xor_sync(0xffffffffu, pd[mt][hf], 1);
            pd[mt][hf] += __shfl_xor_sync(0xffffffffu, pd[mt][hf], 2);
        }
    if ((lane & 3) == 0) {
        #pragma unroll
        for (int mt = 0; mt < 2; mt++)
            #pragma unroll
            for (int hf = 0; hf < 2; hf++) {
                int node = block_row + wm * 32 + mt * 16 + cr + hf * 8;
                if (node < M) {
                    if (HEADS == 4) {
                        int head = blockIdx.y * 2 + wn;
                        oS[node * 4 + head] = ps[mt][hf];
                        oD[node * 4 + head] = pd[mt][hf];
                    } else {
                        atomicAdd(&oS[node], ps[mt][hf]);
                        atomicAdd(&oD[node], pd[mt][hf]);
                    }
                }
            }
    }
}

__device__ __forceinline__ float leaky(float x) {
    return (x > 0.f) ? x : NEG_SLOPE * x;
}

__device__ __forceinline__ void unpack8h(uint4 u, float* f) {
    float2 a = __half22float2(*reinterpret_cast<__half2*>(&u.x));
    float2 b = __half22float2(*reinterpret_cast<__half2*>(&u.y));
    float2 c = __half22float2(*reinterpret_cast<__half2*>(&u.z));
    float2 d = __half22float2(*reinterpret_cast<__half2*>(&u.w));
    f[0] = a.x; f[1] = a.y; f[2] = b.x; f[3] = b.y;
    f[4] = c.x; f[5] = c.y; f[6] = d.x; f[7] = d.y;
}

__device__ __forceinline__ uint4 pack8h(const float* f) {
    __half2 h0 = __float22half2_rn(make_float2(f[0], f[1]));
    __half2 h1 = __float22half2_rn(make_float2(f[2], f[3]));
    __half2 h2 = __float22half2_rn(make_float2(f[4], f[5]));
    __half2 h3 = __float22half2_rn(make_float2(f[6], f[7]));
    uint4 o;
    o.x = *reinterpret_cast<uint32_t*>(&h0);
    o.y = *reinterpret_cast<uint32_t*>(&h1);
    o.z = *reinterpret_cast<uint32_t*>(&h2);
    o.w = *reinterpret_cast<uint32_t*>(&h3);
    return o;
}

// ---------------- aggregation, layer 1 (4 heads, fp16 gather) + bias + ELU -> fp16 h1 ----------------
__global__ __launch_bounds__(64) void agg1_kernel(const __half* __restrict__ xph,
                            const float* __restrict__ bias,
                            __half* __restrict__ out, int n)
{
    int node = (blockIdx.x * blockDim.x + threadIdx.x) >> 5;
    if (node >= n) return;
    int lane = threadIdx.x & 31;
    int h  = lane >> 3;         // 8 lanes per head
    int c0 = lane * 8;
    float ad = g_adst[node * NHEADS + h];
    int beg = g_rowptr[node], end = g_rowptr[node + 1];
    float m = -1e30f, s = 0.f;
    float acc[8] = {0,0,0,0,0,0,0,0};
    int p = beg;
    for (; p + 1 < end; p += 2) {
        int j0 = g_csrsrc[p];
        int j1 = g_csrsrc[p + 1];
        float e0 = leaky(g_asrc[j0 * NHEADS + h] + ad);
        float e1 = leaky(g_asrc[j1 * NHEADS + h] + ad);
        uint4 u0 = *reinterpret_cast<const uint4*>(xph + (size_t)j0 * FEAT + c0);
        uint4 u1 = *reinterpret_cast<const uint4*>(xph + (size_t)j1 * FEAT + c0);
        float fa[8], fb[8];
        unpack8h(u0, fa);
        unpack8h(u1, fb);
        float mn = fmaxf(m, fmaxf(e0, e1));
        float corr = __expf(m - mn);
        float p0   = __expf(e0 - mn);
        float p1   = __expf(e1 - mn);
        s = s * corr + p0 + p1;
        #pragma unroll
        for (int k = 0; k < 8; k++)
            acc[k] = acc[k] * corr + p0 * fa[k] + p1 * fb[k];
        m = mn;
    }
    if (p < end) {
        int j = g_csrsrc[p];
        float e = leaky(g_asrc[j * NHEADS + h] + ad);
        uint4 u = *reinterpret_cast<const uint4*>(xph + (size_t)j * FEAT + c0);
        float fa[8];
        unpack8h(u, fa);
        float mn = fmaxf(m, e);
        float corr = __expf(m - mn);
        float pw   = __expf(e - mn);
        s = s * corr + pw;
        #pragma unroll
        for (int k = 0; k < 8; k++)
            acc[k] = acc[k] * corr + pw * fa[k];
    }
    float inv = 1.f / s;
    const float4* b4 = reinterpret_cast<const float4*>(bias + c0);
    float4 bb0 = b4[0], bb1 = b4[1];
    float vb[8] = {bb0.x, bb0.y, bb0.z, bb0.w, bb1.x, bb1.y, bb1.z, bb1.w};
    float v[8];
    #pragma unroll
    for (int k = 0; k < 8; k++) {
        float t = acc[k] * inv + vb[k];
        v[k] = (t > 0.f) ? t : expm1f(t);   // ELU
    }
    *reinterpret_cast<uint4*>(out + (size_t)node * FEAT + c0) = pack8h(v);
}

// ---------------- aggregation, layer 2 (1 head, fp16 gather) + bias + ELU + BN + LN ----------------
__global__ __launch_bounds__(64) void agg2_kernel(const __half* __restrict__ xph,
                            const float* __restrict__ bias,
                            const float* __restrict__ bn_gamma,
                            const float* __restrict__ bn_beta,
                            const float* __restrict__ bn_mean,
                            const float* __restrict__ bn_var,
                            const float* __restrict__ ln_gamma,
                            const float* __restrict__ ln_beta,
                            float* __restrict__ out, int n)
{
    int node = (blockIdx.x * blockDim.x + threadIdx.x) >> 5;
    if (node >= n) return;
    int lane = threadIdx.x & 31;
    int c0 = lane * 8;
    float ad = g_adst2[node];
    int beg = g_rowptr[node], end = g_rowptr[node + 1];
    float m = -1e30f, s = 0.f;
    float acc[8] = {0,0,0,0,0,0,0,0};
    int p = beg;
    for (; p + 1 < end; p += 2) {
        int j0 = g_csrsrc[p];
        int j1 = g_csrsrc[p + 1];
        float e0 = leaky(g_asrc2[j0] + ad);
        float e1 = leaky(g_asrc2[j1] + ad);
        uint4 u0 = *reinterpret_cast<const uint4*>(xph + (size_t)j0 * FEAT + c0);
        uint4 u1 = *reinterpret_cast<const uint4*>(xph + (size_t)j1 * FEAT + c0);
        float fa[8], fb[8];
        unpack8h(u0, fa);
        unpack8h(u1, fb);
        float mn = fmaxf(m, fmaxf(e0, e1));
        float corr = __expf(m - mn);
        float p0   = __expf(e0 - mn);
        float p1   = __expf(e1 - mn);
        s = s * corr + p0 + p1;
        #pragma unroll
        for (int k = 0; k < 8; k++)
            acc[k] = acc[k] * corr + p0 * fa[k] + p1 * fb[k];
        m = mn;
    }
    if (p < end) {
        int j = g_csrsrc[p];
        float e = leaky(g_asrc2[j] + ad);
        uint4 u = *reinterpret_cast<const uint4*>(xph + (size_t)j * FEAT + c0);
        float fa[8];
        unpack8h(u, fa);
        float mn = fmaxf(m, e);
        float corr = __expf(m - mn);
        float pw   = __expf(e - mn);
        s = s * corr + pw;
        #pragma unroll
        for (int k = 0; k < 8; k++)
            acc[k] = acc[k] * corr + pw * fa[k];
    }
    float inv = 1.f / s;
    float v[8];
    #pragma unroll
    for (int k = 0; k < 8; k++) {
        int c = c0 + k;
        float x = acc[k] * inv + bias[c];
        x = (x > 0.f) ? x : expm1f(x);                           // ELU
        x = (x - bn_mean[c]) * rsqrtf(bn_var[c] + BN_EPS) * bn_gamma[c] + bn_beta[c];  // BN eval
        v[k] = x;
    }
    // LayerNorm over 256 channels (warp = row, 8 ch/lane)
    float lsum = 0.f;
    #pragma unroll
    for (int k = 0; k < 8; k++) lsum += v[k];
    #pragma unroll
    for (int off = 16; off; off >>= 1) lsum += __shfl_xor_sync(0xffffffffu, lsum, off);
    float mu = lsum * (1.f / 256.f);
    float lvar = 0.f;
    #pragma unroll
    for (int k = 0; k < 8; k++) { float d = v[k] - mu; lvar += d * d; }
    #pragma unroll
    for (int off = 16; off; off >>= 1) lvar += __shfl_xor_sync(0xffffffffu, lvar, off);
    float r = rsqrtf(lvar * (1.f / 256.f) + LN_EPS);
    float w[8];
    #pragma unroll
    for (int k = 0; k < 8; k++) {
        int c = c0 + k;
        w[k] = (v[k] - mu) * r * ln_gamma[c] + ln_beta[c];
    }
    float4 o0 = make_float4(w[0], w[1], w[2], w[3]);
    float4 o1 = make_float4(w[4], w[5], w[6], w[7]);
    float4* orow = reinterpret_cast<float4*>(out + (size_t)node * FEAT + c0);
    orow[0] = o0; orow[1] = o1;
}

// ---------------- launch ----------------
extern "C" void kernel_launch(void* const* d_in, const int* in_sizes, int n_in,
                              void* d_out, int out_size)
{
    const float* x        = (const float*)d_in[0];
    const int*   ei       = (const int*)  d_in[1];
    const float* W1       = (const float*)d_in[2];
    const float* att_src1 = (const float*)d_in[3];
    const float* att_dst1 = (const float*)d_in[4];
    const float* bias1    = (const float*)d_in[5];
    const float* W2       = (const float*)d_in[6];
    const float* att_src2 = (const float*)d_in[7];
    const float* att_dst2 = (const float*)d_in[8];
    const float* bias2    = (const float*)d_in[9];
    const float* bn_gamma = (const float*)d_in[10];
    const float* bn_beta  = (const float*)d_in[11];
    const float* bn_mean  = (const float*)d_in[12];
    const float* bn_var   = (const float*)d_in[13];
    const float* ln_gamma = (const float*)d_in[14];
    const float* ln_beta  = (const float*)d_in[15];
    float* out = (float*)d_out;

    int n = in_sizes[0] / FEAT;      // 50000
    int E = in_sizes[1] / 2;         // 800000
    if (n > NN) n = NN;
    if (E > EMAX) E = EMAX;

    float *asrc, *adst, *asrc2, *adst2;
    __half *xh, *xph, *h1h, *wth1, *wth2;
    cudaGetSymbolAddress((void**)&xh,    g_xh);
    cudaGetSymbolAddress((void**)&xph,   g_xph);
    cudaGetSymbolAddress((void**)&h1h,   g_h1h);
    cudaGetSymbolAddress((void**)&wth1,  g_wth1);
    cudaGetSymbolAddress((void**)&wth2,  g_wth2);
    cudaGetSymbolAddress((void**)&asrc,  g_asrc);
    cudaGetSymbolAddress((void**)&adst,  g_adst);
    cudaGetSymbolAddress((void**)&asrc2, g_asrc2);
    cudaGetSymbolAddress((void**)&adst2, g_adst2);

    // lazy side-stream / event creation (first call is outside graph capture)
    static cudaStream_t s_side = nullptr;
    static cudaEvent_t  s_evF  = nullptr, s_evW = nullptr, s_evJ = nullptr;
    if (s_side == nullptr) {
        cudaStreamCreateWithFlags(&s_side, cudaStreamNonBlocking);
        cudaEventCreateWithFlags(&s_evF, cudaEventDisableTiming);
        cudaEventCreateWithFlags(&s_evW, cudaEventDisableTiming);
        cudaEventCreateWithFlags(&s_evJ, cudaEventDisableTiming);
    }

    // --- fork: CSR count + weight transpose + x->fp16 on side stream ---
    cudaEventRecord(s_evF, 0);
    cudaStreamWaitEvent(s_side, s_evF, 0);
    int nblk_e = (E + 255) / 256;
    int nx8 = n * FEAT / 8;
    int nblk_x = (nx8 + 255) / 256;
    prep_kernel<<<nblk_e + 128 + nblk_x, 256, 0, s_side>>>(ei, E, nblk_e, W1, W2, x, nx8);
    cudaEventRecord(s_evW, s_side);              // weights + xh ready
    scan_kernel<<<1, 1024, 0, s_side>>>(n);
    fill_kernel<<<(E + n + 255) / 256, 256, 0, s_side>>>(ei, E, n);
    cudaEventRecord(s_evJ, s_side);              // CSR ready

    // --- main stream: layer-1 GEMM (waits on prep; overlaps scan+fill) ---
    cudaStreamWaitEvent(0, s_evW, 0);
    dim3 ggrid((n + 127) / 128, FEAT / 128);
    gemm_att_kernel<4><<<ggrid, 256>>>(xh, wth1, xph,
                                       att_src1, att_dst1, asrc, adst, n);

    // --- join: CSR ready ---
    cudaStreamWaitEvent(0, s_evJ, 0);

    agg1_kernel<<<(n * 32 + 63) / 64, 64>>>(xph, bias1, h1h, n);

    // --- layer 2 ---
    gemm_att_kernel<1><<<ggrid, 256>>>(h1h, wth2, xph,
                                       att_src2, att_dst2, asrc2, adst2, n);
    agg2_kernel<<<(n * 32 + 63) / 64, 64>>>(xph, bias2, bn_gamma, bn_beta, bn_mean,
                                            bn_var, ln_gamma, ln_beta, out, n);
    (void)n_in; (void)out_size;
}